// round 8
// baseline (speedup 1.0000x reference)
#include <cuda_runtime.h>
#include <cuda_bf16.h>
#include <math.h>
#include <stdint.h>

#define N_NODES 346
#define L_SEQ   50
#define D_EMB   300
#define H_HID   300
#define G4      1200   // 4*H

typedef __nv_bfloat16 bf16;

// ---------------------------------------------------------------------------
// Scratch pool (static device allocation — no cudaMalloc anywhere)
// All offsets in float (4B) units; bf16 regions use ceil(halves/2) floats.
// ---------------------------------------------------------------------------
constexpr size_t A256(size_t x) { return (x + 255) & ~(size_t)255; }
constexpr size_t HF(size_t halves) { return (halves + 1) / 2; }

constexpr size_t SZ_X   = (size_t)L_SEQ * N_NODES * D_EMB;   // 5,190,000
constexpr size_t SZ_P   = (size_t)L_SEQ * N_NODES * G4;      // 20,760,000
constexpr size_t SZ_O0  = (size_t)L_SEQ * N_NODES * 600;     // 10,380,000
constexpr size_t SZ_NG4 = (size_t)N_NODES * G4;
constexpr size_t SZ_NH  = (size_t)N_NODES * H_HID;
constexpr size_t SZ_W3  = (size_t)G4 * 300;                  // 360,000
constexpr size_t SZ_W6  = (size_t)G4 * 600;                  // 720,000
constexpr size_t SZ_FC1 = (size_t)4800 * 9600;               // 46,080,000

constexpr size_t OFF_PF   = 0;
constexpr size_t OFF_PB   = A256(OFF_PF  + SZ_P);
constexpr size_t OFF_XH   = A256(OFF_PB  + SZ_P);
constexpr size_t OFF_XL   = A256(OFF_XH  + HF(SZ_X));
constexpr size_t OFF_O0H  = A256(OFF_XL  + HF(SZ_X));
constexpr size_t OFF_O0L  = A256(OFF_O0H + HF(SZ_O0));
constexpr size_t OFF_HSA  = A256(OFF_O0L + HF(SZ_O0));
constexpr size_t OFF_HSB  = A256(OFF_HSA + SZ_NG4);
constexpr size_t OFF_C4   = A256(OFF_HSB + SZ_NG4);
constexpr size_t OFF_CAT  = A256(OFF_C4  + 4 * SZ_NH);
constexpr size_t OFF_WH   = A256(OFF_CAT + (size_t)N_NODES * 2400);
constexpr size_t OFF_ATT  = A256(OFF_WH  + SZ_NG4);
constexpr size_t OFF_HS1  = A256(OFF_ATT + (size_t)N_NODES * N_NODES);
constexpr size_t OFF_HS2  = A256(OFF_HS1 + SZ_NG4);
constexpr size_t OFF_ZH   = A256(OFF_HS2 + SZ_NG4);
constexpr size_t OFF_ZL   = A256(OFF_ZH  + HF((size_t)N_NODES * 4800));
constexpr size_t OFF_HC3  = A256(OFF_ZL  + HF((size_t)N_NODES * 4800));
constexpr size_t OFF_WHHR  = A256(OFF_HC3  + (size_t)N_NODES * 9600);   // fp32 4x[1200][300]
constexpr size_t OFF_WIHR0 = A256(OFF_WHHR + 4 * SZ_W3);                // fp32 2x[1200][300]
constexpr size_t OFF_WIHR1 = A256(OFF_WIHR0 + 2 * SZ_W3);               // fp32 2x[1200][600]
constexpr size_t OFF_W0H   = A256(OFF_WIHR1 + 2 * SZ_W6);               // bf16 2x[1200][300]
constexpr size_t OFF_W0L   = A256(OFF_W0H + HF(2 * SZ_W3));
constexpr size_t OFF_W1H   = A256(OFF_W0L + HF(2 * SZ_W3));             // bf16 2x[1200][600]
constexpr size_t OFF_W1L   = A256(OFF_W1H + HF(2 * SZ_W6));
constexpr size_t OFF_F1H   = A256(OFF_W1L + HF(2 * SZ_W6));             // bf16 [4800][9600]
constexpr size_t OFF_F1L   = A256(OFF_F1H + HF(SZ_FC1));
constexpr size_t OFF_BR    = A256(OFF_F1L + HF(SZ_FC1));                // fp32 4x1200
constexpr size_t OFF_U    = A256(OFF_BR  + 4 * (size_t)G4);
constexpr size_t OFF_V    = A256(OFF_U   + 512);
constexpr size_t OFF_S    = A256(OFF_V   + 32);
constexpr size_t OFF_E1   = A256(OFF_S   + 1280);
constexpr size_t OFF_E2   = A256(OFF_E1  + 512);
constexpr size_t OFF_BATT = A256(OFF_E2  + 512);
constexpr size_t OFF_EA   = A256(OFF_BATT + 512);
constexpr size_t POOL_SZ  = A256(OFF_EA + 2560);

__device__ float g_pool[POOL_SZ];

__device__ __forceinline__ float sigm_(float x) { return 1.0f / (1.0f + expf(-x)); }

__device__ __forceinline__ void split_bf16(float v, bf16* hi, bf16* lo) {
    bf16 h = __float2bfloat16(v);
    *hi = h;
    *lo = __float2bfloat16(v - __bfloat162float(h));
}

// ---------------------------------------------------------------------------
// bf16x3-split tensor-core GEMM (HMMA m16n8k16), fp32-accurate.
//   C = epi( Ah@op(B)h + Ah@op(B)l + Al@op(B)h + bias )
//   TB=1: B global layout [N][K] (k contiguous);  TB=0: B [K][N]
//   Block 128x128, 8 warps (2m x 4n), warp tile 64x32, BK=32.
// ---------------------------------------------------------------------------
#define TKP 40   // padded halves per smem row (80B)

__device__ __forceinline__ void mma16816(float c[4], const uint32_t a[4], const uint32_t b[2]) {
    asm volatile(
        "mma.sync.aligned.m16n8k16.row.col.f32.bf16.bf16.f32 "
        "{%0,%1,%2,%3}, {%4,%5,%6,%7}, {%8,%9}, {%0,%1,%2,%3};"
        : "+f"(c[0]), "+f"(c[1]), "+f"(c[2]), "+f"(c[3])
        : "r"(a[0]), "r"(a[1]), "r"(a[2]), "r"(a[3]), "r"(b[0]), "r"(b[1]));
}

template<int TB, int EPI>
__global__ void __launch_bounds__(256) bmma_kernel(
    int M, int N, int K,
    const bf16* __restrict__ Ah, const bf16* __restrict__ Al,
    const bf16* __restrict__ Bh, const bf16* __restrict__ Bl,
    const float* __restrict__ bias, float* __restrict__ C, int ldc)
{
    __shared__ bf16 As[128 * TKP];
    __shared__ bf16 Bs[128 * TKP];
    const int m0b = blockIdx.y * 128, n0b = blockIdx.x * 128;
    const int tid = threadIdx.x, lane = tid & 31, wid = tid >> 5;
    const int wm = wid & 1, wn = wid >> 1;       // 2 x 4 warps
    const int g = lane >> 2, tg = lane & 3;

    float acc[4][4][4];
#pragma unroll
    for (int a = 0; a < 4; a++)
#pragma unroll
        for (int b = 0; b < 4; b++)
#pragma unroll
            for (int c = 0; c < 4; c++) acc[a][b][c] = 0.0f;

    for (int pass = 0; pass < 3; pass++) {
        const bf16* A = (pass == 2) ? Al : Ah;
        const bf16* B = (pass == 1) ? Bl : Bh;
        for (int k0 = 0; k0 < K; k0 += 32) {
            // A tile: [128 m][32 k] as 2048 u32 units
            for (int u = tid; u < 2048; u += 256) {
                int row = u >> 4, kc = u & 15;
                int gm = m0b + row, gk = k0 + kc * 2;
                uint32_t v = 0;
                if (gm < M) {
                    if (gk + 1 < K) v = *reinterpret_cast<const uint32_t*>(&A[(size_t)gm * K + gk]);
                    else if (gk < K) v = *reinterpret_cast<const uint16_t*>(&A[(size_t)gm * K + gk]);
                }
                *reinterpret_cast<uint32_t*>(&As[row * TKP + kc * 2]) = v;
            }
            if (TB) {
                for (int u = tid; u < 2048; u += 256) {
                    int row = u >> 4, kc = u & 15;
                    int gn = n0b + row, gk = k0 + kc * 2;
                    uint32_t v = 0;
                    if (gn < N) {
                        if (gk + 1 < K) v = *reinterpret_cast<const uint32_t*>(&B[(size_t)gn * K + gk]);
                        else if (gk < K) v = *reinterpret_cast<const uint16_t*>(&B[(size_t)gn * K + gk]);
                    }
                    *reinterpret_cast<uint32_t*>(&Bs[row * TKP + kc * 2]) = v;
                }
            } else {
                // B [K][N] -> Bs[n][k] (transpose in smem)
                int k = tid & 31, nb = (tid >> 5) * 16;
                int gk = k0 + k;
#pragma unroll
                for (int j = 0; j < 16; j++) {
                    int n = nb + j, gn = n0b + n;
                    bf16 v = __float2bfloat16(0.0f);
                    if (gk < K && gn < N) v = B[(size_t)gk * N + gn];
                    Bs[n * TKP + k] = v;
                }
            }
            __syncthreads();
#pragma unroll
            for (int kk = 0; kk < 32; kk += 16) {
                uint32_t afrag[4][4];
#pragma unroll
                for (int mt = 0; mt < 4; mt++) {
                    int r = wm * 64 + mt * 16;
                    afrag[mt][0] = *reinterpret_cast<const uint32_t*>(&As[(r + g) * TKP + kk + 2 * tg]);
                    afrag[mt][1] = *reinterpret_cast<const uint32_t*>(&As[(r + g + 8) * TKP + kk + 2 * tg]);
                    afrag[mt][2] = *reinterpret_cast<const uint32_t*>(&As[(r + g) * TKP + kk + 2 * tg + 8]);
                    afrag[mt][3] = *reinterpret_cast<const uint32_t*>(&As[(r + g + 8) * TKP + kk + 2 * tg + 8]);
                }
                uint32_t bfrag[4][2];
#pragma unroll
                for (int nt = 0; nt < 4; nt++) {
                    int c = wn * 32 + nt * 8;
                    bfrag[nt][0] = *reinterpret_cast<const uint32_t*>(&Bs[(c + g) * TKP + kk + 2 * tg]);
                    bfrag[nt][1] = *reinterpret_cast<const uint32_t*>(&Bs[(c + g) * TKP + kk + 2 * tg + 8]);
                }
#pragma unroll
                for (int mt = 0; mt < 4; mt++)
#pragma unroll
                    for (int nt = 0; nt < 4; nt++)
                        mma16816(acc[mt][nt], afrag[mt], bfrag[nt]);
            }
            __syncthreads();
        }
    }

    // Epilogue: c0=(g,2tg) c1=(g,2tg+1) c2=(g+8,2tg) c3=(g+8,2tg+1)
#pragma unroll
    for (int mt = 0; mt < 4; mt++) {
#pragma unroll
        for (int nt = 0; nt < 4; nt++) {
            int r0 = m0b + wm * 64 + mt * 16 + g;
            int c0 = n0b + wn * 32 + nt * 8 + 2 * tg;
#pragma unroll
            for (int h = 0; h < 2; h++) {
                int gm = r0 + h * 8;
                if (gm >= M) continue;
#pragma unroll
                for (int l = 0; l < 2; l++) {
                    int gn = c0 + l;
                    if (gn >= N) continue;
                    float v = acc[mt][nt][h * 2 + l];
                    if (bias) v += bias[gn];
                    if (EPI == 1) v = tanhf(v);
                    C[(size_t)gm * ldc + gn] = v;
                }
            }
        }
    }
}

// ---------------------------------------------------------------------------
// fp32 64x64x16 GEMM core (R3 version) — GAT + LSTM recurrent step
// ---------------------------------------------------------------------------
#define BM 64
#define BN 64
#define BK 16
#define SPAD 68

template<int TB>
__device__ __forceinline__ void gemm_acc64(
    int M, int N, int K,
    const float* __restrict__ A, int lda,
    const float* __restrict__ B, int ldb,
    float* As, float* Bs, float acc[4][4],
    int m0, int n0, int tid, int tx, int ty)
{
#pragma unroll
    for (int i = 0; i < 4; i++)
#pragma unroll
        for (int j = 0; j < 4; j++) acc[i][j] = 0.0f;

    for (int k0 = 0; k0 < K; k0 += BK) {
#pragma unroll
        for (int i = 0; i < 4; i++) {
            int idx = tid + i * 256;
            int m = idx >> 4, k = idx & 15;
            int gm = m0 + m, gk = k0 + k;
            As[k * SPAD + m] = (gm < M && gk < K) ? __ldg(&A[(size_t)gm * lda + gk]) : 0.0f;
        }
        if (TB) {
#pragma unroll
            for (int i = 0; i < 4; i++) {
                int idx = tid + i * 256;
                int j = idx >> 4, k = idx & 15;
                int gj = n0 + j, gk = k0 + k;
                Bs[k * SPAD + j] = (gj < N && gk < K) ? __ldg(&B[(size_t)gj * ldb + gk]) : 0.0f;
            }
        } else {
#pragma unroll
            for (int i = 0; i < 4; i++) {
                int idx = tid + i * 256;
                int j = idx & 63, k = idx >> 6;
                int gj = n0 + j, gk = k0 + k;
                Bs[k * SPAD + j] = (gj < N && gk < K) ? __ldg(&B[(size_t)gk * ldb + gj]) : 0.0f;
            }
        }
        __syncthreads();
#pragma unroll
        for (int kk = 0; kk < BK; kk++) {
            float4 av = *reinterpret_cast<const float4*>(&As[kk * SPAD + ty * 4]);
            float4 bv = *reinterpret_cast<const float4*>(&Bs[kk * SPAD + tx * 4]);
            float a[4] = {av.x, av.y, av.z, av.w};
            float b[4] = {bv.x, bv.y, bv.z, bv.w};
#pragma unroll
            for (int i = 0; i < 4; i++)
#pragma unroll
                for (int j = 0; j < 4; j++)
                    acc[i][j] += a[i] * b[j];
        }
        __syncthreads();
    }
}

template<int TB, int EPI>
__global__ void __launch_bounds__(256) gemm_kernel(
    int M, int N, int K,
    const float* __restrict__ A, int lda,
    const float* __restrict__ B, int ldb,
    const float* __restrict__ Dm, int ldd,
    float* __restrict__ C, int ldc)
{
    __shared__ float As[BK * SPAD], Bs[BK * SPAD];
    const int m0 = blockIdx.y * BM, n0 = blockIdx.x * BN;
    const int tid = threadIdx.x, tx = tid & 15, ty = tid >> 4;
    float acc[4][4];
    gemm_acc64<TB>(M, N, K, A, lda, B, ldb, As, Bs, acc, m0, n0, tid, tx, ty);

#pragma unroll
    for (int i = 0; i < 4; i++) {
        int gm = m0 + ty * 4 + i;
        if (gm >= M) continue;
#pragma unroll
        for (int j = 0; j < 4; j++) {
            int gn = n0 + tx * 4 + j;
            if (gn >= N) continue;
            float v = acc[i][j];
            if (Dm) v += (ldd == 0) ? Dm[gn] : Dm[(size_t)gm * ldd + gn];
            if (EPI == 1) v = tanhf(v);
            if (EPI == 2) v = (v > 0.0f) ? v : expm1f(v);
            C[(size_t)gm * ldc + gn] = v;
        }
    }
}

// ---------------------------------------------------------------------------
// Fused LSTM step (gate-interleaved weights, cell update in epilogue)
// ---------------------------------------------------------------------------
__global__ void __launch_bounds__(256) lstm_fused_kernel(
    const float* __restrict__ hs_in, float* __restrict__ hs_out,
    int hcol_f, int hcol_b,
    const float* __restrict__ Whh_rf, const float* __restrict__ Whh_rb,
    const float* __restrict__ Pf, const float* __restrict__ Pb,
    float* __restrict__ cbuf,            // [2][N][H]
    bf16* __restrict__ o0h, bf16* __restrict__ o0l, int t)
{
    __shared__ float As[BK * SPAD], Bs[BK * SPAD];
    const int z = blockIdx.z;
    const int hcol = z ? hcol_b : hcol_f;
    const float* A = hs_in + hcol;
    const float* Bw = z ? Whh_rb : Whh_rf;
    const float* P  = z ? Pb : Pf;

    const int m0 = blockIdx.y * BM, n0 = blockIdx.x * BN;
    const int tid = threadIdx.x, tx = tid & 15, ty = tid >> 4;
    float acc[4][4];
    gemm_acc64<1>(N_NODES, G4, H_HID, A, G4, Bw, H_HID, As, Bs, acc, m0, n0, tid, tx, ty);

    const int r0 = n0 + tx * 4;
    if (r0 + 3 >= G4) return;
    const int j = r0 >> 2;
    float* c = cbuf + (size_t)z * N_NODES * H_HID;

#pragma unroll
    for (int i = 0; i < 4; i++) {
        int gm = m0 + ty * 4 + i;
        if (gm >= N_NODES) continue;
        float4 p = *reinterpret_cast<const float4*>(P + (size_t)gm * G4 + r0);
        float gi = acc[i][0] + p.x;
        float gf = acc[i][1] + p.y;
        float gg = acc[i][2] + p.z;
        float go = acc[i][3] + p.w;
        float cp = c[(size_t)gm * H_HID + j];
        float cn = sigm_(gf) * cp + sigm_(gi) * tanhf(gg);
        float h  = sigm_(go) * tanhf(cn);
        c[(size_t)gm * H_HID + j] = cn;
        hs_out[(size_t)gm * G4 + hcol + j] = h;
        if (o0h) {
            int tt = z ? (L_SEQ - 1 - t) : t;
            size_t oi = (size_t)tt * N_NODES * 600 + (size_t)gm * 600 + z * H_HID + j;
            split_bf16(h, &o0h[oi], &o0l[oi]);
        }
    }
}

// Reorder LSTM weight rows: out[j*4+g][k] = in[g*H + j][k]
__global__ void reorder_rows_kernel(const float* __restrict__ in,
                                    float* __restrict__ out, int K)
{
    size_t idx = (size_t)blockIdx.x * blockDim.x + threadIdx.x;
    if (idx >= (size_t)G4 * K) return;
    int r = (int)(idx / K), k = (int)(idx % K);
    int j = r >> 2, g = r & 3;
    out[(size_t)r * K + k] = in[(size_t)(g * H_HID + j) * K + k];
}

// fp32 -> (hi, lo) bf16 split
__global__ void split2_kernel(const float* __restrict__ in,
                              bf16* __restrict__ hi, bf16* __restrict__ lo, size_t n)
{
    size_t i = (size_t)blockIdx.x * blockDim.x + threadIdx.x;
    if (i >= n) return;
    split_bf16(in[i], &hi[i], &lo[i]);
}

__global__ void memzero_kernel(float* p, int n)
{
    int i = blockIdx.x * blockDim.x + threadIdx.x;
    if (i < n) p[i] = 0.0f;
}

// embedding -> hi/lo bf16 splits directly
__global__ void embed_kernel(const int* __restrict__ tok,
                             const float* __restrict__ emb,
                             bf16* __restrict__ xh, bf16* __restrict__ xl)
{
    size_t idx = (size_t)blockIdx.x * blockDim.x + threadIdx.x;
    const size_t total = (size_t)L_SEQ * N_NODES * D_EMB;
    if (idx >= total) return;
    int d = (int)(idx % D_EMB);
    size_t r = idx / D_EMB;
    int n = (int)(r % N_NODES);
    int t = (int)(r / N_NODES);
    int tv = tok[n * L_SEQ + t];
    split_bf16(emb[(size_t)tv * D_EMB + d], &xh[idx], &xl[idx]);
}

// out[row] = epi( dot(A[row,:K], w) )
template<int EPI>
__global__ void rows_dot_kernel(const float* __restrict__ A, int lda,
                                const float* __restrict__ w, int K,
                                float* __restrict__ out)
{
    __shared__ float red[8];
    const float* a = A + (size_t)blockIdx.x * lda;
    float s = 0.0f;
    for (int k = threadIdx.x; k < K; k += blockDim.x) s += a[k] * w[k];
#pragma unroll
    for (int o = 16; o > 0; o >>= 1) s += __shfl_down_sync(0xffffffffu, s, o);
    if ((threadIdx.x & 31) == 0) red[threadIdx.x >> 5] = s;
    __syncthreads();
    if (threadIdx.x == 0) {
        float t = 0.0f;
        int nw = blockDim.x >> 5;
        for (int i = 0; i < nw; i++) t += red[i];
        if (EPI == 1) t = tanhf(t);
        out[blockIdx.x] = t;
    }
}

// out[j] = scale * sum_n (w ? w[n] : 1) * A[n*lda + j]
__global__ void colsum_kernel(const float* __restrict__ A, int lda, int rows,
                              const float* __restrict__ w, float scale,
                              float* __restrict__ out, int ncols)
{
    int j = blockIdx.x * blockDim.x + threadIdx.x;
    if (j >= ncols) return;
    float s = 0.0f;
#pragma unroll 4
    for (int n = 0; n < rows; n++) {
        float v = A[(size_t)n * lda + j];
        s += w ? w[n] * v : v;
    }
    out[j] = s * scale;
}

// cat[n] = [ h[n] , gate(h)[n] ]
__global__ void gate_cat_kernel(const float* __restrict__ h,
                                const float* __restrict__ u,
                                const float* __restrict__ vsc,
                                const float* __restrict__ s,
                                float* __restrict__ cat)
{
    int idx = blockIdx.x * blockDim.x + threadIdx.x;
    if (idx >= N_NODES * G4) return;
    int n = idx / G4, j = idx % G4;
    float hv = h[(size_t)n * G4 + j];
    float h0 = h[j];
    float val;
    if (n == 0) {
        val = h0;
    } else {
        float g = sigm_(u[n] + vsc[0]);
        val = g * s[j] + (1.0f - g) * ((float)(N_NODES - 1) * h0);
    }
    cat[(size_t)n * 2400 + j] = hv;
    cat[(size_t)n * 2400 + 1200 + j] = val;
}

__global__ void att_softmax_kernel(const float* __restrict__ e1,
                                   const float* __restrict__ e2,
                                   const int* __restrict__ adj,
                                   float* __restrict__ att)
{
    __shared__ float warpred[4];
    __shared__ float s_max, s_sum;
    int i = blockIdx.x;
    float ei = e1[i];

    float mx = -3.4e38f;
    for (int j = threadIdx.x; j < N_NODES; j += blockDim.x) {
        float v = ei + e2[j];
        v = (v > 0.0f) ? v : 0.01f * v;
        if (adj[(size_t)i * N_NODES + j] <= 0) v = -9.0e15f;
        mx = fmaxf(mx, v);
    }
#pragma unroll
    for (int o = 16; o > 0; o >>= 1) mx = fmaxf(mx, __shfl_down_sync(0xffffffffu, mx, o));
    if ((threadIdx.x & 31) == 0) warpred[threadIdx.x >> 5] = mx;
    __syncthreads();
    if (threadIdx.x == 0) {
        float m2 = warpred[0];
        int nw = blockDim.x >> 5;
        for (int k = 1; k < nw; k++) m2 = fmaxf(m2, warpred[k]);
        s_max = m2;
    }
    __syncthreads();
    float smax = s_max;

    float sum = 0.0f;
    for (int j = threadIdx.x; j < N_NODES; j += blockDim.x) {
        float v = ei + e2[j];
        v = (v > 0.0f) ? v : 0.01f * v;
        if (adj[(size_t)i * N_NODES + j] <= 0) v = -9.0e15f;
        sum += expf(v - smax);
    }
#pragma unroll
    for (int o = 16; o > 0; o >>= 1) sum += __shfl_down_sync(0xffffffffu, sum, o);
    if ((threadIdx.x & 31) == 0) warpred[threadIdx.x >> 5] = sum;
    __syncthreads();
    if (threadIdx.x == 0) {
        float t = 0.0f;
        int nw = blockDim.x >> 5;
        for (int k = 0; k < nw; k++) t += warpred[k];
        s_sum = t;
    }
    __syncthreads();
    float inv = 1.0f / s_sum;

    for (int j = threadIdx.x; j < N_NODES; j += blockDim.x) {
        float v = ei + e2[j];
        v = (v > 0.0f) ? v : 0.01f * v;
        if (adj[(size_t)i * N_NODES + j] <= 0) v = -9.0e15f;
        att[(size_t)i * N_NODES + j] = expf(v - smax) * inv;
    }
}

// Z[n] = [hc, hs2[n], hc*hs2[n], hc-hs2[n]] -> hi/lo bf16 splits
__global__ void zassemble_kernel(const float* __restrict__ h2,
                                 bf16* __restrict__ Zh, bf16* __restrict__ Zl)
{
    int idx = blockIdx.x * blockDim.x + threadIdx.x;
    if (idx >= N_NODES * G4) return;
    int n = idx / G4, j = idx % G4;
    float a = h2[j];
    float b = h2[(size_t)n * G4 + j];
    size_t base = (size_t)n * 4800;
    split_bf16(a,     &Zh[base + j],        &Zl[base + j]);
    split_bf16(b,     &Zh[base + 1200 + j], &Zl[base + 1200 + j]);
    split_bf16(a * b, &Zh[base + 2400 + j], &Zl[base + 2400 + j]);
    split_bf16(a - b, &Zh[base + 3600 + j], &Zl[base + 3600 + j]);
}

__global__ void final_kernel(const float* __restrict__ ea,
                             const float* __restrict__ Wlin,
                             const float* __restrict__ blin,
                             float* __restrict__ out)
{
    __shared__ float r0[8], r1[8];
    float s0 = 0.0f, s1 = 0.0f;
    for (int j = threadIdx.x; j < 2400; j += blockDim.x) {
        float e = ea[j];
        s0 += e * Wlin[j];
        s1 += e * Wlin[2400 + j];
    }
#pragma unroll
    for (int o = 16; o > 0; o >>= 1) {
        s0 += __shfl_down_sync(0xffffffffu, s0, o);
        s1 += __shfl_down_sync(0xffffffffu, s1, o);
    }
    if ((threadIdx.x & 31) == 0) { r0[threadIdx.x >> 5] = s0; r1[threadIdx.x >> 5] = s1; }
    __syncthreads();
    if (threadIdx.x == 0) {
        float l0 = 0.0f, l1 = 0.0f;
        int nw = blockDim.x >> 5;
        for (int i = 0; i < nw; i++) { l0 += r0[i]; l1 += r1[i]; }
        l0 += blin[0]; l1 += blin[1];
        float m = fmaxf(l0, l1);
        float e0 = expf(l0 - m), e1v = expf(l1 - m);
        float inv = 1.0f / (e0 + e1v);
        out[0] = e0 * inv;
        out[1] = e1v * inv;
    }
}

// ---------------------------------------------------------------------------
// Host orchestration
// ---------------------------------------------------------------------------
static inline dim3 grid64(int M, int N)  { return dim3((N + BN - 1) / BN, (M + BM - 1) / BM); }
static inline dim3 gridT(int M, int N)   { return dim3((N + 127) / 128, (M + 127) / 128); }

static void run_gate_gat(const float* h_in, float* h_out,
                         const float* gate_W, const float* gate_U,
                         const float* W_gat, const float* a_gat,
                         const int* adj, float* pool)
{
    float* U   = pool + OFF_U;
    float* Vb  = pool + OFF_V;
    float* S   = pool + OFF_S;
    float* CAT = pool + OFF_CAT;
    float* WHp = pool + OFF_WH;
    float* E1  = pool + OFF_E1;
    float* E2  = pool + OFF_E2;
    float* ATT = pool + OFF_ATT;

    rows_dot_kernel<0><<<N_NODES, 256>>>(h_in, G4, gate_W, G4, U);
    rows_dot_kernel<0><<<1, 256>>>(h_in, G4, gate_U, G4, Vb);
    colsum_kernel<<<(G4 + 255) / 256, 256>>>(h_in + G4, G4, N_NODES - 1, nullptr, 1.0f, S, G4);
    gate_cat_kernel<<<(N_NODES * G4 + 255) / 256, 256>>>(h_in, U, Vb, S, CAT);

    gemm_kernel<0, 0><<<grid64(N_NODES, G4), 256>>>(
        N_NODES, G4, 2400, CAT, 2400, W_gat, G4, nullptr, 0, WHp, G4);
    rows_dot_kernel<0><<<N_NODES, 256>>>(WHp, G4, a_gat, G4, E1);
    rows_dot_kernel<0><<<N_NODES, 256>>>(WHp, G4, a_gat + G4, G4, E2);
    att_softmax_kernel<<<N_NODES, 128>>>(E1, E2, adj, ATT);
    gemm_kernel<0, 2><<<grid64(N_NODES, G4), 256>>>(
        N_NODES, G4, N_NODES, ATT, N_NODES, WHp, G4, nullptr, 0, h_out, G4);
}

extern "C" void kernel_launch(void* const* d_in, const int* in_sizes, int n_in,
                              void* d_out, int out_size)
{
    (void)in_sizes; (void)n_in; (void)out_size;

    float* pool = nullptr;
    cudaGetSymbolAddress((void**)&pool, g_pool);

    const int*   tokens  = (const int*)d_in[0];
    const int*   adj     = (const int*)d_in[1];
    const float* emb     = (const float*)d_in[2];
    const float* Wih_l0f = (const float*)d_in[3];
    const float* Whh_l0f = (const float*)d_in[4];
    const float* b_l0f   = (const float*)d_in[5];
    const float* Wih_l0b = (const float*)d_in[6];
    const float* Whh_l0b = (const float*)d_in[7];
    const float* b_l0b   = (const float*)d_in[8];
    const float* Wih_l1f = (const float*)d_in[9];
    const float* Whh_l1f = (const float*)d_in[10];
    const float* b_l1f   = (const float*)d_in[11];
    const float* Wih_l1b = (const float*)d_in[12];
    const float* Whh_l1b = (const float*)d_in[13];
    const float* b_l1b   = (const float*)d_in[14];
    const float* W_gat   = (const float*)d_in[15];
    const float* a_gat   = (const float*)d_in[16];
    const float* gate_W  = (const float*)d_in[17];
    const float* gate_U  = (const float*)d_in[18];
    const float* FC1     = (const float*)d_in[19];
    const float* FC2     = (const float*)d_in[20];
    const float* Wlin    = (const float*)d_in[21];
    const float* blin    = (const float*)d_in[22];
    float* out = (float*)d_out;

    float* PF   = pool + OFF_PF;
    float* PB   = pool + OFF_PB;
    bf16*  XH   = (bf16*)(pool + OFF_XH);
    bf16*  XL   = (bf16*)(pool + OFF_XL);
    bf16*  O0H  = (bf16*)(pool + OFF_O0H);
    bf16*  O0L  = (bf16*)(pool + OFF_O0L);
    float* HSA  = pool + OFF_HSA;
    float* HSB  = pool + OFF_HSB;
    float* C4   = pool + OFF_C4;
    float* HS1  = pool + OFF_HS1;
    float* HS2  = pool + OFF_HS2;
    bf16*  ZH   = (bf16*)(pool + OFF_ZH);
    bf16*  ZL   = (bf16*)(pool + OFF_ZL);
    float* HC3  = pool + OFF_HC3;
    float* WHHR  = pool + OFF_WHHR;
    float* WIHR0 = pool + OFF_WIHR0;
    float* WIHR1 = pool + OFF_WIHR1;
    bf16*  W0H  = (bf16*)(pool + OFF_W0H);
    bf16*  W0L  = (bf16*)(pool + OFF_W0L);
    bf16*  W1H  = (bf16*)(pool + OFF_W1H);
    bf16*  W1L  = (bf16*)(pool + OFF_W1L);
    bf16*  F1H  = (bf16*)(pool + OFF_F1H);
    bf16*  F1L  = (bf16*)(pool + OFF_F1L);
    float* BR   = pool + OFF_BR;
    float* BATT = pool + OFF_BATT;
    float* EA   = pool + OFF_EA;

    const int LN = L_SEQ * N_NODES;   // 17300
    const int thr = 256;
    const int g3 = (int)((SZ_W3 + thr - 1) / thr);
    const int g6 = (int)((SZ_W6 + thr - 1) / thr);
    const int g1 = (G4 + thr - 1) / thr;

    // ---- weight prep: reorder (gate-interleave) + bf16 splits ----
    reorder_rows_kernel<<<g3, thr>>>(Wih_l0f, WIHR0 + 0 * SZ_W3, 300);
    reorder_rows_kernel<<<g3, thr>>>(Wih_l0b, WIHR0 + 1 * SZ_W3, 300);
    reorder_rows_kernel<<<g6, thr>>>(Wih_l1f, WIHR1 + 0 * SZ_W6, 600);
    reorder_rows_kernel<<<g6, thr>>>(Wih_l1b, WIHR1 + 1 * SZ_W6, 600);
    reorder_rows_kernel<<<g3, thr>>>(Whh_l0f, WHHR + 0 * SZ_W3, 300);
    reorder_rows_kernel<<<g3, thr>>>(Whh_l0b, WHHR + 1 * SZ_W3, 300);
    reorder_rows_kernel<<<g3, thr>>>(Whh_l1f, WHHR + 2 * SZ_W3, 300);
    reorder_rows_kernel<<<g3, thr>>>(Whh_l1b, WHHR + 3 * SZ_W3, 300);
    reorder_rows_kernel<<<g1, thr>>>(b_l0f, BR + 0 * G4, 1);
    reorder_rows_kernel<<<g1, thr>>>(b_l0b, BR + 1 * G4, 1);
    reorder_rows_kernel<<<g1, thr>>>(b_l1f, BR + 2 * G4, 1);
    reorder_rows_kernel<<<g1, thr>>>(b_l1b, BR + 3 * G4, 1);
    split2_kernel<<<(int)((2 * SZ_W3 + 255) / 256), 256>>>(WIHR0, W0H, W0L, 2 * SZ_W3);
    split2_kernel<<<(int)((2 * SZ_W6 + 255) / 256), 256>>>(WIHR1, W1H, W1L, 2 * SZ_W6);
    split2_kernel<<<(int)((SZ_FC1 + 255) / 256), 256>>>(FC1, F1H, F1L, SZ_FC1);

    // ---- init states ----
    memzero_kernel<<<((int)SZ_NG4 + 255) / 256, 256>>>(HSA, (int)SZ_NG4);
    memzero_kernel<<<(4 * (int)SZ_NH + 255) / 256, 256>>>(C4, 4 * (int)SZ_NH);

    // ---- embedding (bf16 splits) ----
    embed_kernel<<<(int)((SZ_X + 255) / 256), 256>>>(tokens, emb, XH, XL);

    // ---- layer-0 input projections (tensor cores, bf16x3) ----
    bmma_kernel<1, 0><<<gridT(LN, G4), 256>>>(
        LN, G4, D_EMB, XH, XL, W0H, W0L, BR + 0 * G4, PF, G4);
    bmma_kernel<1, 0><<<gridT(LN, G4), 256>>>(
        LN, G4, D_EMB, XH, XL, W0H + SZ_W3, W0L + SZ_W3, BR + 1 * G4, PB, G4);

    // ---- layer-0 scan (fp32 fused GEMM+cell, h double-buffered) ----
    {
        dim3 grid = grid64(N_NODES, G4); grid.z = 2;
        const float* hin = HSA; float* hout = HSB;
        for (int t = 0; t < L_SEQ; t++) {
            lstm_fused_kernel<<<grid, 256>>>(
                hin, hout, 0, 300,
                WHHR + 0 * SZ_W3, WHHR + 1 * SZ_W3,
                PF + (size_t)t * N_NODES * G4,
                PB + (size_t)(L_SEQ - 1 - t) * N_NODES * G4,
                C4, O0H, O0L, t);
            const float* tmp = hin; hin = hout; hout = (float*)tmp;
        }
    }

    // ---- layer-1 input projections (tensor cores) ----
    bmma_kernel<1, 0><<<gridT(LN, G4), 256>>>(
        LN, G4, 600, O0H, O0L, W1H, W1L, BR + 2 * G4, PF, G4);
    bmma_kernel<1, 0><<<gridT(LN, G4), 256>>>(
        LN, G4, 600, O0H, O0L, W1H + SZ_W6, W1L + SZ_W6, BR + 3 * G4, PB, G4);

    // ---- layer-1 scan ----
    {
        dim3 grid = grid64(N_NODES, G4); grid.z = 2;
        const float* hin = HSA; float* hout = HSB;
        for (int t = 0; t < L_SEQ; t++) {
            lstm_fused_kernel<<<grid, 256>>>(
                hin, hout, 600, 900,
                WHHR + 2 * SZ_W3, WHHR + 3 * SZ_W3,
                PF + (size_t)t * N_NODES * G4,
                PB + (size_t)(L_SEQ - 1 - t) * N_NODES * G4,
                C4 + 2 * SZ_NH, nullptr, nullptr, t);
            const float* tmp = hin; hin = hout; hout = (float*)tmp;
        }
    }
    // L_SEQ=50 (even): final h for both layers lands in HSA.

    // ---- two gate+GAT stages (fp32) ----
    run_gate_gat(HSA, HS1, gate_W, gate_U, W_gat, a_gat, adj, pool);
    run_gate_gat(HS1, HS2, gate_W, gate_U, W_gat, a_gat, adj, pool);

    // ---- final head: FC1 on tensor cores ----
    zassemble_kernel<<<(N_NODES * G4 + 255) / 256, 256>>>(HS2, ZH, ZL);
    bmma_kernel<0, 1><<<gridT(N_NODES, 9600), 256>>>(
        N_NODES, 9600, 4800, ZH, ZL, F1H, F1L, nullptr, HC3, 9600);
    rows_dot_kernel<1><<<N_NODES, 256>>>(HC3, 9600, FC2, 9600, BATT);
    colsum_kernel<<<(G4 + 255) / 256, 256>>>(HS2, G4, N_NODES, nullptr,
                                             1.0f / (float)N_NODES, EA, G4);
    colsum_kernel<<<(G4 + 255) / 256, 256>>>(HS2, G4, N_NODES, BATT, 1.0f, EA + G4, G4);
    final_kernel<<<1, 256>>>(EA, Wlin, blin, out);
}

// round 9
// speedup vs baseline: 1.2961x; 1.2961x over previous
#include <cuda_runtime.h>
#include <math.h>

#define N_NODES 346
#define L_SEQ   50
#define D_EMB   300
#define H_HID   300
#define G4      1200   // 4*H

// ---------------------------------------------------------------------------
// Scratch pool (static device allocation — no cudaMalloc anywhere)
// ---------------------------------------------------------------------------
constexpr size_t A256(size_t x) { return (x + 255) & ~(size_t)255; }

constexpr size_t SZ_X   = (size_t)L_SEQ * N_NODES * D_EMB;
constexpr size_t SZ_P   = (size_t)L_SEQ * N_NODES * G4;
constexpr size_t SZ_O0  = (size_t)L_SEQ * N_NODES * 600;
constexpr size_t SZ_NG4 = (size_t)N_NODES * G4;
constexpr size_t SZ_NH  = (size_t)N_NODES * H_HID;

constexpr size_t OFF_X    = 0;
constexpr size_t OFF_P0F  = A256(OFF_X   + SZ_X);
constexpr size_t OFF_P0B  = A256(OFF_P0F + SZ_P);
constexpr size_t OFF_O0   = A256(OFF_P0B + SZ_P);
constexpr size_t OFF_HSA  = A256(OFF_O0  + SZ_O0);
constexpr size_t OFF_HSB  = A256(OFF_HSA + SZ_NG4);
constexpr size_t OFF_C4   = A256(OFF_HSB + SZ_NG4);
constexpr size_t OFF_CAT  = A256(OFF_C4  + 4 * SZ_NH);
constexpr size_t OFF_WH   = A256(OFF_CAT + (size_t)N_NODES * 2400);
constexpr size_t OFF_ATT  = A256(OFF_WH  + SZ_NG4);
constexpr size_t OFF_HS1  = A256(OFF_ATT + (size_t)N_NODES * N_NODES);
constexpr size_t OFF_HS2  = A256(OFF_HS1 + SZ_NG4);
constexpr size_t OFF_Z    = A256(OFF_HS2 + SZ_NG4);
constexpr size_t OFF_HC3  = A256(OFF_Z   + (size_t)N_NODES * 4800);
constexpr size_t OFF_WHHR  = A256(OFF_HC3  + (size_t)N_NODES * 9600);
constexpr size_t OFF_WIHR0 = A256(OFF_WHHR + 4 * (size_t)G4 * H_HID);
constexpr size_t OFF_WIHR1 = A256(OFF_WIHR0 + 2 * (size_t)G4 * 300);
constexpr size_t OFF_BR    = A256(OFF_WIHR1 + 2 * (size_t)G4 * 600);
constexpr size_t OFF_U    = A256(OFF_BR  + 4 * (size_t)G4);
constexpr size_t OFF_V    = A256(OFF_U   + 512);
constexpr size_t OFF_S    = A256(OFF_V   + 32);
constexpr size_t OFF_E1   = A256(OFF_S   + 1280);
constexpr size_t OFF_E2   = A256(OFF_E1  + 512);
constexpr size_t OFF_BATT = A256(OFF_E2  + 512);
constexpr size_t OFF_EA   = A256(OFF_BATT + 512);
constexpr size_t POOL_SZ  = A256(OFF_EA + 2560);

__device__ float g_pool[POOL_SZ];

__device__ __forceinline__ float sigm_(float x) { return 1.0f / (1.0f + expf(-x)); }

// ---------------------------------------------------------------------------
// 64x64x16 fp32 GEMM core (4x4 per thread) — GAT GEMMs
// ---------------------------------------------------------------------------
#define BM 64
#define BN 64
#define BK 16
#define SPAD 68

template<int TB>
__device__ __forceinline__ void gemm_acc64(
    int M, int N, int K,
    const float* __restrict__ A, int lda,
    const float* __restrict__ B, int ldb,
    float* As, float* Bs, float acc[4][4],
    int m0, int n0, int tid, int tx, int ty)
{
#pragma unroll
    for (int i = 0; i < 4; i++)
#pragma unroll
        for (int j = 0; j < 4; j++) acc[i][j] = 0.0f;

    for (int k0 = 0; k0 < K; k0 += BK) {
#pragma unroll
        for (int i = 0; i < 4; i++) {
            int idx = tid + i * 256;
            int m = idx >> 4, k = idx & 15;
            int gm = m0 + m, gk = k0 + k;
            As[k * SPAD + m] = (gm < M && gk < K) ? __ldg(&A[(size_t)gm * lda + gk]) : 0.0f;
        }
        if (TB) {
#pragma unroll
            for (int i = 0; i < 4; i++) {
                int idx = tid + i * 256;
                int j = idx >> 4, k = idx & 15;
                int gj = n0 + j, gk = k0 + k;
                Bs[k * SPAD + j] = (gj < N && gk < K) ? __ldg(&B[(size_t)gj * ldb + gk]) : 0.0f;
            }
        } else {
#pragma unroll
            for (int i = 0; i < 4; i++) {
                int idx = tid + i * 256;
                int j = idx & 63, k = idx >> 6;
                int gj = n0 + j, gk = k0 + k;
                Bs[k * SPAD + j] = (gj < N && gk < K) ? __ldg(&B[(size_t)gk * ldb + gj]) : 0.0f;
            }
        }
        __syncthreads();
#pragma unroll
        for (int kk = 0; kk < BK; kk++) {
            float4 av = *reinterpret_cast<const float4*>(&As[kk * SPAD + ty * 4]);
            float4 bv = *reinterpret_cast<const float4*>(&Bs[kk * SPAD + tx * 4]);
            float a[4] = {av.x, av.y, av.z, av.w};
            float b[4] = {bv.x, bv.y, bv.z, bv.w};
#pragma unroll
            for (int i = 0; i < 4; i++)
#pragma unroll
                for (int j = 0; j < 4; j++)
                    acc[i][j] += a[i] * b[j];
        }
        __syncthreads();
    }
}

template<int TB, int EPI>
__global__ void __launch_bounds__(256) gemm_kernel(
    int M, int N, int K,
    const float* __restrict__ A, int lda,
    const float* __restrict__ B, int ldb,
    const float* __restrict__ Dm, int ldd,
    float* __restrict__ C, int ldc)
{
    __shared__ float As[BK * SPAD], Bs[BK * SPAD];
    const int m0 = blockIdx.y * BM, n0 = blockIdx.x * BN;
    const int tid = threadIdx.x, tx = tid & 15, ty = tid >> 4;
    float acc[4][4];
    gemm_acc64<TB>(M, N, K, A, lda, B, ldb, As, Bs, acc, m0, n0, tid, tx, ty);

#pragma unroll
    for (int i = 0; i < 4; i++) {
        int gm = m0 + ty * 4 + i;
        if (gm >= M) continue;
#pragma unroll
        for (int j = 0; j < 4; j++) {
            int gn = n0 + tx * 4 + j;
            if (gn >= N) continue;
            float v = acc[i][j];
            if (Dm) v += (ldd == 0) ? Dm[gn] : Dm[(size_t)gm * ldd + gn];
            if (EPI == 1) v = tanhf(v);
            if (EPI == 2) v = (v > 0.0f) ? v : expm1f(v);
            C[(size_t)gm * ldc + gn] = v;
        }
    }
}

// ---------------------------------------------------------------------------
// 128x128x8 fp32 GEMM, 8x8 per thread — big feedforward GEMMs
// ---------------------------------------------------------------------------
#define XBM 128
#define XBN 128
#define XBK 8
#define XPAD 132

template<int TB, int EPI>
__global__ void __launch_bounds__(256) gemm128_kernel(
    int M, int N, int K,
    const float* __restrict__ A, int lda,
    const float* __restrict__ B, int ldb,
    const float* __restrict__ Dm, int ldd,
    float* __restrict__ C, int ldc)
{
    __shared__ float As[XBK * XPAD], Bs[XBK * XPAD];
    const int m0 = blockIdx.y * XBM, n0 = blockIdx.x * XBN;
    const int tid = threadIdx.x, tx = tid & 15, ty = tid >> 4;

    float acc[8][8];
#pragma unroll
    for (int i = 0; i < 8; i++)
#pragma unroll
        for (int j = 0; j < 8; j++) acc[i][j] = 0.0f;

    for (int k0 = 0; k0 < K; k0 += XBK) {
#pragma unroll
        for (int l = 0; l < 4; l++) {
            int idx = tid + l * 256;
            int m = idx >> 3, k = idx & 7;
            int gm = m0 + m, gk = k0 + k;
            As[k * XPAD + m] = (gm < M && gk < K) ? __ldg(&A[(size_t)gm * lda + gk]) : 0.0f;
        }
        if (TB) {
#pragma unroll
            for (int l = 0; l < 4; l++) {
                int idx = tid + l * 256;
                int j = idx >> 3, k = idx & 7;
                int gj = n0 + j, gk = k0 + k;
                Bs[k * XPAD + j] = (gj < N && gk < K) ? __ldg(&B[(size_t)gj * ldb + gk]) : 0.0f;
            }
        } else {
#pragma unroll
            for (int l = 0; l < 4; l++) {
                int idx = tid + l * 256;
                int k = idx >> 7, j = idx & 127;
                int gj = n0 + j, gk = k0 + k;
                Bs[k * XPAD + j] = (gj < N && gk < K) ? __ldg(&B[(size_t)gk * ldb + gj]) : 0.0f;
            }
        }
        __syncthreads();
#pragma unroll
        for (int kk = 0; kk < XBK; kk++) {
            float a[8], b[8];
            float4 a0 = *reinterpret_cast<const float4*>(&As[kk * XPAD + ty * 8]);
            float4 a1 = *reinterpret_cast<const float4*>(&As[kk * XPAD + ty * 8 + 4]);
            float4 b0 = *reinterpret_cast<const float4*>(&Bs[kk * XPAD + tx * 8]);
            float4 b1 = *reinterpret_cast<const float4*>(&Bs[kk * XPAD + tx * 8 + 4]);
            a[0]=a0.x; a[1]=a0.y; a[2]=a0.z; a[3]=a0.w;
            a[4]=a1.x; a[5]=a1.y; a[6]=a1.z; a[7]=a1.w;
            b[0]=b0.x; b[1]=b0.y; b[2]=b0.z; b[3]=b0.w;
            b[4]=b1.x; b[5]=b1.y; b[6]=b1.z; b[7]=b1.w;
#pragma unroll
            for (int i = 0; i < 8; i++)
#pragma unroll
                for (int j = 0; j < 8; j++)
                    acc[i][j] += a[i] * b[j];
        }
        __syncthreads();
    }

#pragma unroll
    for (int i = 0; i < 8; i++) {
        int gm = m0 + ty * 8 + i;
        if (gm >= M) continue;
#pragma unroll
        for (int j = 0; j < 8; j++) {
            int gn = n0 + tx * 8 + j;
            if (gn >= N) continue;
            float v = acc[i][j];
            if (Dm) v += (ldd == 0) ? Dm[gn] : Dm[(size_t)gm * ldd + gn];
            if (EPI == 1) v = tanhf(v);
            if (EPI == 2) v = (v > 0.0f) ? v : expm1f(v);
            C[(size_t)gm * ldc + gn] = v;
        }
    }
}

// ---------------------------------------------------------------------------
// Fused LSTM step: 64x128 tile (4 rows x 8 gate-cols per thread), single-wave
// grid (10,6,2)=120 blocks. Weights/P gate-interleaved (row r = j*4+gate), so
// each thread's two 4-col quads are (i,f,g,o) of hidden units j0, j0+1.
// ---------------------------------------------------------------------------
#define LBN 128
#define LPAD 136

__global__ void __launch_bounds__(256) lstm_fused_kernel(
    const float* __restrict__ hs_in, float* __restrict__ hs_out,
    int hcol_f, int hcol_b,
    const float* __restrict__ Whh_rf, const float* __restrict__ Whh_rb,
    const float* __restrict__ Pf, const float* __restrict__ Pb,
    float* __restrict__ cbuf,            // [2][N][H]
    float* __restrict__ outbuf, int t)   // o0 or null
{
    __shared__ float As[BK * SPAD];    // 16 x 68
    __shared__ float Bs[BK * LPAD];    // 16 x 136
    const int z = blockIdx.z;
    const int hcol = z ? hcol_b : hcol_f;
    const float* A = hs_in + hcol;
    const float* Bw = z ? Whh_rb : Whh_rf;
    const float* P  = z ? Pb : Pf;

    const int m0 = blockIdx.y * BM, n0 = blockIdx.x * LBN;
    const int tid = threadIdx.x, tx = tid & 15, ty = tid >> 4;

    float acc[4][8];
#pragma unroll
    for (int i = 0; i < 4; i++)
#pragma unroll
        for (int j = 0; j < 8; j++) acc[i][j] = 0.0f;

    for (int k0 = 0; k0 < H_HID; k0 += BK) {
        // A tile 64x16 (1024 elems, 4/thread)
#pragma unroll
        for (int i = 0; i < 4; i++) {
            int idx = tid + i * 256;
            int m = idx >> 4, k = idx & 15;
            int gm = m0 + m, gk = k0 + k;
            As[k * SPAD + m] = (gm < N_NODES && gk < H_HID) ? __ldg(&A[(size_t)gm * G4 + gk]) : 0.0f;
        }
        // B tile 128x16 (2048 elems, 8/thread), B row-major [G4][H_HID]
#pragma unroll
        for (int i = 0; i < 8; i++) {
            int idx = tid + i * 256;
            int j = idx >> 4, k = idx & 15;
            int gj = n0 + j, gk = k0 + k;
            Bs[k * LPAD + j] = (gj < G4 && gk < H_HID) ? __ldg(&Bw[(size_t)gj * H_HID + gk]) : 0.0f;
        }
        __syncthreads();
#pragma unroll
        for (int kk = 0; kk < BK; kk++) {
            float4 av = *reinterpret_cast<const float4*>(&As[kk * SPAD + ty * 4]);
            float4 b0 = *reinterpret_cast<const float4*>(&Bs[kk * LPAD + tx * 8]);
            float4 b1 = *reinterpret_cast<const float4*>(&Bs[kk * LPAD + tx * 8 + 4]);
            float a[4] = {av.x, av.y, av.z, av.w};
            float b[8] = {b0.x, b0.y, b0.z, b0.w, b1.x, b1.y, b1.z, b1.w};
#pragma unroll
            for (int i = 0; i < 4; i++)
#pragma unroll
                for (int j = 0; j < 8; j++)
                    acc[i][j] += a[i] * b[j];
        }
        __syncthreads();
    }

    const int r0 = n0 + tx * 8;          // multiple of 8; whole group valid iff r0 < G4
    if (r0 >= G4) return;
    const int j0 = r0 >> 2;              // hidden units j0, j0+1
    float* c = cbuf + (size_t)z * N_NODES * H_HID;

#pragma unroll
    for (int i = 0; i < 4; i++) {
        int gm = m0 + ty * 4 + i;
        if (gm >= N_NODES) continue;
        float4 p0 = *reinterpret_cast<const float4*>(P + (size_t)gm * G4 + r0);
        float4 p1 = *reinterpret_cast<const float4*>(P + (size_t)gm * G4 + r0 + 4);
#pragma unroll
        for (int q = 0; q < 2; q++) {
            int ju = j0 + q;
            float gi = acc[i][4 * q + 0] + (q ? p1.x : p0.x);
            float gf = acc[i][4 * q + 1] + (q ? p1.y : p0.y);
            float gg = acc[i][4 * q + 2] + (q ? p1.z : p0.z);
            float go = acc[i][4 * q + 3] + (q ? p1.w : p0.w);
            float cp = c[(size_t)gm * H_HID + ju];
            float cn = sigm_(gf) * cp + sigm_(gi) * tanhf(gg);
            float h  = sigm_(go) * tanhf(cn);
            c[(size_t)gm * H_HID + ju] = cn;
            hs_out[(size_t)gm * G4 + hcol + ju] = h;
            if (outbuf) {
                int tt = z ? (L_SEQ - 1 - t) : t;
                outbuf[(size_t)tt * N_NODES * 600 + (size_t)gm * 600 + z * H_HID + ju] = h;
            }
        }
    }
}

// Reorder LSTM weight rows: out[j*4+g][k] = in[g*H + j][k]
__global__ void reorder_rows_kernel(const float* __restrict__ in,
                                    float* __restrict__ out, int K)
{
    size_t idx = (size_t)blockIdx.x * blockDim.x + threadIdx.x;
    if (idx >= (size_t)G4 * K) return;
    int r = (int)(idx / K), k = (int)(idx % K);
    int j = r >> 2, g = r & 3;
    out[(size_t)r * K + k] = in[(size_t)(g * H_HID + j) * K + k];
}

__global__ void memzero_kernel(float* p, int n)
{
    int i = blockIdx.x * blockDim.x + threadIdx.x;
    if (i < n) p[i] = 0.0f;
}

__global__ void embed_kernel(const int* __restrict__ tok,
                             const float* __restrict__ emb,
                             float* __restrict__ x)
{
    size_t idx = (size_t)blockIdx.x * blockDim.x + threadIdx.x;
    const size_t total = (size_t)L_SEQ * N_NODES * D_EMB;
    if (idx >= total) return;
    int d = (int)(idx % D_EMB);
    size_t r = idx / D_EMB;
    int n = (int)(r % N_NODES);
    int t = (int)(r / N_NODES);
    int tv = tok[n * L_SEQ + t];
    x[idx] = emb[(size_t)tv * D_EMB + d];
}

// out[row] = epi( dot(A[row,:K], w) )
template<int EPI>
__global__ void rows_dot_kernel(const float* __restrict__ A, int lda,
                                const float* __restrict__ w, int K,
                                float* __restrict__ out)
{
    __shared__ float red[8];
    const float* a = A + (size_t)blockIdx.x * lda;
    float s = 0.0f;
    for (int k = threadIdx.x; k < K; k += blockDim.x) s += a[k] * w[k];
#pragma unroll
    for (int o = 16; o > 0; o >>= 1) s += __shfl_down_sync(0xffffffffu, s, o);
    if ((threadIdx.x & 31) == 0) red[threadIdx.x >> 5] = s;
    __syncthreads();
    if (threadIdx.x == 0) {
        float t = 0.0f;
        int nw = blockDim.x >> 5;
        for (int i = 0; i < nw; i++) t += red[i];
        if (EPI == 1) t = tanhf(t);
        out[blockIdx.x] = t;
    }
}

// out[j] = scale * sum_n (w ? w[n] : 1) * A[n*lda + j]
__global__ void colsum_kernel(const float* __restrict__ A, int lda, int rows,
                              const float* __restrict__ w, float scale,
                              float* __restrict__ out, int ncols)
{
    int j = blockIdx.x * blockDim.x + threadIdx.x;
    if (j >= ncols) return;
    float s = 0.0f;
#pragma unroll 4
    for (int n = 0; n < rows; n++) {
        float v = A[(size_t)n * lda + j];
        s += w ? w[n] * v : v;
    }
    out[j] = s * scale;
}

// cat[n] = [ h[n] , gate(h)[n] ]
__global__ void gate_cat_kernel(const float* __restrict__ h,
                                const float* __restrict__ u,
                                const float* __restrict__ vsc,
                                const float* __restrict__ s,
                                float* __restrict__ cat)
{
    int idx = blockIdx.x * blockDim.x + threadIdx.x;
    if (idx >= N_NODES * G4) return;
    int n = idx / G4, j = idx % G4;
    float hv = h[(size_t)n * G4 + j];
    float h0 = h[j];
    float val;
    if (n == 0) {
        val = h0;
    } else {
        float g = sigm_(u[n] + vsc[0]);
        val = g * s[j] + (1.0f - g) * ((float)(N_NODES - 1) * h0);
    }
    cat[(size_t)n * 2400 + j] = hv;
    cat[(size_t)n * 2400 + 1200 + j] = val;
}

__global__ void att_softmax_kernel(const float* __restrict__ e1,
                                   const float* __restrict__ e2,
                                   const int* __restrict__ adj,
                                   float* __restrict__ att)
{
    __shared__ float warpred[4];
    __shared__ float s_max, s_sum;
    int i = blockIdx.x;
    float ei = e1[i];

    float mx = -3.4e38f;
    for (int j = threadIdx.x; j < N_NODES; j += blockDim.x) {
        float v = ei + e2[j];
        v = (v > 0.0f) ? v : 0.01f * v;
        if (adj[(size_t)i * N_NODES + j] <= 0) v = -9.0e15f;
        mx = fmaxf(mx, v);
    }
#pragma unroll
    for (int o = 16; o > 0; o >>= 1) mx = fmaxf(mx, __shfl_down_sync(0xffffffffu, mx, o));
    if ((threadIdx.x & 31) == 0) warpred[threadIdx.x >> 5] = mx;
    __syncthreads();
    if (threadIdx.x == 0) {
        float m2 = warpred[0];
        int nw = blockDim.x >> 5;
        for (int k = 1; k < nw; k++) m2 = fmaxf(m2, warpred[k]);
        s_max = m2;
    }
    __syncthreads();
    float smax = s_max;

    float sum = 0.0f;
    for (int j = threadIdx.x; j < N_NODES; j += blockDim.x) {
        float v = ei + e2[j];
        v = (v > 0.0f) ? v : 0.01f * v;
        if (adj[(size_t)i * N_NODES + j] <= 0) v = -9.0e15f;
        sum += expf(v - smax);
    }
#pragma unroll
    for (int o = 16; o > 0; o >>= 1) sum += __shfl_down_sync(0xffffffffu, sum, o);
    if ((threadIdx.x & 31) == 0) warpred[threadIdx.x >> 5] = sum;
    __syncthreads();
    if (threadIdx.x == 0) {
        float t = 0.0f;
        int nw = blockDim.x >> 5;
        for (int k = 0; k < nw; k++) t += warpred[k];
        s_sum = t;
    }
    __syncthreads();
    float inv = 1.0f / s_sum;

    for (int j = threadIdx.x; j < N_NODES; j += blockDim.x) {
        float v = ei + e2[j];
        v = (v > 0.0f) ? v : 0.01f * v;
        if (adj[(size_t)i * N_NODES + j] <= 0) v = -9.0e15f;
        att[(size_t)i * N_NODES + j] = expf(v - smax) * inv;
    }
}

// Z[n] = [hc, hs2[n], hc*hs2[n], hc - hs2[n]],  hc = hs2[0]
__global__ void zassemble_kernel(const float* __restrict__ h2, float* __restrict__ Z)
{
    int idx = blockIdx.x * blockDim.x + threadIdx.x;
    if (idx >= N_NODES * G4) return;
    int n = idx / G4, j = idx % G4;
    float a = h2[j];
    float b = h2[(size_t)n * G4 + j];
    size_t base = (size_t)n * 4800;
    Z[base + j]        = a;
    Z[base + 1200 + j] = b;
    Z[base + 2400 + j] = a * b;
    Z[base + 3600 + j] = a - b;
}

__global__ void final_kernel(const float* __restrict__ ea,
                             const float* __restrict__ Wlin,
                             const float* __restrict__ blin,
                             float* __restrict__ out)
{
    __shared__ float r0[8], r1[8];
    float s0 = 0.0f, s1 = 0.0f;
    for (int j = threadIdx.x; j < 2400; j += blockDim.x) {
        float e = ea[j];
        s0 += e * Wlin[j];
        s1 += e * Wlin[2400 + j];
    }
#pragma unroll
    for (int o = 16; o > 0; o >>= 1) {
        s0 += __shfl_down_sync(0xffffffffu, s0, o);
        s1 += __shfl_down_sync(0xffffffffu, s1, o);
    }
    if ((threadIdx.x & 31) == 0) { r0[threadIdx.x >> 5] = s0; r1[threadIdx.x >> 5] = s1; }
    __syncthreads();
    if (threadIdx.x == 0) {
        float l0 = 0.0f, l1 = 0.0f;
        int nw = blockDim.x >> 5;
        for (int i = 0; i < nw; i++) { l0 += r0[i]; l1 += r1[i]; }
        l0 += blin[0]; l1 += blin[1];
        float m = fmaxf(l0, l1);
        float e0 = expf(l0 - m), e1v = expf(l1 - m);
        float inv = 1.0f / (e0 + e1v);
        out[0] = e0 * inv;
        out[1] = e1v * inv;
    }
}

// ---------------------------------------------------------------------------
// Host orchestration
// ---------------------------------------------------------------------------
static inline dim3 grid64(int M, int N)  { return dim3((N + BN - 1) / BN, (M + BM - 1) / BM); }
static inline dim3 grid128(int M, int N) { return dim3((N + XBN - 1) / XBN, (M + XBM - 1) / XBM); }

static void run_gate_gat(const float* h_in, float* h_out,
                         const float* gate_W, const float* gate_U,
                         const float* W_gat, const float* a_gat,
                         const int* adj, float* pool)
{
    float* U   = pool + OFF_U;
    float* Vb  = pool + OFF_V;
    float* S   = pool + OFF_S;
    float* CAT = pool + OFF_CAT;
    float* WHp = pool + OFF_WH;
    float* E1  = pool + OFF_E1;
    float* E2  = pool + OFF_E2;
    float* ATT = pool + OFF_ATT;

    rows_dot_kernel<0><<<N_NODES, 256>>>(h_in, G4, gate_W, G4, U);
    rows_dot_kernel<0><<<1, 256>>>(h_in, G4, gate_U, G4, Vb);
    colsum_kernel<<<(G4 + 255) / 256, 256>>>(h_in + G4, G4, N_NODES - 1, nullptr, 1.0f, S, G4);
    gate_cat_kernel<<<(N_NODES * G4 + 255) / 256, 256>>>(h_in, U, Vb, S, CAT);

    gemm_kernel<0, 0><<<grid64(N_NODES, G4), 256>>>(
        N_NODES, G4, 2400, CAT, 2400, W_gat, G4, nullptr, 0, WHp, G4);
    rows_dot_kernel<0><<<N_NODES, 256>>>(WHp, G4, a_gat, G4, E1);
    rows_dot_kernel<0><<<N_NODES, 256>>>(WHp, G4, a_gat + G4, G4, E2);
    att_softmax_kernel<<<N_NODES, 128>>>(E1, E2, adj, ATT);
    gemm_kernel<0, 2><<<grid64(N_NODES, G4), 256>>>(
        N_NODES, G4, N_NODES, ATT, N_NODES, WHp, G4, nullptr, 0, h_out, G4);
}

extern "C" void kernel_launch(void* const* d_in, const int* in_sizes, int n_in,
                              void* d_out, int out_size)
{
    (void)in_sizes; (void)n_in; (void)out_size;

    float* pool = nullptr;
    cudaGetSymbolAddress((void**)&pool, g_pool);

    const int*   tokens  = (const int*)d_in[0];
    const int*   adj     = (const int*)d_in[1];
    const float* emb     = (const float*)d_in[2];
    const float* Wih_l0f = (const float*)d_in[3];
    const float* Whh_l0f = (const float*)d_in[4];
    const float* b_l0f   = (const float*)d_in[5];
    const float* Wih_l0b = (const float*)d_in[6];
    const float* Whh_l0b = (const float*)d_in[7];
    const float* b_l0b   = (const float*)d_in[8];
    const float* Wih_l1f = (const float*)d_in[9];
    const float* Whh_l1f = (const float*)d_in[10];
    const float* b_l1f   = (const float*)d_in[11];
    const float* Wih_l1b = (const float*)d_in[12];
    const float* Whh_l1b = (const float*)d_in[13];
    const float* b_l1b   = (const float*)d_in[14];
    const float* W_gat   = (const float*)d_in[15];
    const float* a_gat   = (const float*)d_in[16];
    const float* gate_W  = (const float*)d_in[17];
    const float* gate_U  = (const float*)d_in[18];
    const float* FC1     = (const float*)d_in[19];
    const float* FC2     = (const float*)d_in[20];
    const float* Wlin    = (const float*)d_in[21];
    const float* blin    = (const float*)d_in[22];
    float* out = (float*)d_out;

    float* X    = pool + OFF_X;
    float* PF   = pool + OFF_P0F;
    float* PB   = pool + OFF_P0B;
    float* O0   = pool + OFF_O0;
    float* HSA  = pool + OFF_HSA;
    float* HSB  = pool + OFF_HSB;
    float* C4   = pool + OFF_C4;
    float* HS1  = pool + OFF_HS1;
    float* HS2  = pool + OFF_HS2;
    float* Z    = pool + OFF_Z;
    float* HC3  = pool + OFF_HC3;
    float* WHHR  = pool + OFF_WHHR;   // 4 x [1200][300]: l0f,l0b,l1f,l1b
    float* WIHR0 = pool + OFF_WIHR0;  // 2 x [1200][300]
    float* WIHR1 = pool + OFF_WIHR1;  // 2 x [1200][600]
    float* BR    = pool + OFF_BR;     // 4 x [1200]
    float* BATT = pool + OFF_BATT;
    float* EA   = pool + OFF_EA;

    const int LN = L_SEQ * N_NODES;   // 17300
    const size_t W3 = (size_t)G4 * 300, W6 = (size_t)G4 * 600;

    const int thr = 256;
    const int g3 = (int)((W3 + thr - 1) / thr), g6 = (int)((W6 + thr - 1) / thr);
    const int g1 = (G4 + thr - 1) / thr;

    // ---- weight reorders (gate-interleaved rows) ----
    reorder_rows_kernel<<<g3, thr>>>(Wih_l0f, WIHR0 + 0 * W3, 300);
    reorder_rows_kernel<<<g3, thr>>>(Wih_l0b, WIHR0 + 1 * W3, 300);
    reorder_rows_kernel<<<g3, thr>>>(Whh_l0f, WHHR + 0 * W3, 300);
    reorder_rows_kernel<<<g3, thr>>>(Whh_l0b, WHHR + 1 * W3, 300);
    reorder_rows_kernel<<<g3, thr>>>(Whh_l1f, WHHR + 2 * W3, 300);
    reorder_rows_kernel<<<g3, thr>>>(Whh_l1b, WHHR + 3 * W3, 300);
    reorder_rows_kernel<<<g6, thr>>>(Wih_l1f, WIHR1 + 0 * W6, 600);
    reorder_rows_kernel<<<g6, thr>>>(Wih_l1b, WIHR1 + 1 * W6, 600);
    reorder_rows_kernel<<<g1, thr>>>(b_l0f, BR + 0 * G4, 1);
    reorder_rows_kernel<<<g1, thr>>>(b_l0b, BR + 1 * G4, 1);
    reorder_rows_kernel<<<g1, thr>>>(b_l1f, BR + 2 * G4, 1);
    reorder_rows_kernel<<<g1, thr>>>(b_l1b, BR + 3 * G4, 1);

    // ---- init states ----
    memzero_kernel<<<((int)SZ_NG4 + 255) / 256, 256>>>(HSA, (int)SZ_NG4);
    memzero_kernel<<<(4 * (int)SZ_NH + 255) / 256, 256>>>(C4, 4 * (int)SZ_NH);

    // ---- embedding ----
    embed_kernel<<<(int)((SZ_X + 255) / 256), 256>>>(tokens, emb, X);

    // ---- layer-0 input projections ----
    gemm128_kernel<1, 0><<<grid128(LN, G4), 256>>>(
        LN, G4, D_EMB, X, D_EMB, WIHR0 + 0 * W3, 300, BR + 0 * G4, 0, PF, G4);
    gemm128_kernel<1, 0><<<grid128(LN, G4), 256>>>(
        LN, G4, D_EMB, X, D_EMB, WIHR0 + 1 * W3, 300, BR + 1 * G4, 0, PB, G4);

    // ---- layer-0 scan (fused GEMM+cell, single-wave 64x128 tiles) ----
    {
        dim3 grid((G4 + LBN - 1) / LBN, (N_NODES + BM - 1) / BM, 2);  // (10,6,2)
        const float* hin = HSA; float* hout = HSB;
        for (int t = 0; t < L_SEQ; t++) {
            lstm_fused_kernel<<<grid, 256>>>(
                hin, hout, 0, 300,
                WHHR + 0 * W3, WHHR + 1 * W3,
                PF + (size_t)t * N_NODES * G4,
                PB + (size_t)(L_SEQ - 1 - t) * N_NODES * G4,
                C4, O0, t);
            const float* tmp = hin; hin = hout; hout = (float*)tmp;
        }
    }

    // ---- layer-1 input projections ----
    gemm128_kernel<1, 0><<<grid128(LN, G4), 256>>>(
        LN, G4, 600, O0, 600, WIHR1 + 0 * W6, 600, BR + 2 * G4, 0, PF, G4);
    gemm128_kernel<1, 0><<<grid128(LN, G4), 256>>>(
        LN, G4, 600, O0, 600, WIHR1 + 1 * W6, 600, BR + 3 * G4, 0, PB, G4);

    // ---- layer-1 scan ----
    {
        dim3 grid((G4 + LBN - 1) / LBN, (N_NODES + BM - 1) / BM, 2);
        const float* hin = HSA; float* hout = HSB;
        for (int t = 0; t < L_SEQ; t++) {
            lstm_fused_kernel<<<grid, 256>>>(
                hin, hout, 600, 900,
                WHHR + 2 * W3, WHHR + 3 * W3,
                PF + (size_t)t * N_NODES * G4,
                PB + (size_t)(L_SEQ - 1 - t) * N_NODES * G4,
                C4 + 2 * SZ_NH, nullptr, t);
            const float* tmp = hin; hin = hout; hout = (float*)tmp;
        }
    }
    // L_SEQ=50 (even): final h for both layers lands in HSA.

    // ---- two gate+GAT stages ----
    run_gate_gat(HSA, HS1, gate_W, gate_U, W_gat, a_gat, adj, pool);
    run_gate_gat(HS1, HS2, gate_W, gate_U, W_gat, a_gat, adj, pool);

    // ---- final head ----
    zassemble_kernel<<<(N_NODES * G4 + 255) / 256, 256>>>(HS2, Z);
    gemm128_kernel<0, 1><<<grid128(N_NODES, 9600), 256>>>(
        N_NODES, 9600, 4800, Z, 4800, FC1, 9600, nullptr, 0, HC3, 9600);
    rows_dot_kernel<1><<<N_NODES, 256>>>(HC3, 9600, FC2, 9600, BATT);
    colsum_kernel<<<(G4 + 255) / 256, 256>>>(HS2, G4, N_NODES, nullptr,
                                             1.0f / (float)N_NODES, EA, G4);
    colsum_kernel<<<(G4 + 255) / 256, 256>>>(HS2, G4, N_NODES, BATT, 1.0f, EA + G4, G4);
    final_kernel<<<1, 256>>>(EA, Wlin, blin, out);
}

// round 10
// speedup vs baseline: 1.6569x; 1.2784x over previous
#include <cuda_runtime.h>
#include <math.h>

#define N_NODES 346
#define L_SEQ   50
#define D_EMB   300
#define H_HID   300
#define G4      1200   // 4*H

// ---------------------------------------------------------------------------
// Scratch pool (static device allocation — no cudaMalloc anywhere)
// ---------------------------------------------------------------------------
constexpr size_t A256(size_t x) { return (x + 255) & ~(size_t)255; }

constexpr size_t SZ_X   = (size_t)L_SEQ * N_NODES * D_EMB;
constexpr size_t SZ_P   = (size_t)L_SEQ * N_NODES * G4;
constexpr size_t SZ_O0  = (size_t)L_SEQ * N_NODES * 600;
constexpr size_t SZ_NG4 = (size_t)N_NODES * G4;
constexpr size_t SZ_NH  = (size_t)N_NODES * H_HID;

constexpr size_t OFF_X    = 0;
constexpr size_t OFF_P0F  = A256(OFF_X   + SZ_X);
constexpr size_t OFF_P0B  = A256(OFF_P0F + SZ_P);
constexpr size_t OFF_O0   = A256(OFF_P0B + SZ_P);
constexpr size_t OFF_HSA  = A256(OFF_O0  + SZ_O0);
constexpr size_t OFF_HSB  = A256(OFF_HSA + SZ_NG4);
constexpr size_t OFF_C4   = A256(OFF_HSB + SZ_NG4);
constexpr size_t OFF_CAT  = A256(OFF_C4  + 4 * SZ_NH);
constexpr size_t OFF_WH   = A256(OFF_CAT + (size_t)N_NODES * 2400);
constexpr size_t OFF_ATT  = A256(OFF_WH  + SZ_NG4);
constexpr size_t OFF_HS1  = A256(OFF_ATT + (size_t)N_NODES * N_NODES);
constexpr size_t OFF_HS2  = A256(OFF_HS1 + SZ_NG4);
constexpr size_t OFF_Z    = A256(OFF_HS2 + SZ_NG4);
constexpr size_t OFF_HC3  = A256(OFF_Z   + (size_t)N_NODES * 4800);
constexpr size_t OFF_WHHR  = A256(OFF_HC3  + (size_t)N_NODES * 9600);
constexpr size_t OFF_WIHR0 = A256(OFF_WHHR + 4 * (size_t)G4 * H_HID);
constexpr size_t OFF_WIHR1 = A256(OFF_WIHR0 + 2 * (size_t)G4 * 300);
constexpr size_t OFF_BR    = A256(OFF_WIHR1 + 2 * (size_t)G4 * 600);
constexpr size_t OFF_U    = A256(OFF_BR  + 4 * (size_t)G4);
constexpr size_t OFF_V    = A256(OFF_U   + 512);
constexpr size_t OFF_S    = A256(OFF_V   + 32);
constexpr size_t OFF_E1   = A256(OFF_S   + 1280);
constexpr size_t OFF_E2   = A256(OFF_E1  + 512);
constexpr size_t OFF_BATT = A256(OFF_E2  + 512);
constexpr size_t OFF_EA   = A256(OFF_BATT + 512);
constexpr size_t POOL_SZ  = A256(OFF_EA + 2560);

__device__ float g_pool[POOL_SZ];

__device__ __forceinline__ float sigm_(float x) { return 1.0f / (1.0f + expf(-x)); }

// ---------------------------------------------------------------------------
// 64x64x16 fp32 GEMM core, double-buffered (prefetch next tile into regs
// during compute; one barrier per k-tile).
// ---------------------------------------------------------------------------
#define BM 64
#define BN 64
#define BK 16
#define SPAD 68

template<int TB>
__device__ __forceinline__ void gemm_acc64(
    int M, int N, int K,
    const float* __restrict__ A, int lda,
    const float* __restrict__ B, int ldb,
    float (*As)[BK * SPAD], float (*Bs)[BK * SPAD], float acc[4][4],
    int m0, int n0, int tid, int tx, int ty)
{
#pragma unroll
    for (int i = 0; i < 4; i++)
#pragma unroll
        for (int j = 0; j < 4; j++) acc[i][j] = 0.0f;

    const int nt = (K + BK - 1) / BK;

    // prologue: tile 0 direct to smem buffer 0
#pragma unroll
    for (int i = 0; i < 4; i++) {
        int idx = tid + i * 256;
        int m = idx >> 4, k = idx & 15;
        int gm = m0 + m, gk = k;
        As[0][k * SPAD + m] = (gm < M && gk < K) ? __ldg(&A[(size_t)gm * lda + gk]) : 0.0f;
    }
    if (TB) {
#pragma unroll
        for (int i = 0; i < 4; i++) {
            int idx = tid + i * 256;
            int j = idx >> 4, k = idx & 15;
            int gj = n0 + j, gk = k;
            Bs[0][k * SPAD + j] = (gj < N && gk < K) ? __ldg(&B[(size_t)gj * ldb + gk]) : 0.0f;
        }
    } else {
#pragma unroll
        for (int i = 0; i < 4; i++) {
            int idx = tid + i * 256;
            int j = idx & 63, k = idx >> 6;
            int gj = n0 + j, gk = k;
            Bs[0][k * SPAD + j] = (gj < N && gk < K) ? __ldg(&B[(size_t)gk * ldb + gj]) : 0.0f;
        }
    }
    __syncthreads();

    float ra[4], rb[4];
    for (int t = 0; t < nt; t++) {
        const int cur = t & 1;
        const bool more = (t + 1 < nt);
        if (more) {
            int k0 = (t + 1) * BK;
#pragma unroll
            for (int i = 0; i < 4; i++) {
                int idx = tid + i * 256;
                int m = idx >> 4, k = idx & 15;
                int gm = m0 + m, gk = k0 + k;
                ra[i] = (gm < M && gk < K) ? __ldg(&A[(size_t)gm * lda + gk]) : 0.0f;
            }
            if (TB) {
#pragma unroll
                for (int i = 0; i < 4; i++) {
                    int idx = tid + i * 256;
                    int j = idx >> 4, k = idx & 15;
                    int gj = n0 + j, gk = k0 + k;
                    rb[i] = (gj < N && gk < K) ? __ldg(&B[(size_t)gj * ldb + gk]) : 0.0f;
                }
            } else {
#pragma unroll
                for (int i = 0; i < 4; i++) {
                    int idx = tid + i * 256;
                    int j = idx & 63, k = idx >> 6;
                    int gj = n0 + j, gk = k0 + k;
                    rb[i] = (gj < N && gk < K) ? __ldg(&B[(size_t)gk * ldb + gj]) : 0.0f;
                }
            }
        }
#pragma unroll
        for (int kk = 0; kk < BK; kk++) {
            float4 av = *reinterpret_cast<const float4*>(&As[cur][kk * SPAD + ty * 4]);
            float4 bv = *reinterpret_cast<const float4*>(&Bs[cur][kk * SPAD + tx * 4]);
            float a[4] = {av.x, av.y, av.z, av.w};
            float b[4] = {bv.x, bv.y, bv.z, bv.w};
#pragma unroll
            for (int i = 0; i < 4; i++)
#pragma unroll
                for (int j = 0; j < 4; j++)
                    acc[i][j] += a[i] * b[j];
        }
        if (more) {
            const int nxt = cur ^ 1;
#pragma unroll
            for (int i = 0; i < 4; i++) {
                int idx = tid + i * 256;
                int m = idx >> 4, k = idx & 15;
                As[nxt][k * SPAD + m] = ra[i];
            }
            if (TB) {
#pragma unroll
                for (int i = 0; i < 4; i++) {
                    int idx = tid + i * 256;
                    int j = idx >> 4, k = idx & 15;
                    Bs[nxt][k * SPAD + j] = rb[i];
                }
            } else {
#pragma unroll
                for (int i = 0; i < 4; i++) {
                    int idx = tid + i * 256;
                    int j = idx & 63, k = idx >> 6;
                    Bs[nxt][k * SPAD + j] = rb[i];
                }
            }
            __syncthreads();
        }
    }
}

template<int TB, int EPI>
__global__ void __launch_bounds__(256) gemm_kernel(
    int M, int N, int K,
    const float* __restrict__ A, int lda,
    const float* __restrict__ B, int ldb,
    const float* __restrict__ Dm, int ldd,
    float* __restrict__ C, int ldc)
{
    __shared__ float As[2][BK * SPAD], Bs[2][BK * SPAD];
    const int m0 = blockIdx.y * BM, n0 = blockIdx.x * BN;
    const int tid = threadIdx.x, tx = tid & 15, ty = tid >> 4;
    float acc[4][4];
    gemm_acc64<TB>(M, N, K, A, lda, B, ldb, As, Bs, acc, m0, n0, tid, tx, ty);

#pragma unroll
    for (int i = 0; i < 4; i++) {
        int gm = m0 + ty * 4 + i;
        if (gm >= M) continue;
#pragma unroll
        for (int j = 0; j < 4; j++) {
            int gn = n0 + tx * 4 + j;
            if (gn >= N) continue;
            float v = acc[i][j];
            if (Dm) v += (ldd == 0) ? Dm[gn] : Dm[(size_t)gm * ldd + gn];
            if (EPI == 1) v = tanhf(v);
            if (EPI == 2) v = (v > 0.0f) ? v : expm1f(v);
            C[(size_t)gm * ldc + gn] = v;
        }
    }
}

// ---------------------------------------------------------------------------
// 128x128x8 fp32 GEMM, 8x8 per thread, double-buffered
// ---------------------------------------------------------------------------
#define XBM 128
#define XBN 128
#define XBK 8
#define XPAD 132

template<int TB, int EPI>
__global__ void __launch_bounds__(256) gemm128_kernel(
    int M, int N, int K,
    const float* __restrict__ A, int lda,
    const float* __restrict__ B, int ldb,
    const float* __restrict__ Dm, int ldd,
    float* __restrict__ C, int ldc)
{
    __shared__ float As[2][XBK * XPAD], Bs[2][XBK * XPAD];
    const int m0 = blockIdx.y * XBM, n0 = blockIdx.x * XBN;
    const int tid = threadIdx.x, tx = tid & 15, ty = tid >> 4;

    float acc[8][8];
#pragma unroll
    for (int i = 0; i < 8; i++)
#pragma unroll
        for (int j = 0; j < 8; j++) acc[i][j] = 0.0f;

    const int nt = (K + XBK - 1) / XBK;

    // prologue: tile 0
#pragma unroll
    for (int l = 0; l < 4; l++) {
        int idx = tid + l * 256;
        int m = idx >> 3, k = idx & 7;
        int gm = m0 + m, gk = k;
        As[0][k * XPAD + m] = (gm < M && gk < K) ? __ldg(&A[(size_t)gm * lda + gk]) : 0.0f;
    }
    if (TB) {
#pragma unroll
        for (int l = 0; l < 4; l++) {
            int idx = tid + l * 256;
            int j = idx >> 3, k = idx & 7;
            int gj = n0 + j, gk = k;
            Bs[0][k * XPAD + j] = (gj < N && gk < K) ? __ldg(&B[(size_t)gj * ldb + gk]) : 0.0f;
        }
    } else {
#pragma unroll
        for (int l = 0; l < 4; l++) {
            int idx = tid + l * 256;
            int k = idx >> 7, j = idx & 127;
            int gj = n0 + j, gk = k;
            Bs[0][k * XPAD + j] = (gj < N && gk < K) ? __ldg(&B[(size_t)gk * ldb + gj]) : 0.0f;
        }
    }
    __syncthreads();

    float ra[4], rb[4];
    for (int t = 0; t < nt; t++) {
        const int cur = t & 1;
        const bool more = (t + 1 < nt);
        if (more) {
            int k0 = (t + 1) * XBK;
#pragma unroll
            for (int l = 0; l < 4; l++) {
                int idx = tid + l * 256;
                int m = idx >> 3, k = idx & 7;
                int gm = m0 + m, gk = k0 + k;
                ra[l] = (gm < M && gk < K) ? __ldg(&A[(size_t)gm * lda + gk]) : 0.0f;
            }
            if (TB) {
#pragma unroll
                for (int l = 0; l < 4; l++) {
                    int idx = tid + l * 256;
                    int j = idx >> 3, k = idx & 7;
                    int gj = n0 + j, gk = k0 + k;
                    rb[l] = (gj < N && gk < K) ? __ldg(&B[(size_t)gj * ldb + gk]) : 0.0f;
                }
            } else {
#pragma unroll
                for (int l = 0; l < 4; l++) {
                    int idx = tid + l * 256;
                    int k = idx >> 7, j = idx & 127;
                    int gj = n0 + j, gk = k0 + k;
                    rb[l] = (gj < N && gk < K) ? __ldg(&B[(size_t)gk * ldb + gj]) : 0.0f;
                }
            }
        }
#pragma unroll
        for (int kk = 0; kk < XBK; kk++) {
            float a[8], b[8];
            float4 a0 = *reinterpret_cast<const float4*>(&As[cur][kk * XPAD + ty * 8]);
            float4 a1 = *reinterpret_cast<const float4*>(&As[cur][kk * XPAD + ty * 8 + 4]);
            float4 b0 = *reinterpret_cast<const float4*>(&Bs[cur][kk * XPAD + tx * 8]);
            float4 b1 = *reinterpret_cast<const float4*>(&Bs[cur][kk * XPAD + tx * 8 + 4]);
            a[0]=a0.x; a[1]=a0.y; a[2]=a0.z; a[3]=a0.w;
            a[4]=a1.x; a[5]=a1.y; a[6]=a1.z; a[7]=a1.w;
            b[0]=b0.x; b[1]=b0.y; b[2]=b0.z; b[3]=b0.w;
            b[4]=b1.x; b[5]=b1.y; b[6]=b1.z; b[7]=b1.w;
#pragma unroll
            for (int i = 0; i < 8; i++)
#pragma unroll
                for (int j = 0; j < 8; j++)
                    acc[i][j] += a[i] * b[j];
        }
        if (more) {
            const int nxt = cur ^ 1;
#pragma unroll
            for (int l = 0; l < 4; l++) {
                int idx = tid + l * 256;
                int m = idx >> 3, k = idx & 7;
                As[nxt][k * XPAD + m] = ra[l];
            }
            if (TB) {
#pragma unroll
                for (int l = 0; l < 4; l++) {
                    int idx = tid + l * 256;
                    int j = idx >> 3, k = idx & 7;
                    Bs[nxt][k * XPAD + j] = rb[l];
                }
            } else {
#pragma unroll
                for (int l = 0; l < 4; l++) {
                    int idx = tid + l * 256;
                    int k = idx >> 7, j = idx & 127;
                    Bs[nxt][k * XPAD + j] = rb[l];
                }
            }
            __syncthreads();
        }
    }

#pragma unroll
    for (int i = 0; i < 8; i++) {
        int gm = m0 + ty * 8 + i;
        if (gm >= M) continue;
#pragma unroll
        for (int j = 0; j < 8; j++) {
            int gn = n0 + tx * 8 + j;
            if (gn >= N) continue;
            float v = acc[i][j];
            if (Dm) v += (ldd == 0) ? Dm[gn] : Dm[(size_t)gm * ldd + gn];
            if (EPI == 1) v = tanhf(v);
            if (EPI == 2) v = (v > 0.0f) ? v : expm1f(v);
            C[(size_t)gm * ldc + gn] = v;
        }
    }
}

// ---------------------------------------------------------------------------
// Fused LSTM step (R3 config: 64x64 tiles, 228 blocks), pipelined core.
// Weights/P gate-interleaved (row r = j*4 + gate).
// ---------------------------------------------------------------------------
__global__ void __launch_bounds__(256) lstm_fused_kernel(
    const float* __restrict__ hs_in, float* __restrict__ hs_out,
    int hcol_f, int hcol_b,
    const float* __restrict__ Whh_rf, const float* __restrict__ Whh_rb,
    const float* __restrict__ Pf, const float* __restrict__ Pb,
    float* __restrict__ cbuf,            // [2][N][H]
    float* __restrict__ outbuf, int t)   // o0 or null
{
    __shared__ float As[2][BK * SPAD], Bs[2][BK * SPAD];
    const int z = blockIdx.z;
    const int hcol = z ? hcol_b : hcol_f;
    const float* A = hs_in + hcol;
    const float* Bw = z ? Whh_rb : Whh_rf;
    const float* P  = z ? Pb : Pf;

    const int m0 = blockIdx.y * BM, n0 = blockIdx.x * BN;
    const int tid = threadIdx.x, tx = tid & 15, ty = tid >> 4;
    float acc[4][4];
    gemm_acc64<1>(N_NODES, G4, H_HID, A, G4, Bw, H_HID, As, Bs, acc, m0, n0, tid, tx, ty);

    const int r0 = n0 + tx * 4;
    if (r0 + 3 >= G4) return;
    const int j = r0 >> 2;
    float* c = cbuf + (size_t)z * N_NODES * H_HID;

#pragma unroll
    for (int i = 0; i < 4; i++) {
        int gm = m0 + ty * 4 + i;
        if (gm >= N_NODES) continue;
        float4 p = *reinterpret_cast<const float4*>(P + (size_t)gm * G4 + r0);
        float gi = acc[i][0] + p.x;
        float gf = acc[i][1] + p.y;
        float gg = acc[i][2] + p.z;
        float go = acc[i][3] + p.w;
        float cp = c[(size_t)gm * H_HID + j];
        float cn = sigm_(gf) * cp + sigm_(gi) * tanhf(gg);
        float h  = sigm_(go) * tanhf(cn);
        c[(size_t)gm * H_HID + j] = cn;
        hs_out[(size_t)gm * G4 + hcol + j] = h;
        if (outbuf) {
            int tt = z ? (L_SEQ - 1 - t) : t;
            outbuf[(size_t)tt * N_NODES * 600 + (size_t)gm * 600 + z * H_HID + j] = h;
        }
    }
}

// Reorder LSTM weight rows: out[j*4+g][k] = in[g*H + j][k]
__global__ void reorder_rows_kernel(const float* __restrict__ in,
                                    float* __restrict__ out, int K)
{
    size_t idx = (size_t)blockIdx.x * blockDim.x + threadIdx.x;
    if (idx >= (size_t)G4 * K) return;
    int r = (int)(idx / K), k = (int)(idx % K);
    int j = r >> 2, g = r & 3;
    out[(size_t)r * K + k] = in[(size_t)(g * H_HID + j) * K + k];
}

__global__ void memzero_kernel(float* p, int n)
{
    int i = blockIdx.x * blockDim.x + threadIdx.x;
    if (i < n) p[i] = 0.0f;
}

__global__ void embed_kernel(const int* __restrict__ tok,
                             const float* __restrict__ emb,
                             float* __restrict__ x)
{
    size_t idx = (size_t)blockIdx.x * blockDim.x + threadIdx.x;
    const size_t total = (size_t)L_SEQ * N_NODES * D_EMB;
    if (idx >= total) return;
    int d = (int)(idx % D_EMB);
    size_t r = idx / D_EMB;
    int n = (int)(r % N_NODES);
    int t = (int)(r / N_NODES);
    int tv = tok[n * L_SEQ + t];
    x[idx] = emb[(size_t)tv * D_EMB + d];
}

// out[row] = epi( dot(A[row,:K], w) )
template<int EPI>
__global__ void rows_dot_kernel(const float* __restrict__ A, int lda,
                                const float* __restrict__ w, int K,
                                float* __restrict__ out)
{
    __shared__ float red[8];
    const float* a = A + (size_t)blockIdx.x * lda;
    float s = 0.0f;
    for (int k = threadIdx.x; k < K; k += blockDim.x) s += a[k] * w[k];
#pragma unroll
    for (int o = 16; o > 0; o >>= 1) s += __shfl_down_sync(0xffffffffu, s, o);
    if ((threadIdx.x & 31) == 0) red[threadIdx.x >> 5] = s;
    __syncthreads();
    if (threadIdx.x == 0) {
        float t = 0.0f;
        int nw = blockDim.x >> 5;
        for (int i = 0; i < nw; i++) t += red[i];
        if (EPI == 1) t = tanhf(t);
        out[blockIdx.x] = t;
    }
}

// out[j] = scale * sum_n (w ? w[n] : 1) * A[n*lda + j]
__global__ void colsum_kernel(const float* __restrict__ A, int lda, int rows,
                              const float* __restrict__ w, float scale,
                              float* __restrict__ out, int ncols)
{
    int j = blockIdx.x * blockDim.x + threadIdx.x;
    if (j >= ncols) return;
    float s = 0.0f;
#pragma unroll 4
    for (int n = 0; n < rows; n++) {
        float v = A[(size_t)n * lda + j];
        s += w ? w[n] * v : v;
    }
    out[j] = s * scale;
}

// cat[n] = [ h[n] , gate(h)[n] ]
__global__ void gate_cat_kernel(const float* __restrict__ h,
                                const float* __restrict__ u,
                                const float* __restrict__ vsc,
                                const float* __restrict__ s,
                                float* __restrict__ cat)
{
    int idx = blockIdx.x * blockDim.x + threadIdx.x;
    if (idx >= N_NODES * G4) return;
    int n = idx / G4, j = idx % G4;
    float hv = h[(size_t)n * G4 + j];
    float h0 = h[j];
    float val;
    if (n == 0) {
        val = h0;
    } else {
        float g = sigm_(u[n] + vsc[0]);
        val = g * s[j] + (1.0f - g) * ((float)(N_NODES - 1) * h0);
    }
    cat[(size_t)n * 2400 + j] = hv;
    cat[(size_t)n * 2400 + 1200 + j] = val;
}

__global__ void att_softmax_kernel(const float* __restrict__ e1,
                                   const float* __restrict__ e2,
                                   const int* __restrict__ adj,
                                   float* __restrict__ att)
{
    __shared__ float warpred[4];
    __shared__ float s_max, s_sum;
    int i = blockIdx.x;
    float ei = e1[i];

    float mx = -3.4e38f;
    for (int j = threadIdx.x; j < N_NODES; j += blockDim.x) {
        float v = ei + e2[j];
        v = (v > 0.0f) ? v : 0.01f * v;
        if (adj[(size_t)i * N_NODES + j] <= 0) v = -9.0e15f;
        mx = fmaxf(mx, v);
    }
#pragma unroll
    for (int o = 16; o > 0; o >>= 1) mx = fmaxf(mx, __shfl_down_sync(0xffffffffu, mx, o));
    if ((threadIdx.x & 31) == 0) warpred[threadIdx.x >> 5] = mx;
    __syncthreads();
    if (threadIdx.x == 0) {
        float m2 = warpred[0];
        int nw = blockDim.x >> 5;
        for (int k = 1; k < nw; k++) m2 = fmaxf(m2, warpred[k]);
        s_max = m2;
    }
    __syncthreads();
    float smax = s_max;

    float sum = 0.0f;
    for (int j = threadIdx.x; j < N_NODES; j += blockDim.x) {
        float v = ei + e2[j];
        v = (v > 0.0f) ? v : 0.01f * v;
        if (adj[(size_t)i * N_NODES + j] <= 0) v = -9.0e15f;
        sum += expf(v - smax);
    }
#pragma unroll
    for (int o = 16; o > 0; o >>= 1) sum += __shfl_down_sync(0xffffffffu, sum, o);
    if ((threadIdx.x & 31) == 0) warpred[threadIdx.x >> 5] = sum;
    __syncthreads();
    if (threadIdx.x == 0) {
        float t = 0.0f;
        int nw = blockDim.x >> 5;
        for (int k = 0; k < nw; k++) t += warpred[k];
        s_sum = t;
    }
    __syncthreads();
    float inv = 1.0f / s_sum;

    for (int j = threadIdx.x; j < N_NODES; j += blockDim.x) {
        float v = ei + e2[j];
        v = (v > 0.0f) ? v : 0.01f * v;
        if (adj[(size_t)i * N_NODES + j] <= 0) v = -9.0e15f;
        att[(size_t)i * N_NODES + j] = expf(v - smax) * inv;
    }
}

// Z[n] = [hc, hs2[n], hc*hs2[n], hc - hs2[n]],  hc = hs2[0]
__global__ void zassemble_kernel(const float* __restrict__ h2, float* __restrict__ Z)
{
    int idx = blockIdx.x * blockDim.x + threadIdx.x;
    if (idx >= N_NODES * G4) return;
    int n = idx / G4, j = idx % G4;
    float a = h2[j];
    float b = h2[(size_t)n * G4 + j];
    size_t base = (size_t)n * 4800;
    Z[base + j]        = a;
    Z[base + 1200 + j] = b;
    Z[base + 2400 + j] = a * b;
    Z[base + 3600 + j] = a - b;
}

__global__ void final_kernel(const float* __restrict__ ea,
                             const float* __restrict__ Wlin,
                             const float* __restrict__ blin,
                             float* __restrict__ out)
{
    __shared__ float r0[8], r1[8];
    float s0 = 0.0f, s1 = 0.0f;
    for (int j = threadIdx.x; j < 2400; j += blockDim.x) {
        float e = ea[j];
        s0 += e * Wlin[j];
        s1 += e * Wlin[2400 + j];
    }
#pragma unroll
    for (int o = 16; o > 0; o >>= 1) {
        s0 += __shfl_down_sync(0xffffffffu, s0, o);
        s1 += __shfl_down_sync(0xffffffffu, s1, o);
    }
    if ((threadIdx.x & 31) == 0) { r0[threadIdx.x >> 5] = s0; r1[threadIdx.x >> 5] = s1; }
    __syncthreads();
    if (threadIdx.x == 0) {
        float l0 = 0.0f, l1 = 0.0f;
        int nw = blockDim.x >> 5;
        for (int i = 0; i < nw; i++) { l0 += r0[i]; l1 += r1[i]; }
        l0 += blin[0]; l1 += blin[1];
        float m = fmaxf(l0, l1);
        float e0 = expf(l0 - m), e1v = expf(l1 - m);
        float inv = 1.0f / (e0 + e1v);
        out[0] = e0 * inv;
        out[1] = e1v * inv;
    }
}

// ---------------------------------------------------------------------------
// Host orchestration
// ---------------------------------------------------------------------------
static inline dim3 grid64(int M, int N)  { return dim3((N + BN - 1) / BN, (M + BM - 1) / BM); }
static inline dim3 grid128(int M, int N) { return dim3((N + XBN - 1) / XBN, (M + XBM - 1) / XBM); }

static void run_gate_gat(const float* h_in, float* h_out,
                         const float* gate_W, const float* gate_U,
                         const float* W_gat, const float* a_gat,
                         const int* adj, float* pool)
{
    float* U   = pool + OFF_U;
    float* Vb  = pool + OFF_V;
    float* S   = pool + OFF_S;
    float* CAT = pool + OFF_CAT;
    float* WHp = pool + OFF_WH;
    float* E1  = pool + OFF_E1;
    float* E2  = pool + OFF_E2;
    float* ATT = pool + OFF_ATT;

    rows_dot_kernel<0><<<N_NODES, 256>>>(h_in, G4, gate_W, G4, U);
    rows_dot_kernel<0><<<1, 256>>>(h_in, G4, gate_U, G4, Vb);
    colsum_kernel<<<(G4 + 255) / 256, 256>>>(h_in + G4, G4, N_NODES - 1, nullptr, 1.0f, S, G4);
    gate_cat_kernel<<<(N_NODES * G4 + 255) / 256, 256>>>(h_in, U, Vb, S, CAT);

    gemm_kernel<0, 0><<<grid64(N_NODES, G4), 256>>>(
        N_NODES, G4, 2400, CAT, 2400, W_gat, G4, nullptr, 0, WHp, G4);
    rows_dot_kernel<0><<<N_NODES, 256>>>(WHp, G4, a_gat, G4, E1);
    rows_dot_kernel<0><<<N_NODES, 256>>>(WHp, G4, a_gat + G4, G4, E2);
    att_softmax_kernel<<<N_NODES, 128>>>(E1, E2, adj, ATT);
    gemm_kernel<0, 2><<<grid64(N_NODES, G4), 256>>>(
        N_NODES, G4, N_NODES, ATT, N_NODES, WHp, G4, nullptr, 0, h_out, G4);
}

extern "C" void kernel_launch(void* const* d_in, const int* in_sizes, int n_in,
                              void* d_out, int out_size)
{
    (void)in_sizes; (void)n_in; (void)out_size;

    float* pool = nullptr;
    cudaGetSymbolAddress((void**)&pool, g_pool);

    const int*   tokens  = (const int*)d_in[0];
    const int*   adj     = (const int*)d_in[1];
    const float* emb     = (const float*)d_in[2];
    const float* Wih_l0f = (const float*)d_in[3];
    const float* Whh_l0f = (const float*)d_in[4];
    const float* b_l0f   = (const float*)d_in[5];
    const float* Wih_l0b = (const float*)d_in[6];
    const float* Whh_l0b = (const float*)d_in[7];
    const float* b_l0b   = (const float*)d_in[8];
    const float* Wih_l1f = (const float*)d_in[9];
    const float* Whh_l1f = (const float*)d_in[10];
    const float* b_l1f   = (const float*)d_in[11];
    const float* Wih_l1b = (const float*)d_in[12];
    const float* Whh_l1b = (const float*)d_in[13];
    const float* b_l1b   = (const float*)d_in[14];
    const float* W_gat   = (const float*)d_in[15];
    const float* a_gat   = (const float*)d_in[16];
    const float* gate_W  = (const float*)d_in[17];
    const float* gate_U  = (const float*)d_in[18];
    const float* FC1     = (const float*)d_in[19];
    const float* FC2     = (const float*)d_in[20];
    const float* Wlin    = (const float*)d_in[21];
    const float* blin    = (const float*)d_in[22];
    float* out = (float*)d_out;

    float* X    = pool + OFF_X;
    float* PF   = pool + OFF_P0F;
    float* PB   = pool + OFF_P0B;
    float* O0   = pool + OFF_O0;
    float* HSA  = pool + OFF_HSA;
    float* HSB  = pool + OFF_HSB;
    float* C4   = pool + OFF_C4;
    float* HS1  = pool + OFF_HS1;
    float* HS2  = pool + OFF_HS2;
    float* Z    = pool + OFF_Z;
    float* HC3  = pool + OFF_HC3;
    float* WHHR  = pool + OFF_WHHR;   // 4 x [1200][300]: l0f,l0b,l1f,l1b
    float* WIHR0 = pool + OFF_WIHR0;  // 2 x [1200][300]
    float* WIHR1 = pool + OFF_WIHR1;  // 2 x [1200][600]
    float* BR    = pool + OFF_BR;     // 4 x [1200]
    float* BATT = pool + OFF_BATT;
    float* EA   = pool + OFF_EA;

    const int LN = L_SEQ * N_NODES;   // 17300
    const size_t W3 = (size_t)G4 * 300, W6 = (size_t)G4 * 600;

    const int thr = 256;
    const int g3 = (int)((W3 + thr - 1) / thr), g6 = (int)((W6 + thr - 1) / thr);
    const int g1 = (G4 + thr - 1) / thr;

    // ---- weight reorders (gate-interleaved rows) ----
    reorder_rows_kernel<<<g3, thr>>>(Wih_l0f, WIHR0 + 0 * W3, 300);
    reorder_rows_kernel<<<g3, thr>>>(Wih_l0b, WIHR0 + 1 * W3, 300);
    reorder_rows_kernel<<<g3, thr>>>(Whh_l0f, WHHR + 0 * W3, 300);
    reorder_rows_kernel<<<g3, thr>>>(Whh_l0b, WHHR + 1 * W3, 300);
    reorder_rows_kernel<<<g3, thr>>>(Whh_l1f, WHHR + 2 * W3, 300);
    reorder_rows_kernel<<<g3, thr>>>(Whh_l1b, WHHR + 3 * W3, 300);
    reorder_rows_kernel<<<g6, thr>>>(Wih_l1f, WIHR1 + 0 * W6, 600);
    reorder_rows_kernel<<<g6, thr>>>(Wih_l1b, WIHR1 + 1 * W6, 600);
    reorder_rows_kernel<<<g1, thr>>>(b_l0f, BR + 0 * G4, 1);
    reorder_rows_kernel<<<g1, thr>>>(b_l0b, BR + 1 * G4, 1);
    reorder_rows_kernel<<<g1, thr>>>(b_l1f, BR + 2 * G4, 1);
    reorder_rows_kernel<<<g1, thr>>>(b_l1b, BR + 3 * G4, 1);

    // ---- init states ----
    memzero_kernel<<<((int)SZ_NG4 + 255) / 256, 256>>>(HSA, (int)SZ_NG4);
    memzero_kernel<<<(4 * (int)SZ_NH + 255) / 256, 256>>>(C4, 4 * (int)SZ_NH);

    // ---- embedding ----
    embed_kernel<<<(int)((SZ_X + 255) / 256), 256>>>(tokens, emb, X);

    // ---- layer-0 input projections ----
    gemm128_kernel<1, 0><<<grid128(LN, G4), 256>>>(
        LN, G4, D_EMB, X, D_EMB, WIHR0 + 0 * W3, 300, BR + 0 * G4, 0, PF, G4);
    gemm128_kernel<1, 0><<<grid128(LN, G4), 256>>>(
        LN, G4, D_EMB, X, D_EMB, WIHR0 + 1 * W3, 300, BR + 1 * G4, 0, PB, G4);

    // ---- layer-0 scan (fused GEMM+cell, 64x64 tiles, 228 blocks) ----
    {
        dim3 grid = grid64(N_NODES, G4); grid.z = 2;
        const float* hin = HSA; float* hout = HSB;
        for (int t = 0; t < L_SEQ; t++) {
            lstm_fused_kernel<<<grid, 256>>>(
                hin, hout, 0, 300,
                WHHR + 0 * W3, WHHR + 1 * W3,
                PF + (size_t)t * N_NODES * G4,
                PB + (size_t)(L_SEQ - 1 - t) * N_NODES * G4,
                C4, O0, t);
            const float* tmp = hin; hin = hout; hout = (float*)tmp;
        }
    }

    // ---- layer-1 input projections ----
    gemm128_kernel<1, 0><<<grid128(LN, G4), 256>>>(
        LN, G4, 600, O0, 600, WIHR1 + 0 * W6, 600, BR + 2 * G4, 0, PF, G4);
    gemm128_kernel<1, 0><<<grid128(LN, G4), 256>>>(
        LN, G4, 600, O0, 600, WIHR1 + 1 * W6, 600, BR + 3 * G4, 0, PB, G4);

    // ---- layer-1 scan ----
    {
        dim3 grid = grid64(N_NODES, G4); grid.z = 2;
        const float* hin = HSA; float* hout = HSB;
        for (int t = 0; t < L_SEQ; t++) {
            lstm_fused_kernel<<<grid, 256>>>(
                hin, hout, 600, 900,
                WHHR + 2 * W3, WHHR + 3 * W3,
                PF + (size_t)t * N_NODES * G4,
                PB + (size_t)(L_SEQ - 1 - t) * N_NODES * G4,
                C4 + 2 * SZ_NH, nullptr, t);
            const float* tmp = hin; hin = hout; hout = (float*)tmp;
        }
    }
    // L_SEQ=50 (even): final h for both layers lands in HSA.

    // ---- two gate+GAT stages ----
    run_gate_gat(HSA, HS1, gate_W, gate_U, W_gat, a_gat, adj, pool);
    run_gate_gat(HS1, HS2, gate_W, gate_U, W_gat, a_gat, adj, pool);

    // ---- final head ----
    zassemble_kernel<<<(N_NODES * G4 + 255) / 256, 256>>>(HS2, Z);
    gemm128_kernel<0, 1><<<grid128(N_NODES, 9600), 256>>>(
        N_NODES, 9600, 4800, Z, 4800, FC1, 9600, nullptr, 0, HC3, 9600);
    rows_dot_kernel<1><<<N_NODES, 256>>>(HC3, 9600, FC2, 9600, BATT);
    colsum_kernel<<<(G4 + 255) / 256, 256>>>(HS2, G4, N_NODES, nullptr,
                                             1.0f / (float)N_NODES, EA, G4);
    colsum_kernel<<<(G4 + 255) / 256, 256>>>(HS2, G4, N_NODES, BATT, 1.0f, EA + G4, G4);
    final_kernel<<<1, 256>>>(EA, Wlin, blin, out);
}

// round 11
// speedup vs baseline: 1.7518x; 1.0573x over previous
#include <cuda_runtime.h>
#include <math.h>

#define N_NODES 346
#define L_SEQ   50
#define D_EMB   300
#define H_HID   300
#define G4      1200   // 4*H

// ---------------------------------------------------------------------------
// Scratch pool (static device allocation — no cudaMalloc anywhere)
// ---------------------------------------------------------------------------
constexpr size_t A256(size_t x) { return (x + 255) & ~(size_t)255; }

constexpr size_t SZ_X   = (size_t)L_SEQ * N_NODES * D_EMB;
constexpr size_t SZ_P   = (size_t)L_SEQ * N_NODES * G4;
constexpr size_t SZ_O0  = (size_t)L_SEQ * N_NODES * 600;
constexpr size_t SZ_NG4 = (size_t)N_NODES * G4;
constexpr size_t SZ_NH  = (size_t)N_NODES * H_HID;

constexpr size_t OFF_X    = 0;
constexpr size_t OFF_P0F  = A256(OFF_X   + SZ_X);
constexpr size_t OFF_P0B  = A256(OFF_P0F + SZ_P);
constexpr size_t OFF_O0   = A256(OFF_P0B + SZ_P);
constexpr size_t OFF_HSA  = A256(OFF_O0  + SZ_O0);
constexpr size_t OFF_HSB  = A256(OFF_HSA + SZ_NG4);
constexpr size_t OFF_CAT  = A256(OFF_HSB + SZ_NG4);
constexpr size_t OFF_WH   = A256(OFF_CAT + (size_t)N_NODES * 2400);
constexpr size_t OFF_ATT  = A256(OFF_WH  + SZ_NG4);
constexpr size_t OFF_HS1  = A256(OFF_ATT + (size_t)N_NODES * N_NODES);
constexpr size_t OFF_HS2  = A256(OFF_HS1 + SZ_NG4);
constexpr size_t OFF_Z    = A256(OFF_HS2 + SZ_NG4);
constexpr size_t OFF_HC3  = A256(OFF_Z   + (size_t)N_NODES * 4800);
constexpr size_t OFF_WHHR  = A256(OFF_HC3  + (size_t)N_NODES * 9600);
constexpr size_t OFF_WIHR0 = A256(OFF_WHHR + 4 * (size_t)G4 * H_HID);
constexpr size_t OFF_WIHR1 = A256(OFF_WIHR0 + 2 * (size_t)G4 * 300);
constexpr size_t OFF_BR    = A256(OFF_WIHR1 + 2 * (size_t)G4 * 600);
constexpr size_t OFF_BAR  = A256(OFF_BR  + 4 * (size_t)G4);
constexpr size_t OFF_U    = A256(OFF_BAR + 64);
constexpr size_t OFF_V    = A256(OFF_U   + 512);
constexpr size_t OFF_S    = A256(OFF_V   + 32);
constexpr size_t OFF_E1   = A256(OFF_S   + 1280);
constexpr size_t OFF_E2   = A256(OFF_E1  + 512);
constexpr size_t OFF_BATT = A256(OFF_E2  + 512);
constexpr size_t OFF_EA   = A256(OFF_BATT + 512);
constexpr size_t POOL_SZ  = A256(OFF_EA + 2560);

__device__ float g_pool[POOL_SZ];

__device__ __forceinline__ float sigm_(float x) { return 1.0f / (1.0f + expf(-x)); }

// ---------------------------------------------------------------------------
// 64x64x16 fp32 GEMM core, double-buffered (R10 winner) — GAT GEMMs
// ---------------------------------------------------------------------------
#define BM 64
#define BN 64
#define BK 16
#define SPAD 68

template<int TB>
__device__ __forceinline__ void gemm_acc64(
    int M, int N, int K,
    const float* __restrict__ A, int lda,
    const float* __restrict__ B, int ldb,
    float (*As)[BK * SPAD], float (*Bs)[BK * SPAD], float acc[4][4],
    int m0, int n0, int tid, int tx, int ty)
{
#pragma unroll
    for (int i = 0; i < 4; i++)
#pragma unroll
        for (int j = 0; j < 4; j++) acc[i][j] = 0.0f;

    const int nt = (K + BK - 1) / BK;

#pragma unroll
    for (int i = 0; i < 4; i++) {
        int idx = tid + i * 256;
        int m = idx >> 4, k = idx & 15;
        int gm = m0 + m, gk = k;
        As[0][k * SPAD + m] = (gm < M && gk < K) ? __ldg(&A[(size_t)gm * lda + gk]) : 0.0f;
    }
    if (TB) {
#pragma unroll
        for (int i = 0; i < 4; i++) {
            int idx = tid + i * 256;
            int j = idx >> 4, k = idx & 15;
            int gj = n0 + j, gk = k;
            Bs[0][k * SPAD + j] = (gj < N && gk < K) ? __ldg(&B[(size_t)gj * ldb + gk]) : 0.0f;
        }
    } else {
#pragma unroll
        for (int i = 0; i < 4; i++) {
            int idx = tid + i * 256;
            int j = idx & 63, k = idx >> 6;
            int gj = n0 + j, gk = k;
            Bs[0][k * SPAD + j] = (gj < N && gk < K) ? __ldg(&B[(size_t)gk * ldb + gj]) : 0.0f;
        }
    }
    __syncthreads();

    float ra[4], rb[4];
    for (int t = 0; t < nt; t++) {
        const int cur = t & 1;
        const bool more = (t + 1 < nt);
        if (more) {
            int k0 = (t + 1) * BK;
#pragma unroll
            for (int i = 0; i < 4; i++) {
                int idx = tid + i * 256;
                int m = idx >> 4, k = idx & 15;
                int gm = m0 + m, gk = k0 + k;
                ra[i] = (gm < M && gk < K) ? __ldg(&A[(size_t)gm * lda + gk]) : 0.0f;
            }
            if (TB) {
#pragma unroll
                for (int i = 0; i < 4; i++) {
                    int idx = tid + i * 256;
                    int j = idx >> 4, k = idx & 15;
                    int gj = n0 + j, gk = k0 + k;
                    rb[i] = (gj < N && gk < K) ? __ldg(&B[(size_t)gj * ldb + gk]) : 0.0f;
                }
            } else {
#pragma unroll
                for (int i = 0; i < 4; i++) {
                    int idx = tid + i * 256;
                    int j = idx & 63, k = idx >> 6;
                    int gj = n0 + j, gk = k0 + k;
                    rb[i] = (gj < N && gk < K) ? __ldg(&B[(size_t)gk * ldb + gj]) : 0.0f;
                }
            }
        }
#pragma unroll
        for (int kk = 0; kk < BK; kk++) {
            float4 av = *reinterpret_cast<const float4*>(&As[cur][kk * SPAD + ty * 4]);
            float4 bv = *reinterpret_cast<const float4*>(&Bs[cur][kk * SPAD + tx * 4]);
            float a[4] = {av.x, av.y, av.z, av.w};
            float b[4] = {bv.x, bv.y, bv.z, bv.w};
#pragma unroll
            for (int i = 0; i < 4; i++)
#pragma unroll
                for (int j = 0; j < 4; j++)
                    acc[i][j] += a[i] * b[j];
        }
        if (more) {
            const int nxt = cur ^ 1;
#pragma unroll
            for (int i = 0; i < 4; i++) {
                int idx = tid + i * 256;
                int m = idx >> 4, k = idx & 15;
                As[nxt][k * SPAD + m] = ra[i];
            }
            if (TB) {
#pragma unroll
                for (int i = 0; i < 4; i++) {
                    int idx = tid + i * 256;
                    int j = idx >> 4, k = idx & 15;
                    Bs[nxt][k * SPAD + j] = rb[i];
                }
            } else {
#pragma unroll
                for (int i = 0; i < 4; i++) {
                    int idx = tid + i * 256;
                    int j = idx & 63, k = idx >> 6;
                    Bs[nxt][k * SPAD + j] = rb[i];
                }
            }
            __syncthreads();
        }
    }
}

template<int TB, int EPI>
__global__ void __launch_bounds__(256) gemm_kernel(
    int M, int N, int K,
    const float* __restrict__ A, int lda,
    const float* __restrict__ B, int ldb,
    const float* __restrict__ Dm, int ldd,
    float* __restrict__ C, int ldc)
{
    __shared__ float As[2][BK * SPAD], Bs[2][BK * SPAD];
    const int m0 = blockIdx.y * BM, n0 = blockIdx.x * BN;
    const int tid = threadIdx.x, tx = tid & 15, ty = tid >> 4;
    float acc[4][4];
    gemm_acc64<TB>(M, N, K, A, lda, B, ldb, As, Bs, acc, m0, n0, tid, tx, ty);

#pragma unroll
    for (int i = 0; i < 4; i++) {
        int gm = m0 + ty * 4 + i;
        if (gm >= M) continue;
#pragma unroll
        for (int j = 0; j < 4; j++) {
            int gn = n0 + tx * 4 + j;
            if (gn >= N) continue;
            float v = acc[i][j];
            if (Dm) v += (ldd == 0) ? Dm[gn] : Dm[(size_t)gm * ldd + gn];
            if (EPI == 1) v = tanhf(v);
            if (EPI == 2) v = (v > 0.0f) ? v : expm1f(v);
            C[(size_t)gm * ldc + gn] = v;
        }
    }
}

// ---------------------------------------------------------------------------
// 128x128x8 fp32 GEMM, 8x8 per thread, double-buffered (R10 winner)
// ---------------------------------------------------------------------------
#define XBM 128
#define XBN 128
#define XBK 8
#define XPAD 132

template<int TB, int EPI>
__global__ void __launch_bounds__(256) gemm128_kernel(
    int M, int N, int K,
    const float* __restrict__ A, int lda,
    const float* __restrict__ B, int ldb,
    const float* __restrict__ Dm, int ldd,
    float* __restrict__ C, int ldc)
{
    __shared__ float As[2][XBK * XPAD], Bs[2][XBK * XPAD];
    const int m0 = blockIdx.y * XBM, n0 = blockIdx.x * XBN;
    const int tid = threadIdx.x, tx = tid & 15, ty = tid >> 4;

    float acc[8][8];
#pragma unroll
    for (int i = 0; i < 8; i++)
#pragma unroll
        for (int j = 0; j < 8; j++) acc[i][j] = 0.0f;

    const int nt = (K + XBK - 1) / XBK;

#pragma unroll
    for (int l = 0; l < 4; l++) {
        int idx = tid + l * 256;
        int m = idx >> 3, k = idx & 7;
        int gm = m0 + m, gk = k;
        As[0][k * XPAD + m] = (gm < M && gk < K) ? __ldg(&A[(size_t)gm * lda + gk]) : 0.0f;
    }
    if (TB) {
#pragma unroll
        for (int l = 0; l < 4; l++) {
            int idx = tid + l * 256;
            int j = idx >> 3, k = idx & 7;
            int gj = n0 + j, gk = k;
            Bs[0][k * XPAD + j] = (gj < N && gk < K) ? __ldg(&B[(size_t)gj * ldb + gk]) : 0.0f;
        }
    } else {
#pragma unroll
        for (int l = 0; l < 4; l++) {
            int idx = tid + l * 256;
            int k = idx >> 7, j = idx & 127;
            int gj = n0 + j, gk = k;
            Bs[0][k * XPAD + j] = (gj < N && gk < K) ? __ldg(&B[(size_t)gk * ldb + gj]) : 0.0f;
        }
    }
    __syncthreads();

    float ra[4], rb[4];
    for (int t = 0; t < nt; t++) {
        const int cur = t & 1;
        const bool more = (t + 1 < nt);
        if (more) {
            int k0 = (t + 1) * XBK;
#pragma unroll
            for (int l = 0; l < 4; l++) {
                int idx = tid + l * 256;
                int m = idx >> 3, k = idx & 7;
                int gm = m0 + m, gk = k0 + k;
                ra[l] = (gm < M && gk < K) ? __ldg(&A[(size_t)gm * lda + gk]) : 0.0f;
            }
            if (TB) {
#pragma unroll
                for (int l = 0; l < 4; l++) {
                    int idx = tid + l * 256;
                    int j = idx >> 3, k = idx & 7;
                    int gj = n0 + j, gk = k0 + k;
                    rb[l] = (gj < N && gk < K) ? __ldg(&B[(size_t)gj * ldb + gk]) : 0.0f;
                }
            } else {
#pragma unroll
                for (int l = 0; l < 4; l++) {
                    int idx = tid + l * 256;
                    int k = idx >> 7, j = idx & 127;
                    int gj = n0 + j, gk = k0 + k;
                    rb[l] = (gj < N && gk < K) ? __ldg(&B[(size_t)gk * ldb + gj]) : 0.0f;
                }
            }
        }
#pragma unroll
        for (int kk = 0; kk < XBK; kk++) {
            float a[8], b[8];
            float4 a0 = *reinterpret_cast<const float4*>(&As[cur][kk * XPAD + ty * 8]);
            float4 a1 = *reinterpret_cast<const float4*>(&As[cur][kk * XPAD + ty * 8 + 4]);
            float4 b0 = *reinterpret_cast<const float4*>(&Bs[cur][kk * XPAD + tx * 8]);
            float4 b1 = *reinterpret_cast<const float4*>(&Bs[cur][kk * XPAD + tx * 8 + 4]);
            a[0]=a0.x; a[1]=a0.y; a[2]=a0.z; a[3]=a0.w;
            a[4]=a1.x; a[5]=a1.y; a[6]=a1.z; a[7]=a1.w;
            b[0]=b0.x; b[1]=b0.y; b[2]=b0.z; b[3]=b0.w;
            b[4]=b1.x; b[5]=b1.y; b[6]=b1.z; b[7]=b1.w;
#pragma unroll
            for (int i = 0; i < 8; i++)
#pragma unroll
                for (int j = 0; j < 8; j++)
                    acc[i][j] += a[i] * b[j];
        }
        if (more) {
            const int nxt = cur ^ 1;
#pragma unroll
            for (int l = 0; l < 4; l++) {
                int idx = tid + l * 256;
                int m = idx >> 3, k = idx & 7;
                As[nxt][k * XPAD + m] = ra[l];
            }
            if (TB) {
#pragma unroll
                for (int l = 0; l < 4; l++) {
                    int idx = tid + l * 256;
                    int j = idx >> 3, k = idx & 7;
                    Bs[nxt][k * XPAD + j] = rb[l];
                }
            } else {
#pragma unroll
                for (int l = 0; l < 4; l++) {
                    int idx = tid + l * 256;
                    int k = idx >> 7, j = idx & 127;
                    Bs[nxt][k * XPAD + j] = rb[l];
                }
            }
            __syncthreads();
        }
    }

#pragma unroll
    for (int i = 0; i < 8; i++) {
        int gm = m0 + ty * 8 + i;
        if (gm >= M) continue;
#pragma unroll
        for (int j = 0; j < 8; j++) {
            int gn = n0 + tx * 8 + j;
            if (gn >= N) continue;
            float v = acc[i][j];
            if (Dm) v += (ldd == 0) ? Dm[gn] : Dm[(size_t)gm * ldd + gn];
            if (EPI == 1) v = tanhf(v);
            if (EPI == 2) v = (v > 0.0f) ? v : expm1f(v);
            C[(size_t)gm * ldc + gn] = v;
        }
    }
}

// ---------------------------------------------------------------------------
// Persistent LSTM scan: one launch runs all L_SEQ steps for one layer.
// Grid (19,6,2)=228 blocks, all co-resident (2 blocks/SM at ~91KB smem).
// Whh tile resident in smem; c in registers; h ping-pongs HSA/HSB; hand-rolled
// grid barrier between steps (atomic epoch counter + volatile spin).
// ---------------------------------------------------------------------------
constexpr int LSTM_GX = (G4 + BN - 1) / BN;        // 19
constexpr int LSTM_GY = (N_NODES + BM - 1) / BM;   // 6
constexpr unsigned LSTM_BLOCKS = LSTM_GX * LSTM_GY * 2;  // 228
constexpr int BS_ROWS = 304;  // 300 rounded to 16 multiple (zero-padded)
constexpr size_t SMEM_SCAN = (size_t)(BS_ROWS * SPAD + 2 * BK * SPAD) * 4;  // 91392 B

__global__ void __launch_bounds__(256) lstm_scan_kernel(
    float* __restrict__ hsA, float* __restrict__ hsB,
    int hcol_f, int hcol_b,
    const float* __restrict__ Whh_rf, const float* __restrict__ Whh_rb,
    const float* __restrict__ Pf, const float* __restrict__ Pb,
    float* __restrict__ outbuf,              // o0 or null
    unsigned* __restrict__ bar)
{
    extern __shared__ float smem[];
    float* Bres = smem;                          // [BS_ROWS][SPAD]
    float* As   = smem + BS_ROWS * SPAD;         // [2][BK*SPAD]

    const int z = blockIdx.z;
    const int hcol = z ? hcol_b : hcol_f;
    const float* Bw = z ? Whh_rb : Whh_rf;
    const float* Pbase = z ? Pb : Pf;

    const int m0 = blockIdx.y * BM, n0 = blockIdx.x * BN;
    const int tid = threadIdx.x, tx = tid & 15, ty = tid >> 4;

    // Load resident B tile: Bres[k*SPAD + j] = Whh_r[n0+j][k], zero-pad k>=300
    for (int idx = tid; idx < BN * BS_ROWS; idx += 256) {
        int j = idx / BS_ROWS, k = idx % BS_ROWS;
        int gj = n0 + j;
        Bres[k * SPAD + j] = (gj < G4 && k < H_HID) ? __ldg(&Bw[(size_t)gj * H_HID + k]) : 0.0f;
    }

    const int r0 = n0 + tx * 4;
    const bool valid_col = (r0 + 3 < G4);
    const int ju = r0 >> 2;
    float c_reg[4] = {0.0f, 0.0f, 0.0f, 0.0f};

    __syncthreads();

    const int nt = (H_HID + BK - 1) / BK;   // 19

    for (int t = 0; t < L_SEQ; t++) {
        const float* hin  = (t & 1) ? hsB : hsA;
        float*       hout = (t & 1) ? hsA : hsB;
        const float* A = hin + hcol;

        // prologue: A tile 0
#pragma unroll
        for (int i = 0; i < 4; i++) {
            int idx = tid + i * 256;
            int m = idx >> 4, k = idx & 15;
            int gm = m0 + m;
            As[k * SPAD + m] = (gm < N_NODES) ? __ldg(&A[(size_t)gm * G4 + k]) : 0.0f;
        }
        __syncthreads();

        float acc[4][4];
#pragma unroll
        for (int i = 0; i < 4; i++)
#pragma unroll
            for (int j = 0; j < 4; j++) acc[i][j] = 0.0f;

        float ra[4];
        for (int kt = 0; kt < nt; kt++) {
            const int cur = kt & 1;
            const bool more = (kt + 1 < nt);
            if (more) {
                int k0 = (kt + 1) * BK;
#pragma unroll
                for (int i = 0; i < 4; i++) {
                    int idx = tid + i * 256;
                    int m = idx >> 4, k = idx & 15;
                    int gm = m0 + m, gk = k0 + k;
                    ra[i] = (gm < N_NODES && gk < H_HID) ? __ldg(&A[(size_t)gm * G4 + gk]) : 0.0f;
                }
            }
#pragma unroll
            for (int kk = 0; kk < BK; kk++) {
                float4 av = *reinterpret_cast<const float4*>(&As[cur * (BK * SPAD) + kk * SPAD + ty * 4]);
                float4 bv = *reinterpret_cast<const float4*>(&Bres[(kt * BK + kk) * SPAD + tx * 4]);
                float a[4] = {av.x, av.y, av.z, av.w};
                float b[4] = {bv.x, bv.y, bv.z, bv.w};
#pragma unroll
                for (int i = 0; i < 4; i++)
#pragma unroll
                    for (int j = 0; j < 4; j++)
                        acc[i][j] += a[i] * b[j];
            }
            if (more) {
                const int nxt = cur ^ 1;
#pragma unroll
                for (int i = 0; i < 4; i++) {
                    int idx = tid + i * 256;
                    int m = idx >> 4, k = idx & 15;
                    As[nxt * (BK * SPAD) + k * SPAD + m] = ra[i];
                }
                __syncthreads();
            }
        }

        // epilogue: cell update (c in registers), h to global
        if (valid_col) {
            const size_t toff = (size_t)(z ? (L_SEQ - 1 - t) : t) * N_NODES * G4;
            const float* P = Pbase + toff;
#pragma unroll
            for (int i = 0; i < 4; i++) {
                int gm = m0 + ty * 4 + i;
                if (gm >= N_NODES) continue;
                float4 p = *reinterpret_cast<const float4*>(P + (size_t)gm * G4 + r0);
                float gi = acc[i][0] + p.x;
                float gf = acc[i][1] + p.y;
                float gg = acc[i][2] + p.z;
                float go = acc[i][3] + p.w;
                float cn = sigm_(gf) * c_reg[i] + sigm_(gi) * tanhf(gg);
                float h  = sigm_(go) * tanhf(cn);
                c_reg[i] = cn;
                hout[(size_t)gm * G4 + hcol + ju] = h;
                if (outbuf) {
                    int tt = z ? (L_SEQ - 1 - t) : t;
                    outbuf[(size_t)tt * N_NODES * 600 + (size_t)gm * 600 + z * H_HID + ju] = h;
                }
            }
        }

        // grid barrier (skip after final step)
        if (t + 1 < L_SEQ) {
            __threadfence();
            __syncthreads();
            if (tid == 0) {
                atomicAdd(bar, 1u);
                const unsigned target = LSTM_BLOCKS * (unsigned)(t + 1);
                const volatile unsigned* vb = bar;
                while (*vb < target) __nanosleep(64);
                __threadfence();
            }
            __syncthreads();
        }
    }
}

// Reorder LSTM weight rows: out[j*4+g][k] = in[g*H + j][k]
__global__ void reorder_rows_kernel(const float* __restrict__ in,
                                    float* __restrict__ out, int K)
{
    size_t idx = (size_t)blockIdx.x * blockDim.x + threadIdx.x;
    if (idx >= (size_t)G4 * K) return;
    int r = (int)(idx / K), k = (int)(idx % K);
    int j = r >> 2, g = r & 3;
    out[(size_t)r * K + k] = in[(size_t)(g * H_HID + j) * K + k];
}

__global__ void memzero_kernel(float* p, int n)
{
    int i = blockIdx.x * blockDim.x + threadIdx.x;
    if (i < n) p[i] = 0.0f;
}

__global__ void embed_kernel(const int* __restrict__ tok,
                             const float* __restrict__ emb,
                             float* __restrict__ x)
{
    size_t idx = (size_t)blockIdx.x * blockDim.x + threadIdx.x;
    const size_t total = (size_t)L_SEQ * N_NODES * D_EMB;
    if (idx >= total) return;
    int d = (int)(idx % D_EMB);
    size_t r = idx / D_EMB;
    int n = (int)(r % N_NODES);
    int t = (int)(r / N_NODES);
    int tv = tok[n * L_SEQ + t];
    x[idx] = emb[(size_t)tv * D_EMB + d];
}

// out[row] = epi( dot(A[row,:K], w) )
template<int EPI>
__global__ void rows_dot_kernel(const float* __restrict__ A, int lda,
                                const float* __restrict__ w, int K,
                                float* __restrict__ out)
{
    __shared__ float red[8];
    const float* a = A + (size_t)blockIdx.x * lda;
    float s = 0.0f;
    for (int k = threadIdx.x; k < K; k += blockDim.x) s += a[k] * w[k];
#pragma unroll
    for (int o = 16; o > 0; o >>= 1) s += __shfl_down_sync(0xffffffffu, s, o);
    if ((threadIdx.x & 31) == 0) red[threadIdx.x >> 5] = s;
    __syncthreads();
    if (threadIdx.x == 0) {
        float t = 0.0f;
        int nw = blockDim.x >> 5;
        for (int i = 0; i < nw; i++) t += red[i];
        if (EPI == 1) t = tanhf(t);
        out[blockIdx.x] = t;
    }
}

// out[j] = scale * sum_n (w ? w[n] : 1) * A[n*lda + j]
__global__ void colsum_kernel(const float* __restrict__ A, int lda, int rows,
                              const float* __restrict__ w, float scale,
                              float* __restrict__ out, int ncols)
{
    int j = blockIdx.x * blockDim.x + threadIdx.x;
    if (j >= ncols) return;
    float s = 0.0f;
#pragma unroll 4
    for (int n = 0; n < rows; n++) {
        float v = A[(size_t)n * lda + j];
        s += w ? w[n] * v : v;
    }
    out[j] = s * scale;
}

// cat[n] = [ h[n] , gate(h)[n] ]
__global__ void gate_cat_kernel(const float* __restrict__ h,
                                const float* __restrict__ u,
                                const float* __restrict__ vsc,
                                const float* __restrict__ s,
                                float* __restrict__ cat)
{
    int idx = blockIdx.x * blockDim.x + threadIdx.x;
    if (idx >= N_NODES * G4) return;
    int n = idx / G4, j = idx % G4;
    float hv = h[(size_t)n * G4 + j];
    float h0 = h[j];
    float val;
    if (n == 0) {
        val = h0;
    } else {
        float g = sigm_(u[n] + vsc[0]);
        val = g * s[j] + (1.0f - g) * ((float)(N_NODES - 1) * h0);
    }
    cat[(size_t)n * 2400 + j] = hv;
    cat[(size_t)n * 2400 + 1200 + j] = val;
}

__global__ void att_softmax_kernel(const float* __restrict__ e1,
                                   const float* __restrict__ e2,
                                   const int* __restrict__ adj,
                                   float* __restrict__ att)
{
    __shared__ float warpred[4];
    __shared__ float s_max, s_sum;
    int i = blockIdx.x;
    float ei = e1[i];

    float mx = -3.4e38f;
    for (int j = threadIdx.x; j < N_NODES; j += blockDim.x) {
        float v = ei + e2[j];
        v = (v > 0.0f) ? v : 0.01f * v;
        if (adj[(size_t)i * N_NODES + j] <= 0) v = -9.0e15f;
        mx = fmaxf(mx, v);
    }
#pragma unroll
    for (int o = 16; o > 0; o >>= 1) mx = fmaxf(mx, __shfl_down_sync(0xffffffffu, mx, o));
    if ((threadIdx.x & 31) == 0) warpred[threadIdx.x >> 5] = mx;
    __syncthreads();
    if (threadIdx.x == 0) {
        float m2 = warpred[0];
        int nw = blockDim.x >> 5;
        for (int k = 1; k < nw; k++) m2 = fmaxf(m2, warpred[k]);
        s_max = m2;
    }
    __syncthreads();
    float smax = s_max;

    float sum = 0.0f;
    for (int j = threadIdx.x; j < N_NODES; j += blockDim.x) {
        float v = ei + e2[j];
        v = (v > 0.0f) ? v : 0.01f * v;
        if (adj[(size_t)i * N_NODES + j] <= 0) v = -9.0e15f;
        sum += expf(v - smax);
    }
#pragma unroll
    for (int o = 16; o > 0; o >>= 1) sum += __shfl_down_sync(0xffffffffu, sum, o);
    if ((threadIdx.x & 31) == 0) warpred[threadIdx.x >> 5] = sum;
    __syncthreads();
    if (threadIdx.x == 0) {
        float t = 0.0f;
        int nw = blockDim.x >> 5;
        for (int k = 0; k < nw; k++) t += warpred[k];
        s_sum = t;
    }
    __syncthreads();
    float inv = 1.0f / s_sum;

    for (int j = threadIdx.x; j < N_NODES; j += blockDim.x) {
        float v = ei + e2[j];
        v = (v > 0.0f) ? v : 0.01f * v;
        if (adj[(size_t)i * N_NODES + j] <= 0) v = -9.0e15f;
        att[(size_t)i * N_NODES + j] = expf(v - smax) * inv;
    }
}

// Z[n] = [hc, hs2[n], hc*hs2[n], hc - hs2[n]],  hc = hs2[0]
__global__ void zassemble_kernel(const float* __restrict__ h2, float* __restrict__ Z)
{
    int idx = blockIdx.x * blockDim.x + threadIdx.x;
    if (idx >= N_NODES * G4) return;
    int n = idx / G4, j = idx % G4;
    float a = h2[j];
    float b = h2[(size_t)n * G4 + j];
    size_t base = (size_t)n * 4800;
    Z[base + j]        = a;
    Z[base + 1200 + j] = b;
    Z[base + 2400 + j] = a * b;
    Z[base + 3600 + j] = a - b;
}

__global__ void final_kernel(const float* __restrict__ ea,
                             const float* __restrict__ Wlin,
                             const float* __restrict__ blin,
                             float* __restrict__ out)
{
    __shared__ float r0[8], r1[8];
    float s0 = 0.0f, s1 = 0.0f;
    for (int j = threadIdx.x; j < 2400; j += blockDim.x) {
        float e = ea[j];
        s0 += e * Wlin[j];
        s1 += e * Wlin[2400 + j];
    }
#pragma unroll
    for (int o = 16; o > 0; o >>= 1) {
        s0 += __shfl_down_sync(0xffffffffu, s0, o);
        s1 += __shfl_down_sync(0xffffffffu, s1, o);
    }
    if ((threadIdx.x & 31) == 0) { r0[threadIdx.x >> 5] = s0; r1[threadIdx.x >> 5] = s1; }
    __syncthreads();
    if (threadIdx.x == 0) {
        float l0 = 0.0f, l1 = 0.0f;
        int nw = blockDim.x >> 5;
        for (int i = 0; i < nw; i++) { l0 += r0[i]; l1 += r1[i]; }
        l0 += blin[0]; l1 += blin[1];
        float m = fmaxf(l0, l1);
        float e0 = expf(l0 - m), e1v = expf(l1 - m);
        float inv = 1.0f / (e0 + e1v);
        out[0] = e0 * inv;
        out[1] = e1v * inv;
    }
}

// ---------------------------------------------------------------------------
// Host orchestration
// ---------------------------------------------------------------------------
static inline dim3 grid64(int M, int N)  { return dim3((N + BN - 1) / BN, (M + BM - 1) / BM); }
static inline dim3 grid128(int M, int N) { return dim3((N + XBN - 1) / XBN, (M + XBM - 1) / XBM); }

static void run_gate_gat(const float* h_in, float* h_out,
                         const float* gate_W, const float* gate_U,
                         const float* W_gat, const float* a_gat,
                         const int* adj, float* pool)
{
    float* U   = pool + OFF_U;
    float* Vb  = pool + OFF_V;
    float* S   = pool + OFF_S;
    float* CAT = pool + OFF_CAT;
    float* WHp = pool + OFF_WH;
    float* E1  = pool + OFF_E1;
    float* E2  = pool + OFF_E2;
    float* ATT = pool + OFF_ATT;

    rows_dot_kernel<0><<<N_NODES, 256>>>(h_in, G4, gate_W, G4, U);
    rows_dot_kernel<0><<<1, 256>>>(h_in, G4, gate_U, G4, Vb);
    colsum_kernel<<<(G4 + 255) / 256, 256>>>(h_in + G4, G4, N_NODES - 1, nullptr, 1.0f, S, G4);
    gate_cat_kernel<<<(N_NODES * G4 + 255) / 256, 256>>>(h_in, U, Vb, S, CAT);

    gemm_kernel<0, 0><<<grid64(N_NODES, G4), 256>>>(
        N_NODES, G4, 2400, CAT, 2400, W_gat, G4, nullptr, 0, WHp, G4);
    rows_dot_kernel<0><<<N_NODES, 256>>>(WHp, G4, a_gat, G4, E1);
    rows_dot_kernel<0><<<N_NODES, 256>>>(WHp, G4, a_gat + G4, G4, E2);
    att_softmax_kernel<<<N_NODES, 128>>>(E1, E2, adj, ATT);
    gemm_kernel<0, 2><<<grid64(N_NODES, G4), 256>>>(
        N_NODES, G4, N_NODES, ATT, N_NODES, WHp, G4, nullptr, 0, h_out, G4);
}

extern "C" void kernel_launch(void* const* d_in, const int* in_sizes, int n_in,
                              void* d_out, int out_size)
{
    (void)in_sizes; (void)n_in; (void)out_size;

    float* pool = nullptr;
    cudaGetSymbolAddress((void**)&pool, g_pool);

    static bool attr_done = false;
    if (!attr_done) {
        cudaFuncSetAttribute(lstm_scan_kernel,
                             cudaFuncAttributeMaxDynamicSharedMemorySize, (int)SMEM_SCAN);
        attr_done = true;
    }

    const int*   tokens  = (const int*)d_in[0];
    const int*   adj     = (const int*)d_in[1];
    const float* emb     = (const float*)d_in[2];
    const float* Wih_l0f = (const float*)d_in[3];
    const float* Whh_l0f = (const float*)d_in[4];
    const float* b_l0f   = (const float*)d_in[5];
    const float* Wih_l0b = (const float*)d_in[6];
    const float* Whh_l0b = (const float*)d_in[7];
    const float* b_l0b   = (const float*)d_in[8];
    const float* Wih_l1f = (const float*)d_in[9];
    const float* Whh_l1f = (const float*)d_in[10];
    const float* b_l1f   = (const float*)d_in[11];
    const float* Wih_l1b = (const float*)d_in[12];
    const float* Whh_l1b = (const float*)d_in[13];
    const float* b_l1b   = (const float*)d_in[14];
    const float* W_gat   = (const float*)d_in[15];
    const float* a_gat   = (const float*)d_in[16];
    const float* gate_W  = (const float*)d_in[17];
    const float* gate_U  = (const float*)d_in[18];
    const float* FC1     = (const float*)d_in[19];
    const float* FC2     = (const float*)d_in[20];
    const float* Wlin    = (const float*)d_in[21];
    const float* blin    = (const float*)d_in[22];
    float* out = (float*)d_out;

    float* X    = pool + OFF_X;
    float* PF   = pool + OFF_P0F;
    float* PB   = pool + OFF_P0B;
    float* O0   = pool + OFF_O0;
    float* HSA  = pool + OFF_HSA;
    float* HSB  = pool + OFF_HSB;
    float* HS1  = pool + OFF_HS1;
    float* HS2  = pool + OFF_HS2;
    float* Z    = pool + OFF_Z;
    float* HC3  = pool + OFF_HC3;
    float* WHHR  = pool + OFF_WHHR;   // 4 x [1200][300]: l0f,l0b,l1f,l1b
    float* WIHR0 = pool + OFF_WIHR0;  // 2 x [1200][300]
    float* WIHR1 = pool + OFF_WIHR1;  // 2 x [1200][600]
    float* BR    = pool + OFF_BR;     // 4 x [1200]
    unsigned* BARC = (unsigned*)(pool + OFF_BAR);
    float* BATT = pool + OFF_BATT;
    float* EA   = pool + OFF_EA;

    const int LN = L_SEQ * N_NODES;   // 17300
    const size_t W3 = (size_t)G4 * 300, W6 = (size_t)G4 * 600;

    const int thr = 256;
    const int g3 = (int)((W3 + thr - 1) / thr), g6 = (int)((W6 + thr - 1) / thr);
    const int g1 = (G4 + thr - 1) / thr;

    // ---- weight reorders (gate-interleaved rows) ----
    reorder_rows_kernel<<<g3, thr>>>(Wih_l0f, WIHR0 + 0 * W3, 300);
    reorder_rows_kernel<<<g3, thr>>>(Wih_l0b, WIHR0 + 1 * W3, 300);
    reorder_rows_kernel<<<g3, thr>>>(Whh_l0f, WHHR + 0 * W3, 300);
    reorder_rows_kernel<<<g3, thr>>>(Whh_l0b, WHHR + 1 * W3, 300);
    reorder_rows_kernel<<<g3, thr>>>(Whh_l1f, WHHR + 2 * W3, 300);
    reorder_rows_kernel<<<g3, thr>>>(Whh_l1b, WHHR + 3 * W3, 300);
    reorder_rows_kernel<<<g6, thr>>>(Wih_l1f, WIHR1 + 0 * W6, 600);
    reorder_rows_kernel<<<g6, thr>>>(Wih_l1b, WIHR1 + 1 * W6, 600);
    reorder_rows_kernel<<<g1, thr>>>(b_l0f, BR + 0 * G4, 1);
    reorder_rows_kernel<<<g1, thr>>>(b_l0b, BR + 1 * G4, 1);
    reorder_rows_kernel<<<g1, thr>>>(b_l1f, BR + 2 * G4, 1);
    reorder_rows_kernel<<<g1, thr>>>(b_l1b, BR + 3 * G4, 1);

    // ---- init states ----
    memzero_kernel<<<((int)SZ_NG4 + 255) / 256, 256>>>(HSA, (int)SZ_NG4);

    // ---- embedding ----
    embed_kernel<<<(int)((SZ_X + 255) / 256), 256>>>(tokens, emb, X);

    // ---- layer-0 input projections ----
    gemm128_kernel<1, 0><<<grid128(LN, G4), 256>>>(
        LN, G4, D_EMB, X, D_EMB, WIHR0 + 0 * W3, 300, BR + 0 * G4, 0, PF, G4);
    gemm128_kernel<1, 0><<<grid128(LN, G4), 256>>>(
        LN, G4, D_EMB, X, D_EMB, WIHR0 + 1 * W3, 300, BR + 1 * G4, 0, PB, G4);

    // ---- layer-0 scan (persistent, 50 steps in one launch) ----
    {
        memzero_kernel<<<1, 32>>>((float*)BARC, 1);
        dim3 grid(LSTM_GX, LSTM_GY, 2);
        lstm_scan_kernel<<<grid, 256, SMEM_SCAN>>>(
            HSA, HSB, 0, 300,
            WHHR + 0 * W3, WHHR + 1 * W3,
            PF, PB, O0, BARC);
    }

    // ---- layer-1 input projections ----
    gemm128_kernel<1, 0><<<grid128(LN, G4), 256>>>(
        LN, G4, 600, O0, 600, WIHR1 + 0 * W6, 600, BR + 2 * G4, 0, PF, G4);
    gemm128_kernel<1, 0><<<grid128(LN, G4), 256>>>(
        LN, G4, 600, O0, 600, WIHR1 + 1 * W6, 600, BR + 3 * G4, 0, PB, G4);

    // ---- layer-1 scan (persistent) ----
    {
        memzero_kernel<<<1, 32>>>((float*)BARC, 1);
        dim3 grid(LSTM_GX, LSTM_GY, 2);
        lstm_scan_kernel<<<grid, 256, SMEM_SCAN>>>(
            HSA, HSB, 600, 900,
            WHHR + 2 * W3, WHHR + 3 * W3,
            PF, PB, nullptr, BARC);
    }
    // L_SEQ=50 (even): final h for both layers lands in HSA.

    // ---- two gate+GAT stages ----
    run_gate_gat(HSA, HS1, gate_W, gate_U, W_gat, a_gat, adj, pool);
    run_gate_gat(HS1, HS2, gate_W, gate_U, W_gat, a_gat, adj, pool);

    // ---- final head ----
    zassemble_kernel<<<(N_NODES * G4 + 255) / 256, 256>>>(HS2, Z);
    gemm128_kernel<0, 1><<<grid128(N_NODES, 9600), 256>>>(
        N_NODES, 9600, 4800, Z, 4800, FC1, 9600, nullptr, 0, HC3, 9600);
    rows_dot_kernel<1><<<N_NODES, 256>>>(HC3, 9600, FC2, 9600, BATT);
    colsum_kernel<<<(G4 + 255) / 256, 256>>>(HS2, G4, N_NODES, nullptr,
                                             1.0f / (float)N_NODES, EA, G4);
    colsum_kernel<<<(G4 + 255) / 256, 256>>>(HS2, G4, N_NODES, BATT, 1.0f, EA + G4, G4);
    final_kernel<<<1, 256>>>(EA, Wlin, blin, out);
}

// round 12
// speedup vs baseline: 1.7744x; 1.0129x over previous
#include <cuda_runtime.h>
#include <math.h>

#define N_NODES 346
#define L_SEQ   50
#define D_EMB   300
#define H_HID   300
#define G4      1200   // 4*H

// ---------------------------------------------------------------------------
// Scratch pool (static device allocation — no cudaMalloc anywhere)
// ---------------------------------------------------------------------------
constexpr size_t A256(size_t x) { return (x + 255) & ~(size_t)255; }

constexpr size_t SZ_X   = (size_t)L_SEQ * N_NODES * D_EMB;
constexpr size_t SZ_P   = (size_t)L_SEQ * N_NODES * G4;
constexpr size_t SZ_O0  = (size_t)L_SEQ * N_NODES * 600;
constexpr size_t SZ_NG4 = (size_t)N_NODES * G4;

constexpr size_t OFF_X    = 0;
constexpr size_t OFF_P0F  = A256(OFF_X   + SZ_X);
constexpr size_t OFF_P0B  = A256(OFF_P0F + SZ_P);
constexpr size_t OFF_O0   = A256(OFF_P0B + SZ_P);
constexpr size_t OFF_HSA  = A256(OFF_O0  + SZ_O0);
constexpr size_t OFF_HSB  = A256(OFF_HSA + SZ_NG4);
constexpr size_t OFF_CAT  = A256(OFF_HSB + SZ_NG4);
constexpr size_t OFF_WH   = A256(OFF_CAT + (size_t)N_NODES * 2400);
constexpr size_t OFF_ATT  = A256(OFF_WH  + SZ_NG4);
constexpr size_t OFF_HS1  = A256(OFF_ATT + (size_t)N_NODES * N_NODES);
constexpr size_t OFF_HS2  = A256(OFF_HS1 + SZ_NG4);
constexpr size_t OFF_Z    = A256(OFF_HS2 + SZ_NG4);
constexpr size_t OFF_HC3  = A256(OFF_Z   + (size_t)N_NODES * 4800);
constexpr size_t OFF_WHHR  = A256(OFF_HC3  + (size_t)N_NODES * 9600);
constexpr size_t OFF_WIHR0 = A256(OFF_WHHR + 4 * (size_t)G4 * H_HID);
constexpr size_t OFF_WIHR1 = A256(OFF_WIHR0 + 2 * (size_t)G4 * 300);
constexpr size_t OFF_BR    = A256(OFF_WIHR1 + 2 * (size_t)G4 * 600);
constexpr size_t OFF_BAR  = A256(OFF_BR  + 4 * (size_t)G4);
constexpr size_t OFF_U    = A256(OFF_BAR + 64);
constexpr size_t OFF_V    = A256(OFF_U   + 512);
constexpr size_t OFF_S    = A256(OFF_V   + 32);
constexpr size_t OFF_E1   = A256(OFF_S   + 1280);
constexpr size_t OFF_E2   = A256(OFF_E1  + 512);
constexpr size_t OFF_BATT = A256(OFF_E2  + 512);
constexpr size_t OFF_EA   = A256(OFF_BATT + 512);
// FC1 split-K partials: 8 x [346][9600]
constexpr size_t SZ_HC   = (size_t)N_NODES * 9600;          // 3,321,600
constexpr size_t OFF_FCP  = A256(OFF_EA + 2560);
constexpr size_t POOL_SZ  = A256(OFF_FCP + 8 * SZ_HC);

__device__ float g_pool[POOL_SZ];

__device__ __forceinline__ float sigm_(float x) { return 1.0f / (1.0f + expf(-x)); }

// ---------------------------------------------------------------------------
// 64x64x16 fp32 GEMM core, double-buffered (R10 winner) — GAT GEMMs
// ---------------------------------------------------------------------------
#define BM 64
#define BN 64
#define BK 16
#define SPAD 68

template<int TB>
__device__ __forceinline__ void gemm_acc64(
    int M, int N, int K,
    const float* __restrict__ A, int lda,
    const float* __restrict__ B, int ldb,
    float (*As)[BK * SPAD], float (*Bs)[BK * SPAD], float acc[4][4],
    int m0, int n0, int tid, int tx, int ty)
{
#pragma unroll
    for (int i = 0; i < 4; i++)
#pragma unroll
        for (int j = 0; j < 4; j++) acc[i][j] = 0.0f;

    const int nt = (K + BK - 1) / BK;

#pragma unroll
    for (int i = 0; i < 4; i++) {
        int idx = tid + i * 256;
        int m = idx >> 4, k = idx & 15;
        int gm = m0 + m, gk = k;
        As[0][k * SPAD + m] = (gm < M && gk < K) ? __ldg(&A[(size_t)gm * lda + gk]) : 0.0f;
    }
    if (TB) {
#pragma unroll
        for (int i = 0; i < 4; i++) {
            int idx = tid + i * 256;
            int j = idx >> 4, k = idx & 15;
            int gj = n0 + j, gk = k;
            Bs[0][k * SPAD + j] = (gj < N && gk < K) ? __ldg(&B[(size_t)gj * ldb + gk]) : 0.0f;
        }
    } else {
#pragma unroll
        for (int i = 0; i < 4; i++) {
            int idx = tid + i * 256;
            int j = idx & 63, k = idx >> 6;
            int gj = n0 + j, gk = k;
            Bs[0][k * SPAD + j] = (gj < N && gk < K) ? __ldg(&B[(size_t)gk * ldb + gj]) : 0.0f;
        }
    }
    __syncthreads();

    float ra[4], rb[4];
    for (int t = 0; t < nt; t++) {
        const int cur = t & 1;
        const bool more = (t + 1 < nt);
        if (more) {
            int k0 = (t + 1) * BK;
#pragma unroll
            for (int i = 0; i < 4; i++) {
                int idx = tid + i * 256;
                int m = idx >> 4, k = idx & 15;
                int gm = m0 + m, gk = k0 + k;
                ra[i] = (gm < M && gk < K) ? __ldg(&A[(size_t)gm * lda + gk]) : 0.0f;
            }
            if (TB) {
#pragma unroll
                for (int i = 0; i < 4; i++) {
                    int idx = tid + i * 256;
                    int j = idx >> 4, k = idx & 15;
                    int gj = n0 + j, gk = k0 + k;
                    rb[i] = (gj < N && gk < K) ? __ldg(&B[(size_t)gj * ldb + gk]) : 0.0f;
                }
            } else {
#pragma unroll
                for (int i = 0; i < 4; i++) {
                    int idx = tid + i * 256;
                    int j = idx & 63, k = idx >> 6;
                    int gj = n0 + j, gk = k0 + k;
                    rb[i] = (gj < N && gk < K) ? __ldg(&B[(size_t)gk * ldb + gj]) : 0.0f;
                }
            }
        }
#pragma unroll
        for (int kk = 0; kk < BK; kk++) {
            float4 av = *reinterpret_cast<const float4*>(&As[cur][kk * SPAD + ty * 4]);
            float4 bv = *reinterpret_cast<const float4*>(&Bs[cur][kk * SPAD + tx * 4]);
            float a[4] = {av.x, av.y, av.z, av.w};
            float b[4] = {bv.x, bv.y, bv.z, bv.w};
#pragma unroll
            for (int i = 0; i < 4; i++)
#pragma unroll
                for (int j = 0; j < 4; j++)
                    acc[i][j] += a[i] * b[j];
        }
        if (more) {
            const int nxt = cur ^ 1;
#pragma unroll
            for (int i = 0; i < 4; i++) {
                int idx = tid + i * 256;
                int m = idx >> 4, k = idx & 15;
                As[nxt][k * SPAD + m] = ra[i];
            }
            if (TB) {
#pragma unroll
                for (int i = 0; i < 4; i++) {
                    int idx = tid + i * 256;
                    int j = idx >> 4, k = idx & 15;
                    Bs[nxt][k * SPAD + j] = rb[i];
                }
            } else {
#pragma unroll
                for (int i = 0; i < 4; i++) {
                    int idx = tid + i * 256;
                    int j = idx & 63, k = idx >> 6;
                    Bs[nxt][k * SPAD + j] = rb[i];
                }
            }
            __syncthreads();
        }
    }
}

template<int TB, int EPI>
__global__ void __launch_bounds__(256) gemm_kernel(
    int M, int N, int K,
    const float* __restrict__ A, int lda,
    const float* __restrict__ B, int ldb,
    const float* __restrict__ Dm, int ldd,
    float* __restrict__ C, int ldc)
{
    __shared__ float As[2][BK * SPAD], Bs[2][BK * SPAD];
    const int m0 = blockIdx.y * BM, n0 = blockIdx.x * BN;
    const int tid = threadIdx.x, tx = tid & 15, ty = tid >> 4;
    float acc[4][4];
    gemm_acc64<TB>(M, N, K, A, lda, B, ldb, As, Bs, acc, m0, n0, tid, tx, ty);

#pragma unroll
    for (int i = 0; i < 4; i++) {
        int gm = m0 + ty * 4 + i;
        if (gm >= M) continue;
#pragma unroll
        for (int j = 0; j < 4; j++) {
            int gn = n0 + tx * 4 + j;
            if (gn >= N) continue;
            float v = acc[i][j];
            if (Dm) v += (ldd == 0) ? Dm[gn] : Dm[(size_t)gm * ldd + gn];
            if (EPI == 1) v = tanhf(v);
            if (EPI == 2) v = (v > 0.0f) ? v : expm1f(v);
            C[(size_t)gm * ldc + gn] = v;
        }
    }
}

// ---------------------------------------------------------------------------
// 128x128x8 fp32 GEMM, 8x8 per thread, double-buffered (R10 winner)
// ---------------------------------------------------------------------------
#define XBM 128
#define XBN 128
#define XBK 8
#define XPAD 132

template<int TB, int EPI>
__global__ void __launch_bounds__(256) gemm128_kernel(
    int M, int N, int K,
    const float* __restrict__ A, int lda,
    const float* __restrict__ B, int ldb,
    const float* __restrict__ Dm, int ldd,
    float* __restrict__ C, int ldc)
{
    __shared__ float As[2][XBK * XPAD], Bs[2][XBK * XPAD];
    const int m0 = blockIdx.y * XBM, n0 = blockIdx.x * XBN;
    const int tid = threadIdx.x, tx = tid & 15, ty = tid >> 4;

    float acc[8][8];
#pragma unroll
    for (int i = 0; i < 8; i++)
#pragma unroll
        for (int j = 0; j < 8; j++) acc[i][j] = 0.0f;

    const int nt = (K + XBK - 1) / XBK;

#pragma unroll
    for (int l = 0; l < 4; l++) {
        int idx = tid + l * 256;
        int m = idx >> 3, k = idx & 7;
        int gm = m0 + m, gk = k;
        As[0][k * XPAD + m] = (gm < M && gk < K) ? __ldg(&A[(size_t)gm * lda + gk]) : 0.0f;
    }
    if (TB) {
#pragma unroll
        for (int l = 0; l < 4; l++) {
            int idx = tid + l * 256;
            int j = idx >> 3, k = idx & 7;
            int gj = n0 + j, gk = k;
            Bs[0][k * XPAD + j] = (gj < N && gk < K) ? __ldg(&B[(size_t)gj * ldb + gk]) : 0.0f;
        }
    } else {
#pragma unroll
        for (int l = 0; l < 4; l++) {
            int idx = tid + l * 256;
            int k = idx >> 7, j = idx & 127;
            int gj = n0 + j, gk = k;
            Bs[0][k * XPAD + j] = (gj < N && gk < K) ? __ldg(&B[(size_t)gk * ldb + gj]) : 0.0f;
        }
    }
    __syncthreads();

    float ra[4], rb[4];
    for (int t = 0; t < nt; t++) {
        const int cur = t & 1;
        const bool more = (t + 1 < nt);
        if (more) {
            int k0 = (t + 1) * XBK;
#pragma unroll
            for (int l = 0; l < 4; l++) {
                int idx = tid + l * 256;
                int m = idx >> 3, k = idx & 7;
                int gm = m0 + m, gk = k0 + k;
                ra[l] = (gm < M && gk < K) ? __ldg(&A[(size_t)gm * lda + gk]) : 0.0f;
            }
            if (TB) {
#pragma unroll
                for (int l = 0; l < 4; l++) {
                    int idx = tid + l * 256;
                    int j = idx >> 3, k = idx & 7;
                    int gj = n0 + j, gk = k0 + k;
                    rb[l] = (gj < N && gk < K) ? __ldg(&B[(size_t)gj * ldb + gk]) : 0.0f;
                }
            } else {
#pragma unroll
                for (int l = 0; l < 4; l++) {
                    int idx = tid + l * 256;
                    int k = idx >> 7, j = idx & 127;
                    int gj = n0 + j, gk = k0 + k;
                    rb[l] = (gj < N && gk < K) ? __ldg(&B[(size_t)gk * ldb + gj]) : 0.0f;
                }
            }
        }
#pragma unroll
        for (int kk = 0; kk < XBK; kk++) {
            float a[8], b[8];
            float4 a0 = *reinterpret_cast<const float4*>(&As[cur][kk * XPAD + ty * 8]);
            float4 a1 = *reinterpret_cast<const float4*>(&As[cur][kk * XPAD + ty * 8 + 4]);
            float4 b0 = *reinterpret_cast<const float4*>(&Bs[cur][kk * XPAD + tx * 8]);
            float4 b1 = *reinterpret_cast<const float4*>(&Bs[cur][kk * XPAD + tx * 8 + 4]);
            a[0]=a0.x; a[1]=a0.y; a[2]=a0.z; a[3]=a0.w;
            a[4]=a1.x; a[5]=a1.y; a[6]=a1.z; a[7]=a1.w;
            b[0]=b0.x; b[1]=b0.y; b[2]=b0.z; b[3]=b0.w;
            b[4]=b1.x; b[5]=b1.y; b[6]=b1.z; b[7]=b1.w;
#pragma unroll
            for (int i = 0; i < 8; i++)
#pragma unroll
                for (int j = 0; j < 8; j++)
                    acc[i][j] += a[i] * b[j];
        }
        if (more) {
            const int nxt = cur ^ 1;
#pragma unroll
            for (int l = 0; l < 4; l++) {
                int idx = tid + l * 256;
                int m = idx >> 3, k = idx & 7;
                As[nxt][k * XPAD + m] = ra[l];
            }
            if (TB) {
#pragma unroll
                for (int l = 0; l < 4; l++) {
                    int idx = tid + l * 256;
                    int j = idx >> 3, k = idx & 7;
                    Bs[nxt][k * XPAD + j] = rb[l];
                }
            } else {
#pragma unroll
                for (int l = 0; l < 4; l++) {
                    int idx = tid + l * 256;
                    int k = idx >> 7, j = idx & 127;
                    Bs[nxt][k * XPAD + j] = rb[l];
                }
            }
            __syncthreads();
        }
    }

#pragma unroll
    for (int i = 0; i < 8; i++) {
        int gm = m0 + ty * 8 + i;
        if (gm >= M) continue;
#pragma unroll
        for (int j = 0; j < 8; j++) {
            int gn = n0 + tx * 8 + j;
            if (gn >= N) continue;
            float v = acc[i][j];
            if (Dm) v += (ldd == 0) ? Dm[gn] : Dm[(size_t)gm * ldd + gn];
            if (EPI == 1) v = tanhf(v);
            if (EPI == 2) v = (v > 0.0f) ? v : expm1f(v);
            C[(size_t)gm * ldc + gn] = v;
        }
    }
}

// ---------------------------------------------------------------------------
// FC1 split-K: partial GEMM (K chunk 600 per z-slice) + reduction with tanh.
//   Z [346][4800] @ FC1 [4800][9600] -> HC3 [346][9600]
// ---------------------------------------------------------------------------
#define FC1_KS 8
#define FC1_KC 600

__global__ void __launch_bounds__(256) fc1_partial_kernel(
    const float* __restrict__ A,     // Z, lda 4800
    const float* __restrict__ B,     // FC1, ldb 9600
    float* __restrict__ P)           // partials [8][346][9600]
{
    __shared__ float As[2][XBK * XPAD], Bs[2][XBK * XPAD];
    const int M = N_NODES, N = 9600;
    const int lda = 4800, ldb = 9600;
    const int kbase = blockIdx.z * FC1_KC;
    const int m0 = blockIdx.y * XBM, n0 = blockIdx.x * XBN;
    const int tid = threadIdx.x, tx = tid & 15, ty = tid >> 4;
    float* C = P + (size_t)blockIdx.z * SZ_HC;

    float acc[8][8];
#pragma unroll
    for (int i = 0; i < 8; i++)
#pragma unroll
        for (int j = 0; j < 8; j++) acc[i][j] = 0.0f;

    const int nt = FC1_KC / XBK;   // 75

#pragma unroll
    for (int l = 0; l < 4; l++) {
        int idx = tid + l * 256;
        int m = idx >> 3, k = idx & 7;
        int gm = m0 + m;
        As[0][k * XPAD + m] = (gm < M) ? __ldg(&A[(size_t)gm * lda + kbase + k]) : 0.0f;
    }
#pragma unroll
    for (int l = 0; l < 4; l++) {
        int idx = tid + l * 256;
        int k = idx >> 7, j = idx & 127;
        int gj = n0 + j;
        Bs[0][k * XPAD + j] = __ldg(&B[(size_t)(kbase + k) * ldb + gj]);
    }
    __syncthreads();

    float ra[4], rb[4];
    for (int t = 0; t < nt; t++) {
        const int cur = t & 1;
        const bool more = (t + 1 < nt);
        if (more) {
            int k0 = kbase + (t + 1) * XBK;
#pragma unroll
            for (int l = 0; l < 4; l++) {
                int idx = tid + l * 256;
                int m = idx >> 3, k = idx & 7;
                int gm = m0 + m;
                ra[l] = (gm < M) ? __ldg(&A[(size_t)gm * lda + k0 + k]) : 0.0f;
            }
#pragma unroll
            for (int l = 0; l < 4; l++) {
                int idx = tid + l * 256;
                int k = idx >> 7, j = idx & 127;
                int gj = n0 + j;
                rb[l] = __ldg(&B[(size_t)(k0 + k) * ldb + gj]);
            }
        }
#pragma unroll
        for (int kk = 0; kk < XBK; kk++) {
            float a[8], b[8];
            float4 a0 = *reinterpret_cast<const float4*>(&As[cur][kk * XPAD + ty * 8]);
            float4 a1 = *reinterpret_cast<const float4*>(&As[cur][kk * XPAD + ty * 8 + 4]);
            float4 b0 = *reinterpret_cast<const float4*>(&Bs[cur][kk * XPAD + tx * 8]);
            float4 b1 = *reinterpret_cast<const float4*>(&Bs[cur][kk * XPAD + tx * 8 + 4]);
            a[0]=a0.x; a[1]=a0.y; a[2]=a0.z; a[3]=a0.w;
            a[4]=a1.x; a[5]=a1.y; a[6]=a1.z; a[7]=a1.w;
            b[0]=b0.x; b[1]=b0.y; b[2]=b0.z; b[3]=b0.w;
            b[4]=b1.x; b[5]=b1.y; b[6]=b1.z; b[7]=b1.w;
#pragma unroll
            for (int i = 0; i < 8; i++)
#pragma unroll
                for (int j = 0; j < 8; j++)
                    acc[i][j] += a[i] * b[j];
        }
        if (more) {
            const int nxt = cur ^ 1;
#pragma unroll
            for (int l = 0; l < 4; l++) {
                int idx = tid + l * 256;
                int m = idx >> 3, k = idx & 7;
                As[nxt][k * XPAD + m] = ra[l];
            }
#pragma unroll
            for (int l = 0; l < 4; l++) {
                int idx = tid + l * 256;
                int k = idx >> 7, j = idx & 127;
                Bs[nxt][k * XPAD + j] = rb[l];
            }
            __syncthreads();
        }
    }

#pragma unroll
    for (int i = 0; i < 8; i++) {
        int gm = m0 + ty * 8 + i;
        if (gm >= M) continue;
#pragma unroll
        for (int j = 0; j < 8; j++) {
            int gn = n0 + tx * 8 + j;
            C[(size_t)gm * 9600 + gn] = acc[i][j];
        }
    }
}

__global__ void fc1_reduce_kernel(const float* __restrict__ P, float* __restrict__ out)
{
    size_t idx = (size_t)blockIdx.x * blockDim.x + threadIdx.x;
    if (idx >= SZ_HC) return;
    float s = 0.0f;
#pragma unroll
    for (int z = 0; z < FC1_KS; z++) s += P[(size_t)z * SZ_HC + idx];
    out[idx] = tanhf(s);
}

// ---------------------------------------------------------------------------
// Persistent LSTM scan (R11 winner, unchanged)
// ---------------------------------------------------------------------------
constexpr int LSTM_GX = (G4 + BN - 1) / BN;        // 19
constexpr int LSTM_GY = (N_NODES + BM - 1) / BM;   // 6
constexpr unsigned LSTM_BLOCKS = LSTM_GX * LSTM_GY * 2;  // 228
constexpr int BS_ROWS = 304;
constexpr size_t SMEM_SCAN = (size_t)(BS_ROWS * SPAD + 2 * BK * SPAD) * 4;  // 91392 B

__global__ void __launch_bounds__(256) lstm_scan_kernel(
    float* __restrict__ hsA, float* __restrict__ hsB,
    int hcol_f, int hcol_b,
    const float* __restrict__ Whh_rf, const float* __restrict__ Whh_rb,
    const float* __restrict__ Pf, const float* __restrict__ Pb,
    float* __restrict__ outbuf,
    unsigned* __restrict__ bar)
{
    extern __shared__ float smem[];
    float* Bres = smem;
    float* As   = smem + BS_ROWS * SPAD;

    const int z = blockIdx.z;
    const int hcol = z ? hcol_b : hcol_f;
    const float* Bw = z ? Whh_rb : Whh_rf;
    const float* Pbase = z ? Pb : Pf;

    const int m0 = blockIdx.y * BM, n0 = blockIdx.x * BN;
    const int tid = threadIdx.x, tx = tid & 15, ty = tid >> 4;

    for (int idx = tid; idx < BN * BS_ROWS; idx += 256) {
        int j = idx / BS_ROWS, k = idx % BS_ROWS;
        int gj = n0 + j;
        Bres[k * SPAD + j] = (gj < G4 && k < H_HID) ? __ldg(&Bw[(size_t)gj * H_HID + k]) : 0.0f;
    }

    const int r0 = n0 + tx * 4;
    const bool valid_col = (r0 + 3 < G4);
    const int ju = r0 >> 2;
    float c_reg[4] = {0.0f, 0.0f, 0.0f, 0.0f};

    __syncthreads();

    const int nt = (H_HID + BK - 1) / BK;

    for (int t = 0; t < L_SEQ; t++) {
        const float* hin  = (t & 1) ? hsB : hsA;
        float*       hout = (t & 1) ? hsA : hsB;
        const float* A = hin + hcol;

#pragma unroll
        for (int i = 0; i < 4; i++) {
            int idx = tid + i * 256;
            int m = idx >> 4, k = idx & 15;
            int gm = m0 + m;
            As[k * SPAD + m] = (gm < N_NODES) ? __ldg(&A[(size_t)gm * G4 + k]) : 0.0f;
        }
        __syncthreads();

        float acc[4][4];
#pragma unroll
        for (int i = 0; i < 4; i++)
#pragma unroll
            for (int j = 0; j < 4; j++) acc[i][j] = 0.0f;

        float ra[4];
        for (int kt = 0; kt < nt; kt++) {
            const int cur = kt & 1;
            const bool more = (kt + 1 < nt);
            if (more) {
                int k0 = (kt + 1) * BK;
#pragma unroll
                for (int i = 0; i < 4; i++) {
                    int idx = tid + i * 256;
                    int m = idx >> 4, k = idx & 15;
                    int gm = m0 + m, gk = k0 + k;
                    ra[i] = (gm < N_NODES && gk < H_HID) ? __ldg(&A[(size_t)gm * G4 + gk]) : 0.0f;
                }
            }
#pragma unroll
            for (int kk = 0; kk < BK; kk++) {
                float4 av = *reinterpret_cast<const float4*>(&As[cur * (BK * SPAD) + kk * SPAD + ty * 4]);
                float4 bv = *reinterpret_cast<const float4*>(&Bres[(kt * BK + kk) * SPAD + tx * 4]);
                float a[4] = {av.x, av.y, av.z, av.w};
                float b[4] = {bv.x, bv.y, bv.z, bv.w};
#pragma unroll
                for (int i = 0; i < 4; i++)
#pragma unroll
                    for (int j = 0; j < 4; j++)
                        acc[i][j] += a[i] * b[j];
            }
            if (more) {
                const int nxt = cur ^ 1;
#pragma unroll
                for (int i = 0; i < 4; i++) {
                    int idx = tid + i * 256;
                    int m = idx >> 4, k = idx & 15;
                    As[nxt * (BK * SPAD) + k * SPAD + m] = ra[i];
                }
                __syncthreads();
            }
        }

        if (valid_col) {
            const size_t toff = (size_t)(z ? (L_SEQ - 1 - t) : t) * N_NODES * G4;
            const float* P = Pbase + toff;
#pragma unroll
            for (int i = 0; i < 4; i++) {
                int gm = m0 + ty * 4 + i;
                if (gm >= N_NODES) continue;
                float4 p = *reinterpret_cast<const float4*>(P + (size_t)gm * G4 + r0);
                float gi = acc[i][0] + p.x;
                float gf = acc[i][1] + p.y;
                float gg = acc[i][2] + p.z;
                float go = acc[i][3] + p.w;
                float cn = sigm_(gf) * c_reg[i] + sigm_(gi) * tanhf(gg);
                float h  = sigm_(go) * tanhf(cn);
                c_reg[i] = cn;
                hout[(size_t)gm * G4 + hcol + ju] = h;
                if (outbuf) {
                    int tt = z ? (L_SEQ - 1 - t) : t;
                    outbuf[(size_t)tt * N_NODES * 600 + (size_t)gm * 600 + z * H_HID + ju] = h;
                }
            }
        }

        if (t + 1 < L_SEQ) {
            __threadfence();
            __syncthreads();
            if (tid == 0) {
                atomicAdd(bar, 1u);
                const unsigned target = LSTM_BLOCKS * (unsigned)(t + 1);
                const volatile unsigned* vb = bar;
                while (*vb < target) __nanosleep(64);
                __threadfence();
            }
            __syncthreads();
        }
    }
}

// ---------------------------------------------------------------------------
// prep: all weight reorders + bias reorders + HSA zero in ONE kernel
// ---------------------------------------------------------------------------
constexpr size_t PREP_W3 = (size_t)G4 * 300;   // 360,000
constexpr size_t PREP_W6 = (size_t)G4 * 600;   // 720,000
constexpr size_t PREP_B0 = 6 * PREP_W3;                 // 2,160,000
constexpr size_t PREP_B1 = PREP_B0 + 2 * PREP_W6;       // 3,600,000
constexpr size_t PREP_B2 = PREP_B1 + 4 * (size_t)G4;    // 3,604,800
constexpr size_t PREP_TOTAL = PREP_B2 + SZ_NG4;         // 4,020,000

__device__ __forceinline__ void reo_(const float* in, float* out, size_t idx, int K) {
    int r = (int)(idx / K), k = (int)(idx % K);
    int j = r >> 2, g = r & 3;
    out[(size_t)r * K + k] = in[(size_t)(g * H_HID + j) * K + k];
}

__global__ void prep_kernel(
    const float* __restrict__ Wih_l0f, const float* __restrict__ Wih_l0b,
    const float* __restrict__ Whh_l0f, const float* __restrict__ Whh_l0b,
    const float* __restrict__ Whh_l1f, const float* __restrict__ Whh_l1b,
    const float* __restrict__ Wih_l1f, const float* __restrict__ Wih_l1b,
    const float* __restrict__ b_l0f, const float* __restrict__ b_l0b,
    const float* __restrict__ b_l1f, const float* __restrict__ b_l1b,
    float* __restrict__ pool)
{
    size_t i = (size_t)blockIdx.x * blockDim.x + threadIdx.x;
    if (i >= PREP_TOTAL) return;

    float* WIHR0 = pool + OFF_WIHR0;
    float* WIHR1 = pool + OFF_WIHR1;
    float* WHHR  = pool + OFF_WHHR;
    float* BR    = pool + OFF_BR;

    if (i < PREP_B0) {
        int seg = (int)(i / PREP_W3);
        size_t l = i % PREP_W3;
        switch (seg) {
            case 0: reo_(Wih_l0f, WIHR0 + 0 * PREP_W3, l, 300); break;
            case 1: reo_(Wih_l0b, WIHR0 + 1 * PREP_W3, l, 300); break;
            case 2: reo_(Whh_l0f, WHHR + 0 * PREP_W3, l, 300); break;
            case 3: reo_(Whh_l0b, WHHR + 1 * PREP_W3, l, 300); break;
            case 4: reo_(Whh_l1f, WHHR + 2 * PREP_W3, l, 300); break;
            default: reo_(Whh_l1b, WHHR + 3 * PREP_W3, l, 300); break;
        }
    } else if (i < PREP_B1) {
        size_t l = i - PREP_B0;
        if (l < PREP_W6) reo_(Wih_l1f, WIHR1 + 0 * PREP_W6, l, 600);
        else             reo_(Wih_l1b, WIHR1 + 1 * PREP_W6, l - PREP_W6, 600);
    } else if (i < PREP_B2) {
        size_t l = i - PREP_B1;
        int which = (int)(l / G4);
        int r = (int)(l % G4);
        int j = r >> 2, g = r & 3;
        const float* src = (which == 0) ? b_l0f : (which == 1) ? b_l0b : (which == 2) ? b_l1f : b_l1b;
        BR[(size_t)which * G4 + r] = src[g * H_HID + j];
    } else {
        pool[OFF_HSA + (i - PREP_B2)] = 0.0f;
    }
}

__global__ void memzero_kernel(float* p, int n)
{
    int i = blockIdx.x * blockDim.x + threadIdx.x;
    if (i < n) p[i] = 0.0f;
}

__global__ void embed_kernel(const int* __restrict__ tok,
                             const float* __restrict__ emb,
                             float* __restrict__ x)
{
    size_t idx = (size_t)blockIdx.x * blockDim.x + threadIdx.x;
    const size_t total = (size_t)L_SEQ * N_NODES * D_EMB;
    if (idx >= total) return;
    int d = (int)(idx % D_EMB);
    size_t r = idx / D_EMB;
    int n = (int)(r % N_NODES);
    int t = (int)(r / N_NODES);
    int tv = tok[n * L_SEQ + t];
    x[idx] = emb[(size_t)tv * D_EMB + d];
}

// out[row] = epi( dot(A[row,:K], w) )
template<int EPI>
__global__ void rows_dot_kernel(const float* __restrict__ A, int lda,
                                const float* __restrict__ w, int K,
                                float* __restrict__ out)
{
    __shared__ float red[8];
    const float* a = A + (size_t)blockIdx.x * lda;
    float s = 0.0f;
    for (int k = threadIdx.x; k < K; k += blockDim.x) s += a[k] * w[k];
#pragma unroll
    for (int o = 16; o > 0; o >>= 1) s += __shfl_down_sync(0xffffffffu, s, o);
    if ((threadIdx.x & 31) == 0) red[threadIdx.x >> 5] = s;
    __syncthreads();
    if (threadIdx.x == 0) {
        float t = 0.0f;
        int nw = blockDim.x >> 5;
        for (int i = 0; i < nw; i++) t += red[i];
        if (EPI == 1) t = tanhf(t);
        out[blockIdx.x] = t;
    }
}

// two dots per row in one pass (E1 = A.w1, E2 = A.w2)
__global__ void rows_dot2_kernel(const float* __restrict__ A, int lda,
                                 const float* __restrict__ w1,
                                 const float* __restrict__ w2, int K,
                                 float* __restrict__ out1, float* __restrict__ out2)
{
    __shared__ float red1[8], red2[8];
    const float* a = A + (size_t)blockIdx.x * lda;
    float s1 = 0.0f, s2 = 0.0f;
    for (int k = threadIdx.x; k < K; k += blockDim.x) {
        float v = a[k];
        s1 += v * w1[k];
        s2 += v * w2[k];
    }
#pragma unroll
    for (int o = 16; o > 0; o >>= 1) {
        s1 += __shfl_down_sync(0xffffffffu, s1, o);
        s2 += __shfl_down_sync(0xffffffffu, s2, o);
    }
    if ((threadIdx.x & 31) == 0) { red1[threadIdx.x >> 5] = s1; red2[threadIdx.x >> 5] = s2; }
    __syncthreads();
    if (threadIdx.x == 0) {
        float t1 = 0.0f, t2 = 0.0f;
        int nw = blockDim.x >> 5;
        for (int i = 0; i < nw; i++) { t1 += red1[i]; t2 += red2[i]; }
        out1[blockIdx.x] = t1;
        out2[blockIdx.x] = t2;
    }
}

// out[j] = scale * sum_n (w ? w[n] : 1) * A[n*lda + j]
__global__ void colsum_kernel(const float* __restrict__ A, int lda, int rows,
                              const float* __restrict__ w, float scale,
                              float* __restrict__ out, int ncols)
{
    int j = blockIdx.x * blockDim.x + threadIdx.x;
    if (j >= ncols) return;
    float s = 0.0f;
#pragma unroll 4
    for (int n = 0; n < rows; n++) {
        float v = A[(size_t)n * lda + j];
        s += w ? w[n] * v : v;
    }
    out[j] = s * scale;
}

// cat[n] = [ h[n] , gate(h)[n] ]
__global__ void gate_cat_kernel(const float* __restrict__ h,
                                const float* __restrict__ u,
                                const float* __restrict__ vsc,
                                const float* __restrict__ s,
                                float* __restrict__ cat)
{
    int idx = blockIdx.x * blockDim.x + threadIdx.x;
    if (idx >= N_NODES * G4) return;
    int n = idx / G4, j = idx % G4;
    float hv = h[(size_t)n * G4 + j];
    float h0 = h[j];
    float val;
    if (n == 0) {
        val = h0;
    } else {
        float g = sigm_(u[n] + vsc[0]);
        val = g * s[j] + (1.0f - g) * ((float)(N_NODES - 1) * h0);
    }
    cat[(size_t)n * 2400 + j] = hv;
    cat[(size_t)n * 2400 + 1200 + j] = val;
}

__global__ void att_softmax_kernel(const float* __restrict__ e1,
                                   const float* __restrict__ e2,
                                   const int* __restrict__ adj,
                                   float* __restrict__ att)
{
    __shared__ float warpred[4];
    __shared__ float s_max, s_sum;
    int i = blockIdx.x;
    float ei = e1[i];

    float mx = -3.4e38f;
    for (int j = threadIdx.x; j < N_NODES; j += blockDim.x) {
        float v = ei + e2[j];
        v = (v > 0.0f) ? v : 0.01f * v;
        if (adj[(size_t)i * N_NODES + j] <= 0) v = -9.0e15f;
        mx = fmaxf(mx, v);
    }
#pragma unroll
    for (int o = 16; o > 0; o >>= 1) mx = fmaxf(mx, __shfl_down_sync(0xffffffffu, mx, o));
    if ((threadIdx.x & 31) == 0) warpred[threadIdx.x >> 5] = mx;
    __syncthreads();
    if (threadIdx.x == 0) {
        float m2 = warpred[0];
        int nw = blockDim.x >> 5;
        for (int k = 1; k < nw; k++) m2 = fmaxf(m2, warpred[k]);
        s_max = m2;
    }
    __syncthreads();
    float smax = s_max;

    float sum = 0.0f;
    for (int j = threadIdx.x; j < N_NODES; j += blockDim.x) {
        float v = ei + e2[j];
        v = (v > 0.0f) ? v : 0.01f * v;
        if (adj[(size_t)i * N_NODES + j] <= 0) v = -9.0e15f;
        sum += expf(v - smax);
    }
#pragma unroll
    for (int o = 16; o > 0; o >>= 1) sum += __shfl_down_sync(0xffffffffu, sum, o);
    if ((threadIdx.x & 31) == 0) warpred[threadIdx.x >> 5] = sum;
    __syncthreads();
    if (threadIdx.x == 0) {
        float t = 0.0f;
        int nw = blockDim.x >> 5;
        for (int k = 0; k < nw; k++) t += warpred[k];
        s_sum = t;
    }
    __syncthreads();
    float inv = 1.0f / s_sum;

    for (int j = threadIdx.x; j < N_NODES; j += blockDim.x) {
        float v = ei + e2[j];
        v = (v > 0.0f) ? v : 0.01f * v;
        if (adj[(size_t)i * N_NODES + j] <= 0) v = -9.0e15f;
        att[(size_t)i * N_NODES + j] = expf(v - smax) * inv;
    }
}

// Z[n] = [hc, hs2[n], hc*hs2[n], hc - hs2[n]],  hc = hs2[0]
__global__ void zassemble_kernel(const float* __restrict__ h2, float* __restrict__ Z)
{
    int idx = blockIdx.x * blockDim.x + threadIdx.x;
    if (idx >= N_NODES * G4) return;
    int n = idx / G4, j = idx % G4;
    float a = h2[j];
    float b = h2[(size_t)n * G4 + j];
    size_t base = (size_t)n * 4800;
    Z[base + j]        = a;
    Z[base + 1200 + j] = b;
    Z[base + 2400 + j] = a * b;
    Z[base + 3600 + j] = a - b;
}

__global__ void final_kernel(const float* __restrict__ ea,
                             const float* __restrict__ Wlin,
                             const float* __restrict__ blin,
                             float* __restrict__ out)
{
    __shared__ float r0[8], r1[8];
    float s0 = 0.0f, s1 = 0.0f;
    for (int j = threadIdx.x; j < 2400; j += blockDim.x) {
        float e = ea[j];
        s0 += e * Wlin[j];
        s1 += e * Wlin[2400 + j];
    }
#pragma unroll
    for (int o = 16; o > 0; o >>= 1) {
        s0 += __shfl_down_sync(0xffffffffu, s0, o);
        s1 += __shfl_down_sync(0xffffffffu, s1, o);
    }
    if ((threadIdx.x & 31) == 0) { r0[threadIdx.x >> 5] = s0; r1[threadIdx.x >> 5] = s1; }
    __syncthreads();
    if (threadIdx.x == 0) {
        float l0 = 0.0f, l1 = 0.0f;
        int nw = blockDim.x >> 5;
        for (int i = 0; i < nw; i++) { l0 += r0[i]; l1 += r1[i]; }
        l0 += blin[0]; l1 += blin[1];
        float m = fmaxf(l0, l1);
        float e0 = expf(l0 - m), e1v = expf(l1 - m);
        float inv = 1.0f / (e0 + e1v);
        out[0] = e0 * inv;
        out[1] = e1v * inv;
    }
}

// ---------------------------------------------------------------------------
// Host orchestration
// ---------------------------------------------------------------------------
static inline dim3 grid64(int M, int N)  { return dim3((N + BN - 1) / BN, (M + BM - 1) / BM); }
static inline dim3 grid128(int M, int N) { return dim3((N + XBN - 1) / XBN, (M + XBM - 1) / XBM); }

static void run_gate_gat(const float* h_in, float* h_out,
                         const float* gate_W, const float* gate_U,
                         const float* W_gat, const float* a_gat,
                         const int* adj, float* pool)
{
    float* U   = pool + OFF_U;
    float* Vb  = pool + OFF_V;
    float* S   = pool + OFF_S;
    float* CAT = pool + OFF_CAT;
    float* WHp = pool + OFF_WH;
    float* E1  = pool + OFF_E1;
    float* E2  = pool + OFF_E2;
    float* ATT = pool + OFF_ATT;

    rows_dot_kernel<0><<<N_NODES, 256>>>(h_in, G4, gate_W, G4, U);
    rows_dot_kernel<0><<<1, 256>>>(h_in, G4, gate_U, G4, Vb);
    colsum_kernel<<<(G4 + 255) / 256, 256>>>(h_in + G4, G4, N_NODES - 1, nullptr, 1.0f, S, G4);
    gate_cat_kernel<<<(N_NODES * G4 + 255) / 256, 256>>>(h_in, U, Vb, S, CAT);

    gemm_kernel<0, 0><<<grid64(N_NODES, G4), 256>>>(
        N_NODES, G4, 2400, CAT, 2400, W_gat, G4, nullptr, 0, WHp, G4);
    rows_dot2_kernel<<<N_NODES, 256>>>(WHp, G4, a_gat, a_gat + G4, G4, E1, E2);
    att_softmax_kernel<<<N_NODES, 128>>>(E1, E2, adj, ATT);
    gemm_kernel<0, 2><<<grid64(N_NODES, G4), 256>>>(
        N_NODES, G4, N_NODES, ATT, N_NODES, WHp, G4, nullptr, 0, h_out, G4);
}

extern "C" void kernel_launch(void* const* d_in, const int* in_sizes, int n_in,
                              void* d_out, int out_size)
{
    (void)in_sizes; (void)n_in; (void)out_size;

    float* pool = nullptr;
    cudaGetSymbolAddress((void**)&pool, g_pool);

    static bool attr_done = false;
    if (!attr_done) {
        cudaFuncSetAttribute(lstm_scan_kernel,
                             cudaFuncAttributeMaxDynamicSharedMemorySize, (int)SMEM_SCAN);
        attr_done = true;
    }

    const int*   tokens  = (const int*)d_in[0];
    const int*   adj     = (const int*)d_in[1];
    const float* emb     = (const float*)d_in[2];
    const float* Wih_l0f = (const float*)d_in[3];
    const float* Whh_l0f = (const float*)d_in[4];
    const float* b_l0f   = (const float*)d_in[5];
    const float* Wih_l0b = (const float*)d_in[6];
    const float* Whh_l0b = (const float*)d_in[7];
    const float* b_l0b   = (const float*)d_in[8];
    const float* Wih_l1f = (const float*)d_in[9];
    const float* Whh_l1f = (const float*)d_in[10];
    const float* b_l1f   = (const float*)d_in[11];
    const float* Wih_l1b = (const float*)d_in[12];
    const float* Whh_l1b = (const float*)d_in[13];
    const float* b_l1b   = (const float*)d_in[14];
    const float* W_gat   = (const float*)d_in[15];
    const float* a_gat   = (const float*)d_in[16];
    const float* gate_W  = (const float*)d_in[17];
    const float* gate_U  = (const float*)d_in[18];
    const float* FC1     = (const float*)d_in[19];
    const float* FC2     = (const float*)d_in[20];
    const float* Wlin    = (const float*)d_in[21];
    const float* blin    = (const float*)d_in[22];
    float* out = (float*)d_out;

    float* X    = pool + OFF_X;
    float* PF   = pool + OFF_P0F;
    float* PB   = pool + OFF_P0B;
    float* O0   = pool + OFF_O0;
    float* HSA  = pool + OFF_HSA;
    float* HSB  = pool + OFF_HSB;
    float* HS1  = pool + OFF_HS1;
    float* HS2  = pool + OFF_HS2;
    float* Z    = pool + OFF_Z;
    float* HC3  = pool + OFF_HC3;
    float* WHHR  = pool + OFF_WHHR;
    float* WIHR0 = pool + OFF_WIHR0;
    float* WIHR1 = pool + OFF_WIHR1;
    float* BR    = pool + OFF_BR;
    float* FCP   = pool + OFF_FCP;
    unsigned* BARC = (unsigned*)(pool + OFF_BAR);
    float* BATT = pool + OFF_BATT;
    float* EA   = pool + OFF_EA;

    const int LN = L_SEQ * N_NODES;   // 17300
    const size_t W3 = PREP_W3, W6 = PREP_W6;

    // launch 0: all weight prep + HSA zero in one kernel
    prep_kernel<<<(int)((PREP_TOTAL + 255) / 256), 256>>>(
        Wih_l0f, Wih_l0b, Whh_l0f, Whh_l0b, Whh_l1f, Whh_l1b,
        Wih_l1f, Wih_l1b, b_l0f, b_l0b, b_l1f, b_l1b, pool);

    // launch 1: embedding
    embed_kernel<<<(int)((SZ_X + 255) / 256), 256>>>(tokens, emb, X);

    // launches 2,3: layer-0 input projections
    gemm128_kernel<1, 0><<<grid128(LN, G4), 256>>>(
        LN, G4, D_EMB, X, D_EMB, WIHR0 + 0 * W3, 300, BR + 0 * G4, 0, PF, G4);
    gemm128_kernel<1, 0><<<grid128(LN, G4), 256>>>(
        LN, G4, D_EMB, X, D_EMB, WIHR0 + 1 * W3, 300, BR + 1 * G4, 0, PB, G4);

    // launch 4: barrier counter zero; launch 5 (ncu-profiled): persistent scan l0
    memzero_kernel<<<1, 32>>>((float*)BARC, 1);
    {
        dim3 grid(LSTM_GX, LSTM_GY, 2);
        lstm_scan_kernel<<<grid, 256, SMEM_SCAN>>>(
            HSA, HSB, 0, 300,
            WHHR + 0 * W3, WHHR + 1 * W3,
            PF, PB, O0, BARC);
    }

    // layer-1 input projections
    gemm128_kernel<1, 0><<<grid128(LN, G4), 256>>>(
        LN, G4, 600, O0, 600, WIHR1 + 0 * W6, 600, BR + 2 * G4, 0, PF, G4);
    gemm128_kernel<1, 0><<<grid128(LN, G4), 256>>>(
        LN, G4, 600, O0, 600, WIHR1 + 1 * W6, 600, BR + 3 * G4, 0, PB, G4);

    // layer-1 scan (persistent)
    memzero_kernel<<<1, 32>>>((float*)BARC, 1);
    {
        dim3 grid(LSTM_GX, LSTM_GY, 2);
        lstm_scan_kernel<<<grid, 256, SMEM_SCAN>>>(
            HSA, HSB, 600, 900,
            WHHR + 2 * W3, WHHR + 3 * W3,
            PF, PB, nullptr, BARC);
    }
    // L_SEQ=50 (even): final h for both layers lands in HSA.

    // two gate+GAT stages
    run_gate_gat(HSA, HS1, gate_W, gate_U, W_gat, a_gat, adj, pool);
    run_gate_gat(HS1, HS2, gate_W, gate_U, W_gat, a_gat, adj, pool);

    // final head: FC1 via split-K partials + reduce(+tanh)
    zassemble_kernel<<<(N_NODES * G4 + 255) / 256, 256>>>(HS2, Z);
    {
        dim3 grid(9600 / XBN, (N_NODES + XBM - 1) / XBM, FC1_KS);  // (75,3,8)
        fc1_partial_kernel<<<grid, 256>>>(Z, FC1, FCP);
        fc1_reduce_kernel<<<(int)((SZ_HC + 255) / 256), 256>>>(FCP, HC3);
    }
    rows_dot_kernel<1><<<N_NODES, 256>>>(HC3, 9600, FC2, 9600, BATT);
    colsum_kernel<<<(G4 + 255) / 256, 256>>>(HS2, G4, N_NODES, nullptr,
                                             1.0f / (float)N_NODES, EA, G4);
    colsum_kernel<<<(G4 + 255) / 256, 256>>>(HS2, G4, N_NODES, BATT, 1.0f, EA + G4, G4);
    final_kernel<<<1, 256>>>(EA, Wlin, blin, out);
}

// round 13
// speedup vs baseline: 1.8197x; 1.0255x over previous
#include <cuda_runtime.h>
#include <math.h>

#define N_NODES 346
#define L_SEQ   50
#define D_EMB   300
#define H_HID   300
#define G4      1200   // 4*H

// ---------------------------------------------------------------------------
// Scratch pool (static device allocation — no cudaMalloc anywhere)
// ---------------------------------------------------------------------------
constexpr size_t A256(size_t x) { return (x + 255) & ~(size_t)255; }

constexpr size_t SZ_X   = (size_t)L_SEQ * N_NODES * D_EMB;
constexpr size_t SZ_P   = (size_t)L_SEQ * N_NODES * G4;
constexpr size_t SZ_O0  = (size_t)L_SEQ * N_NODES * 600;
constexpr size_t SZ_NG4 = (size_t)N_NODES * G4;

constexpr size_t OFF_X    = 0;
constexpr size_t OFF_P0F  = A256(OFF_X   + SZ_X);
constexpr size_t OFF_P0B  = A256(OFF_P0F + SZ_P);
constexpr size_t OFF_O0   = A256(OFF_P0B + SZ_P);
constexpr size_t OFF_HSA  = A256(OFF_O0  + SZ_O0);
constexpr size_t OFF_HSB  = A256(OFF_HSA + SZ_NG4);
constexpr size_t OFF_CAT  = A256(OFF_HSB + SZ_NG4);
constexpr size_t OFF_WH   = A256(OFF_CAT + (size_t)N_NODES * 2400);
constexpr size_t OFF_ATT  = A256(OFF_WH  + SZ_NG4);
constexpr size_t OFF_HS1  = A256(OFF_ATT + (size_t)N_NODES * N_NODES);
constexpr size_t OFF_HS2  = A256(OFF_HS1 + SZ_NG4);
constexpr size_t OFF_Z    = A256(OFF_HS2 + SZ_NG4);
constexpr size_t OFF_HC3  = A256(OFF_Z   + (size_t)N_NODES * 4800);
constexpr size_t OFF_WHHR  = A256(OFF_HC3  + (size_t)N_NODES * 9600);
constexpr size_t OFF_WIHR0 = A256(OFF_WHHR + 4 * (size_t)G4 * H_HID);
constexpr size_t OFF_WIHR1 = A256(OFF_WIHR0 + 2 * (size_t)G4 * 300);
constexpr size_t OFF_BR    = A256(OFF_WIHR1 + 2 * (size_t)G4 * 600);
constexpr size_t OFF_BAR  = A256(OFF_BR  + 4 * (size_t)G4);
constexpr size_t OFF_U    = A256(OFF_BAR + 64);
constexpr size_t OFF_V    = A256(OFF_U   + 512);
constexpr size_t OFF_S    = A256(OFF_V   + 32);
constexpr size_t OFF_E1   = A256(OFF_S   + 1280);
constexpr size_t OFF_E2   = A256(OFF_E1  + 512);
constexpr size_t OFF_BATT = A256(OFF_E2  + 512);
constexpr size_t OFF_EA   = A256(OFF_BATT + 512);
// FC1 split-K partials: 8 x [346][9600]
constexpr size_t SZ_HC   = (size_t)N_NODES * 9600;          // 3,321,600
constexpr size_t OFF_FCP  = A256(OFF_EA + 2560);
constexpr size_t POOL_SZ  = A256(OFF_FCP + 8 * SZ_HC);

__device__ float g_pool[POOL_SZ];

__device__ __forceinline__ float sigm_(float x) { return 1.0f / (1.0f + expf(-x)); }

// ---------------------------------------------------------------------------
// 64x64x16 fp32 GEMM core, double-buffered (R10 winner) — GAT GEMMs
// ---------------------------------------------------------------------------
#define BM 64
#define BN 64
#define BK 16
#define SPAD 68

template<int TB>
__device__ __forceinline__ void gemm_acc64(
    int M, int N, int K,
    const float* __restrict__ A, int lda,
    const float* __restrict__ B, int ldb,
    float (*As)[BK * SPAD], float (*Bs)[BK * SPAD], float acc[4][4],
    int m0, int n0, int tid, int tx, int ty)
{
#pragma unroll
    for (int i = 0; i < 4; i++)
#pragma unroll
        for (int j = 0; j < 4; j++) acc[i][j] = 0.0f;

    const int nt = (K + BK - 1) / BK;

#pragma unroll
    for (int i = 0; i < 4; i++) {
        int idx = tid + i * 256;
        int m = idx >> 4, k = idx & 15;
        int gm = m0 + m, gk = k;
        As[0][k * SPAD + m] = (gm < M && gk < K) ? __ldg(&A[(size_t)gm * lda + gk]) : 0.0f;
    }
    if (TB) {
#pragma unroll
        for (int i = 0; i < 4; i++) {
            int idx = tid + i * 256;
            int j = idx >> 4, k = idx & 15;
            int gj = n0 + j, gk = k;
            Bs[0][k * SPAD + j] = (gj < N && gk < K) ? __ldg(&B[(size_t)gj * ldb + gk]) : 0.0f;
        }
    } else {
#pragma unroll
        for (int i = 0; i < 4; i++) {
            int idx = tid + i * 256;
            int j = idx & 63, k = idx >> 6;
            int gj = n0 + j, gk = k;
            Bs[0][k * SPAD + j] = (gj < N && gk < K) ? __ldg(&B[(size_t)gk * ldb + gj]) : 0.0f;
        }
    }
    __syncthreads();

    float ra[4], rb[4];
    for (int t = 0; t < nt; t++) {
        const int cur = t & 1;
        const bool more = (t + 1 < nt);
        if (more) {
            int k0 = (t + 1) * BK;
#pragma unroll
            for (int i = 0; i < 4; i++) {
                int idx = tid + i * 256;
                int m = idx >> 4, k = idx & 15;
                int gm = m0 + m, gk = k0 + k;
                ra[i] = (gm < M && gk < K) ? __ldg(&A[(size_t)gm * lda + gk]) : 0.0f;
            }
            if (TB) {
#pragma unroll
                for (int i = 0; i < 4; i++) {
                    int idx = tid + i * 256;
                    int j = idx >> 4, k = idx & 15;
                    int gj = n0 + j, gk = k0 + k;
                    rb[i] = (gj < N && gk < K) ? __ldg(&B[(size_t)gj * ldb + gk]) : 0.0f;
                }
            } else {
#pragma unroll
                for (int i = 0; i < 4; i++) {
                    int idx = tid + i * 256;
                    int j = idx & 63, k = idx >> 6;
                    int gj = n0 + j, gk = k0 + k;
                    rb[i] = (gj < N && gk < K) ? __ldg(&B[(size_t)gk * ldb + gj]) : 0.0f;
                }
            }
        }
#pragma unroll
        for (int kk = 0; kk < BK; kk++) {
            float4 av = *reinterpret_cast<const float4*>(&As[cur][kk * SPAD + ty * 4]);
            float4 bv = *reinterpret_cast<const float4*>(&Bs[cur][kk * SPAD + tx * 4]);
            float a[4] = {av.x, av.y, av.z, av.w};
            float b[4] = {bv.x, bv.y, bv.z, bv.w};
#pragma unroll
            for (int i = 0; i < 4; i++)
#pragma unroll
                for (int j = 0; j < 4; j++)
                    acc[i][j] += a[i] * b[j];
        }
        if (more) {
            const int nxt = cur ^ 1;
#pragma unroll
            for (int i = 0; i < 4; i++) {
                int idx = tid + i * 256;
                int m = idx >> 4, k = idx & 15;
                As[nxt][k * SPAD + m] = ra[i];
            }
            if (TB) {
#pragma unroll
                for (int i = 0; i < 4; i++) {
                    int idx = tid + i * 256;
                    int j = idx >> 4, k = idx & 15;
                    Bs[nxt][k * SPAD + j] = rb[i];
                }
            } else {
#pragma unroll
                for (int i = 0; i < 4; i++) {
                    int idx = tid + i * 256;
                    int j = idx & 63, k = idx >> 6;
                    Bs[nxt][k * SPAD + j] = rb[i];
                }
            }
            __syncthreads();
        }
    }
}

template<int TB, int EPI>
__global__ void __launch_bounds__(256) gemm_kernel(
    int M, int N, int K,
    const float* __restrict__ A, int lda,
    const float* __restrict__ B, int ldb,
    const float* __restrict__ Dm, int ldd,
    float* __restrict__ C, int ldc)
{
    __shared__ float As[2][BK * SPAD], Bs[2][BK * SPAD];
    const int m0 = blockIdx.y * BM, n0 = blockIdx.x * BN;
    const int tid = threadIdx.x, tx = tid & 15, ty = tid >> 4;
    float acc[4][4];
    gemm_acc64<TB>(M, N, K, A, lda, B, ldb, As, Bs, acc, m0, n0, tid, tx, ty);

#pragma unroll
    for (int i = 0; i < 4; i++) {
        int gm = m0 + ty * 4 + i;
        if (gm >= M) continue;
#pragma unroll
        for (int j = 0; j < 4; j++) {
            int gn = n0 + tx * 4 + j;
            if (gn >= N) continue;
            float v = acc[i][j];
            if (Dm) v += (ldd == 0) ? Dm[gn] : Dm[(size_t)gm * ldd + gn];
            if (EPI == 1) v = tanhf(v);
            if (EPI == 2) v = (v > 0.0f) ? v : expm1f(v);
            C[(size_t)gm * ldc + gn] = v;
        }
    }
}

// ---------------------------------------------------------------------------
// 128x128x8 fp32 GEMM, 8x8 per thread, double-buffered (R10 winner)
// ---------------------------------------------------------------------------
#define XBM 128
#define XBN 128
#define XBK 8
#define XPAD 132

template<int TB, int EPI>
__global__ void __launch_bounds__(256) gemm128_kernel(
    int M, int N, int K,
    const float* __restrict__ A, int lda,
    const float* __restrict__ B, int ldb,
    const float* __restrict__ Dm, int ldd,
    float* __restrict__ C, int ldc)
{
    __shared__ float As[2][XBK * XPAD], Bs[2][XBK * XPAD];
    const int m0 = blockIdx.y * XBM, n0 = blockIdx.x * XBN;
    const int tid = threadIdx.x, tx = tid & 15, ty = tid >> 4;

    float acc[8][8];
#pragma unroll
    for (int i = 0; i < 8; i++)
#pragma unroll
        for (int j = 0; j < 8; j++) acc[i][j] = 0.0f;

    const int nt = (K + XBK - 1) / XBK;

#pragma unroll
    for (int l = 0; l < 4; l++) {
        int idx = tid + l * 256;
        int m = idx >> 3, k = idx & 7;
        int gm = m0 + m, gk = k;
        As[0][k * XPAD + m] = (gm < M && gk < K) ? __ldg(&A[(size_t)gm * lda + gk]) : 0.0f;
    }
    if (TB) {
#pragma unroll
        for (int l = 0; l < 4; l++) {
            int idx = tid + l * 256;
            int j = idx >> 3, k = idx & 7;
            int gj = n0 + j, gk = k;
            Bs[0][k * XPAD + j] = (gj < N && gk < K) ? __ldg(&B[(size_t)gj * ldb + gk]) : 0.0f;
        }
    } else {
#pragma unroll
        for (int l = 0; l < 4; l++) {
            int idx = tid + l * 256;
            int k = idx >> 7, j = idx & 127;
            int gj = n0 + j, gk = k;
            Bs[0][k * XPAD + j] = (gj < N && gk < K) ? __ldg(&B[(size_t)gk * ldb + gj]) : 0.0f;
        }
    }
    __syncthreads();

    float ra[4], rb[4];
    for (int t = 0; t < nt; t++) {
        const int cur = t & 1;
        const bool more = (t + 1 < nt);
        if (more) {
            int k0 = (t + 1) * XBK;
#pragma unroll
            for (int l = 0; l < 4; l++) {
                int idx = tid + l * 256;
                int m = idx >> 3, k = idx & 7;
                int gm = m0 + m, gk = k0 + k;
                ra[l] = (gm < M && gk < K) ? __ldg(&A[(size_t)gm * lda + gk]) : 0.0f;
            }
            if (TB) {
#pragma unroll
                for (int l = 0; l < 4; l++) {
                    int idx = tid + l * 256;
                    int j = idx >> 3, k = idx & 7;
                    int gj = n0 + j, gk = k0 + k;
                    rb[l] = (gj < N && gk < K) ? __ldg(&B[(size_t)gj * ldb + gk]) : 0.0f;
                }
            } else {
#pragma unroll
                for (int l = 0; l < 4; l++) {
                    int idx = tid + l * 256;
                    int k = idx >> 7, j = idx & 127;
                    int gj = n0 + j, gk = k0 + k;
                    rb[l] = (gj < N && gk < K) ? __ldg(&B[(size_t)gk * ldb + gj]) : 0.0f;
                }
            }
        }
#pragma unroll
        for (int kk = 0; kk < XBK; kk++) {
            float a[8], b[8];
            float4 a0 = *reinterpret_cast<const float4*>(&As[cur][kk * XPAD + ty * 8]);
            float4 a1 = *reinterpret_cast<const float4*>(&As[cur][kk * XPAD + ty * 8 + 4]);
            float4 b0 = *reinterpret_cast<const float4*>(&Bs[cur][kk * XPAD + tx * 8]);
            float4 b1 = *reinterpret_cast<const float4*>(&Bs[cur][kk * XPAD + tx * 8 + 4]);
            a[0]=a0.x; a[1]=a0.y; a[2]=a0.z; a[3]=a0.w;
            a[4]=a1.x; a[5]=a1.y; a[6]=a1.z; a[7]=a1.w;
            b[0]=b0.x; b[1]=b0.y; b[2]=b0.z; b[3]=b0.w;
            b[4]=b1.x; b[5]=b1.y; b[6]=b1.z; b[7]=b1.w;
#pragma unroll
            for (int i = 0; i < 8; i++)
#pragma unroll
                for (int j = 0; j < 8; j++)
                    acc[i][j] += a[i] * b[j];
        }
        if (more) {
            const int nxt = cur ^ 1;
#pragma unroll
            for (int l = 0; l < 4; l++) {
                int idx = tid + l * 256;
                int m = idx >> 3, k = idx & 7;
                As[nxt][k * XPAD + m] = ra[l];
            }
            if (TB) {
#pragma unroll
                for (int l = 0; l < 4; l++) {
                    int idx = tid + l * 256;
                    int j = idx >> 3, k = idx & 7;
                    Bs[nxt][k * XPAD + j] = rb[l];
                }
            } else {
#pragma unroll
                for (int l = 0; l < 4; l++) {
                    int idx = tid + l * 256;
                    int k = idx >> 7, j = idx & 127;
                    Bs[nxt][k * XPAD + j] = rb[l];
                }
            }
            __syncthreads();
        }
    }

#pragma unroll
    for (int i = 0; i < 8; i++) {
        int gm = m0 + ty * 8 + i;
        if (gm >= M) continue;
#pragma unroll
        for (int j = 0; j < 8; j++) {
            int gn = n0 + tx * 8 + j;
            if (gn >= N) continue;
            float v = acc[i][j];
            if (Dm) v += (ldd == 0) ? Dm[gn] : Dm[(size_t)gm * ldd + gn];
            if (EPI == 1) v = tanhf(v);
            if (EPI == 2) v = (v > 0.0f) ? v : expm1f(v);
            C[(size_t)gm * ldc + gn] = v;
        }
    }
}

// ---------------------------------------------------------------------------
// FC1 split-K: partial GEMM (K chunk 600 per z-slice) + reduction with tanh.
// ---------------------------------------------------------------------------
#define FC1_KS 8
#define FC1_KC 600

__global__ void __launch_bounds__(256) fc1_partial_kernel(
    const float* __restrict__ A,     // Z, lda 4800
    const float* __restrict__ B,     // FC1, ldb 9600
    float* __restrict__ P)           // partials [8][346][9600]
{
    __shared__ float As[2][XBK * XPAD], Bs[2][XBK * XPAD];
    const int M = N_NODES;
    const int lda = 4800, ldb = 9600;
    const int kbase = blockIdx.z * FC1_KC;
    const int m0 = blockIdx.y * XBM, n0 = blockIdx.x * XBN;
    const int tid = threadIdx.x, tx = tid & 15, ty = tid >> 4;
    float* C = P + (size_t)blockIdx.z * SZ_HC;

    float acc[8][8];
#pragma unroll
    for (int i = 0; i < 8; i++)
#pragma unroll
        for (int j = 0; j < 8; j++) acc[i][j] = 0.0f;

    const int nt = FC1_KC / XBK;   // 75

#pragma unroll
    for (int l = 0; l < 4; l++) {
        int idx = tid + l * 256;
        int m = idx >> 3, k = idx & 7;
        int gm = m0 + m;
        As[0][k * XPAD + m] = (gm < M) ? __ldg(&A[(size_t)gm * lda + kbase + k]) : 0.0f;
    }
#pragma unroll
    for (int l = 0; l < 4; l++) {
        int idx = tid + l * 256;
        int k = idx >> 7, j = idx & 127;
        int gj = n0 + j;
        Bs[0][k * XPAD + j] = __ldg(&B[(size_t)(kbase + k) * ldb + gj]);
    }
    __syncthreads();

    float ra[4], rb[4];
    for (int t = 0; t < nt; t++) {
        const int cur = t & 1;
        const bool more = (t + 1 < nt);
        if (more) {
            int k0 = kbase + (t + 1) * XBK;
#pragma unroll
            for (int l = 0; l < 4; l++) {
                int idx = tid + l * 256;
                int m = idx >> 3, k = idx & 7;
                int gm = m0 + m;
                ra[l] = (gm < M) ? __ldg(&A[(size_t)gm * lda + k0 + k]) : 0.0f;
            }
#pragma unroll
            for (int l = 0; l < 4; l++) {
                int idx = tid + l * 256;
                int k = idx >> 7, j = idx & 127;
                int gj = n0 + j;
                rb[l] = __ldg(&B[(size_t)(k0 + k) * ldb + gj]);
            }
        }
#pragma unroll
        for (int kk = 0; kk < XBK; kk++) {
            float a[8], b[8];
            float4 a0 = *reinterpret_cast<const float4*>(&As[cur][kk * XPAD + ty * 8]);
            float4 a1 = *reinterpret_cast<const float4*>(&As[cur][kk * XPAD + ty * 8 + 4]);
            float4 b0 = *reinterpret_cast<const float4*>(&Bs[cur][kk * XPAD + tx * 8]);
            float4 b1 = *reinterpret_cast<const float4*>(&Bs[cur][kk * XPAD + tx * 8 + 4]);
            a[0]=a0.x; a[1]=a0.y; a[2]=a0.z; a[3]=a0.w;
            a[4]=a1.x; a[5]=a1.y; a[6]=a1.z; a[7]=a1.w;
            b[0]=b0.x; b[1]=b0.y; b[2]=b0.z; b[3]=b0.w;
            b[4]=b1.x; b[5]=b1.y; b[6]=b1.z; b[7]=b1.w;
#pragma unroll
            for (int i = 0; i < 8; i++)
#pragma unroll
                for (int j = 0; j < 8; j++)
                    acc[i][j] += a[i] * b[j];
        }
        if (more) {
            const int nxt = cur ^ 1;
#pragma unroll
            for (int l = 0; l < 4; l++) {
                int idx = tid + l * 256;
                int m = idx >> 3, k = idx & 7;
                As[nxt][k * XPAD + m] = ra[l];
            }
#pragma unroll
            for (int l = 0; l < 4; l++) {
                int idx = tid + l * 256;
                int k = idx >> 7, j = idx & 127;
                Bs[nxt][k * XPAD + j] = rb[l];
            }
            __syncthreads();
        }
    }

#pragma unroll
    for (int i = 0; i < 8; i++) {
        int gm = m0 + ty * 8 + i;
        if (gm >= M) continue;
#pragma unroll
        for (int j = 0; j < 8; j++) {
            int gn = n0 + tx * 8 + j;
            C[(size_t)gm * 9600 + gn] = acc[i][j];
        }
    }
}

__global__ void fc1_reduce_kernel(const float* __restrict__ P, float* __restrict__ out)
{
    size_t idx = (size_t)blockIdx.x * blockDim.x + threadIdx.x;
    if (idx >= SZ_HC) return;
    float s = 0.0f;
#pragma unroll
    for (int z = 0; z < FC1_KS; z++) s += P[(size_t)z * SZ_HC + idx];
    out[idx] = tanhf(s);
}

// ---------------------------------------------------------------------------
// Persistent LSTM scan — rebalanced: BN=48, grid (25,6,2)=300 blocks,
// 192 threads (12 N-threads x 16 M-threads, 4x4 per thread), ~72KB smem,
// all co-resident at <=3 blocks/SM. Whh resident in smem; c in registers.
// ---------------------------------------------------------------------------
#define LBN 48
#define LSPD 52     // 48 + 4 pad
#define LTHREADS 192
constexpr int LSTM_GX = G4 / LBN;                  // 25
constexpr int LSTM_GY = (N_NODES + BM - 1) / BM;   // 6
constexpr unsigned LSTM_BLOCKS = LSTM_GX * LSTM_GY * 2;  // 300
constexpr int BS_ROWS = 304;
constexpr size_t SMEM_SCAN = (size_t)(BS_ROWS * LSPD + 2 * BK * SPAD) * 4;  // 71936 B

__global__ void __launch_bounds__(LTHREADS) lstm_scan_kernel(
    float* __restrict__ hsA, float* __restrict__ hsB,
    int hcol_f, int hcol_b,
    const float* __restrict__ Whh_rf, const float* __restrict__ Whh_rb,
    const float* __restrict__ Pf, const float* __restrict__ Pb,
    float* __restrict__ outbuf,
    unsigned* __restrict__ bar)
{
    extern __shared__ float smem[];
    float* Bres = smem;                       // [BS_ROWS][LSPD]
    float* As   = smem + BS_ROWS * LSPD;      // [2][BK*SPAD]

    const int z = blockIdx.z;
    const int hcol = z ? hcol_b : hcol_f;
    const float* Bw = z ? Whh_rb : Whh_rf;
    const float* Pbase = z ? Pb : Pf;

    const int m0 = blockIdx.y * BM, n0 = blockIdx.x * LBN;
    const int tid = threadIdx.x;
    const int tx = tid % 12, ty = tid / 12;   // ty in [0,16)

    // Resident B tile: Bres[k*LSPD + j] = Whh_r[n0+j][k], zero-pad k>=300
    for (int idx = tid; idx < LBN * BS_ROWS; idx += LTHREADS) {
        int j = idx / BS_ROWS, k = idx % BS_ROWS;
        int gj = n0 + j;
        Bres[k * LSPD + j] = (gj < G4 && k < H_HID) ? __ldg(&Bw[(size_t)gj * H_HID + k]) : 0.0f;
    }

    const int r0 = n0 + tx * 4;               // gate-column group (multiple of 4)
    const int ju = r0 >> 2;                   // hidden unit
    float c_reg[4] = {0.0f, 0.0f, 0.0f, 0.0f};

    __syncthreads();

    const int nt = (H_HID + BK - 1) / BK;     // 19

    for (int t = 0; t < L_SEQ; t++) {
        const float* hin  = (t & 1) ? hsB : hsA;
        float*       hout = (t & 1) ? hsA : hsB;
        const float* A = hin + hcol;

        // prologue: A tile 0 (64 x 16 = 1024 elems)
        for (int idx = tid; idx < BM * BK; idx += LTHREADS) {
            int m = idx >> 4, k = idx & 15;
            int gm = m0 + m;
            As[k * SPAD + m] = (gm < N_NODES) ? __ldg(&A[(size_t)gm * G4 + k]) : 0.0f;
        }
        __syncthreads();

        float acc[4][4];
#pragma unroll
        for (int i = 0; i < 4; i++)
#pragma unroll
            for (int j = 0; j < 4; j++) acc[i][j] = 0.0f;

        float ra[6];
        for (int kt = 0; kt < nt; kt++) {
            const int cur = kt & 1;
            const bool more = (kt + 1 < nt);
            if (more) {
                int k0 = (kt + 1) * BK;
#pragma unroll
                for (int i = 0; i < 6; i++) {
                    int idx = tid + i * LTHREADS;
                    if (idx < BM * BK) {
                        int m = idx >> 4, k = idx & 15;
                        int gm = m0 + m, gk = k0 + k;
                        ra[i] = (gm < N_NODES && gk < H_HID) ? __ldg(&A[(size_t)gm * G4 + gk]) : 0.0f;
                    }
                }
            }
#pragma unroll
            for (int kk = 0; kk < BK; kk++) {
                float4 av = *reinterpret_cast<const float4*>(&As[cur * (BK * SPAD) + kk * SPAD + ty * 4]);
                float4 bv = *reinterpret_cast<const float4*>(&Bres[(kt * BK + kk) * LSPD + tx * 4]);
                float a[4] = {av.x, av.y, av.z, av.w};
                float b[4] = {bv.x, bv.y, bv.z, bv.w};
#pragma unroll
                for (int i = 0; i < 4; i++)
#pragma unroll
                    for (int j = 0; j < 4; j++)
                        acc[i][j] += a[i] * b[j];
            }
            if (more) {
                const int nxt = cur ^ 1;
#pragma unroll
                for (int i = 0; i < 6; i++) {
                    int idx = tid + i * LTHREADS;
                    if (idx < BM * BK) {
                        int m = idx >> 4, k = idx & 15;
                        As[nxt * (BK * SPAD) + k * SPAD + m] = ra[i];
                    }
                }
                __syncthreads();
            }
        }

        // epilogue: cell update (c in registers), h to global
        {
            const size_t toff = (size_t)(z ? (L_SEQ - 1 - t) : t) * N_NODES * G4;
            const float* P = Pbase + toff;
#pragma unroll
            for (int i = 0; i < 4; i++) {
                int gm = m0 + ty * 4 + i;
                if (gm >= N_NODES) continue;
                float4 p = *reinterpret_cast<const float4*>(P + (size_t)gm * G4 + r0);
                float gi = acc[i][0] + p.x;
                float gf = acc[i][1] + p.y;
                float gg = acc[i][2] + p.z;
                float go = acc[i][3] + p.w;
                float cn = sigm_(gf) * c_reg[i] + sigm_(gi) * tanhf(gg);
                float h  = sigm_(go) * tanhf(cn);
                c_reg[i] = cn;
                hout[(size_t)gm * G4 + hcol + ju] = h;
                if (outbuf) {
                    int tt = z ? (L_SEQ - 1 - t) : t;
                    outbuf[(size_t)tt * N_NODES * 600 + (size_t)gm * 600 + z * H_HID + ju] = h;
                }
            }
        }

        // grid barrier (skip after final step)
        if (t + 1 < L_SEQ) {
            __threadfence();
            __syncthreads();
            if (tid == 0) {
                atomicAdd(bar, 1u);
                const unsigned target = LSTM_BLOCKS * (unsigned)(t + 1);
                const volatile unsigned* vb = bar;
                while (*vb < target) __nanosleep(64);
                __threadfence();
            }
            __syncthreads();
        }
    }
}

// ---------------------------------------------------------------------------
// prep: all weight reorders + bias reorders + HSA zero in ONE kernel
// ---------------------------------------------------------------------------
constexpr size_t PREP_W3 = (size_t)G4 * 300;
constexpr size_t PREP_W6 = (size_t)G4 * 600;
constexpr size_t PREP_B0 = 6 * PREP_W3;
constexpr size_t PREP_B1 = PREP_B0 + 2 * PREP_W6;
constexpr size_t PREP_B2 = PREP_B1 + 4 * (size_t)G4;
constexpr size_t PREP_TOTAL = PREP_B2 + SZ_NG4;

__device__ __forceinline__ void reo_(const float* in, float* out, size_t idx, int K) {
    int r = (int)(idx / K), k = (int)(idx % K);
    int j = r >> 2, g = r & 3;
    out[(size_t)r * K + k] = in[(size_t)(g * H_HID + j) * K + k];
}

__global__ void prep_kernel(
    const float* __restrict__ Wih_l0f, const float* __restrict__ Wih_l0b,
    const float* __restrict__ Whh_l0f, const float* __restrict__ Whh_l0b,
    const float* __restrict__ Whh_l1f, const float* __restrict__ Whh_l1b,
    const float* __restrict__ Wih_l1f, const float* __restrict__ Wih_l1b,
    const float* __restrict__ b_l0f, const float* __restrict__ b_l0b,
    const float* __restrict__ b_l1f, const float* __restrict__ b_l1b,
    float* __restrict__ pool)
{
    size_t i = (size_t)blockIdx.x * blockDim.x + threadIdx.x;
    if (i >= PREP_TOTAL) return;

    float* WIHR0 = pool + OFF_WIHR0;
    float* WIHR1 = pool + OFF_WIHR1;
    float* WHHR  = pool + OFF_WHHR;
    float* BR    = pool + OFF_BR;

    if (i < PREP_B0) {
        int seg = (int)(i / PREP_W3);
        size_t l = i % PREP_W3;
        switch (seg) {
            case 0: reo_(Wih_l0f, WIHR0 + 0 * PREP_W3, l, 300); break;
            case 1: reo_(Wih_l0b, WIHR0 + 1 * PREP_W3, l, 300); break;
            case 2: reo_(Whh_l0f, WHHR + 0 * PREP_W3, l, 300); break;
            case 3: reo_(Whh_l0b, WHHR + 1 * PREP_W3, l, 300); break;
            case 4: reo_(Whh_l1f, WHHR + 2 * PREP_W3, l, 300); break;
            default: reo_(Whh_l1b, WHHR + 3 * PREP_W3, l, 300); break;
        }
    } else if (i < PREP_B1) {
        size_t l = i - PREP_B0;
        if (l < PREP_W6) reo_(Wih_l1f, WIHR1 + 0 * PREP_W6, l, 600);
        else             reo_(Wih_l1b, WIHR1 + 1 * PREP_W6, l - PREP_W6, 600);
    } else if (i < PREP_B2) {
        size_t l = i - PREP_B1;
        int which = (int)(l / G4);
        int r = (int)(l % G4);
        int j = r >> 2, g = r & 3;
        const float* src = (which == 0) ? b_l0f : (which == 1) ? b_l0b : (which == 2) ? b_l1f : b_l1b;
        BR[(size_t)which * G4 + r] = src[g * H_HID + j];
    } else {
        pool[OFF_HSA + (i - PREP_B2)] = 0.0f;
    }
}

__global__ void memzero_kernel(float* p, int n)
{
    int i = blockIdx.x * blockDim.x + threadIdx.x;
    if (i < n) p[i] = 0.0f;
}

__global__ void embed_kernel(const int* __restrict__ tok,
                             const float* __restrict__ emb,
                             float* __restrict__ x)
{
    size_t idx = (size_t)blockIdx.x * blockDim.x + threadIdx.x;
    const size_t total = (size_t)L_SEQ * N_NODES * D_EMB;
    if (idx >= total) return;
    int d = (int)(idx % D_EMB);
    size_t r = idx / D_EMB;
    int n = (int)(r % N_NODES);
    int t = (int)(r / N_NODES);
    int tv = tok[n * L_SEQ + t];
    x[idx] = emb[(size_t)tv * D_EMB + d];
}

// out[row] = epi( dot(A[row,:K], w) )
template<int EPI>
__global__ void rows_dot_kernel(const float* __restrict__ A, int lda,
                                const float* __restrict__ w, int K,
                                float* __restrict__ out)
{
    __shared__ float red[8];
    const float* a = A + (size_t)blockIdx.x * lda;
    float s = 0.0f;
    for (int k = threadIdx.x; k < K; k += blockDim.x) s += a[k] * w[k];
#pragma unroll
    for (int o = 16; o > 0; o >>= 1) s += __shfl_down_sync(0xffffffffu, s, o);
    if ((threadIdx.x & 31) == 0) red[threadIdx.x >> 5] = s;
    __syncthreads();
    if (threadIdx.x == 0) {
        float t = 0.0f;
        int nw = blockDim.x >> 5;
        for (int i = 0; i < nw; i++) t += red[i];
        if (EPI == 1) t = tanhf(t);
        out[blockIdx.x] = t;
    }
}

// two dots per row in one pass (E1 = A.w1, E2 = A.w2)
__global__ void rows_dot2_kernel(const float* __restrict__ A, int lda,
                                 const float* __restrict__ w1,
                                 const float* __restrict__ w2, int K,
                                 float* __restrict__ out1, float* __restrict__ out2)
{
    __shared__ float red1[8], red2[8];
    const float* a = A + (size_t)blockIdx.x * lda;
    float s1 = 0.0f, s2 = 0.0f;
    for (int k = threadIdx.x; k < K; k += blockDim.x) {
        float v = a[k];
        s1 += v * w1[k];
        s2 += v * w2[k];
    }
#pragma unroll
    for (int o = 16; o > 0; o >>= 1) {
        s1 += __shfl_down_sync(0xffffffffu, s1, o);
        s2 += __shfl_down_sync(0xffffffffu, s2, o);
    }
    if ((threadIdx.x & 31) == 0) { red1[threadIdx.x >> 5] = s1; red2[threadIdx.x >> 5] = s2; }
    __syncthreads();
    if (threadIdx.x == 0) {
        float t1 = 0.0f, t2 = 0.0f;
        int nw = blockDim.x >> 5;
        for (int i = 0; i < nw; i++) { t1 += red1[i]; t2 += red2[i]; }
        out1[blockIdx.x] = t1;
        out2[blockIdx.x] = t2;
    }
}

// out[j] = scale * sum_n (w ? w[n] : 1) * A[n*lda + j]
__global__ void colsum_kernel(const float* __restrict__ A, int lda, int rows,
                              const float* __restrict__ w, float scale,
                              float* __restrict__ out, int ncols)
{
    int j = blockIdx.x * blockDim.x + threadIdx.x;
    if (j >= ncols) return;
    float s = 0.0f;
#pragma unroll 4
    for (int n = 0; n < rows; n++) {
        float v = A[(size_t)n * lda + j];
        s += w ? w[n] * v : v;
    }
    out[j] = s * scale;
}

// cat[n] = [ h[n] , gate(h)[n] ]
__global__ void gate_cat_kernel(const float* __restrict__ h,
                                const float* __restrict__ u,
                                const float* __restrict__ vsc,
                                const float* __restrict__ s,
                                float* __restrict__ cat)
{
    int idx = blockIdx.x * blockDim.x + threadIdx.x;
    if (idx >= N_NODES * G4) return;
    int n = idx / G4, j = idx % G4;
    float hv = h[(size_t)n * G4 + j];
    float h0 = h[j];
    float val;
    if (n == 0) {
        val = h0;
    } else {
        float g = sigm_(u[n] + vsc[0]);
        val = g * s[j] + (1.0f - g) * ((float)(N_NODES - 1) * h0);
    }
    cat[(size_t)n * 2400 + j] = hv;
    cat[(size_t)n * 2400 + 1200 + j] = val;
}

__global__ void att_softmax_kernel(const float* __restrict__ e1,
                                   const float* __restrict__ e2,
                                   const int* __restrict__ adj,
                                   float* __restrict__ att)
{
    __shared__ float warpred[4];
    __shared__ float s_max, s_sum;
    int i = blockIdx.x;
    float ei = e1[i];

    float mx = -3.4e38f;
    for (int j = threadIdx.x; j < N_NODES; j += blockDim.x) {
        float v = ei + e2[j];
        v = (v > 0.0f) ? v : 0.01f * v;
        if (adj[(size_t)i * N_NODES + j] <= 0) v = -9.0e15f;
        mx = fmaxf(mx, v);
    }
#pragma unroll
    for (int o = 16; o > 0; o >>= 1) mx = fmaxf(mx, __shfl_down_sync(0xffffffffu, mx, o));
    if ((threadIdx.x & 31) == 0) warpred[threadIdx.x >> 5] = mx;
    __syncthreads();
    if (threadIdx.x == 0) {
        float m2 = warpred[0];
        int nw = blockDim.x >> 5;
        for (int k = 1; k < nw; k++) m2 = fmaxf(m2, warpred[k]);
        s_max = m2;
    }
    __syncthreads();
    float smax = s_max;

    float sum = 0.0f;
    for (int j = threadIdx.x; j < N_NODES; j += blockDim.x) {
        float v = ei + e2[j];
        v = (v > 0.0f) ? v : 0.01f * v;
        if (adj[(size_t)i * N_NODES + j] <= 0) v = -9.0e15f;
        sum += expf(v - smax);
    }
#pragma unroll
    for (int o = 16; o > 0; o >>= 1) sum += __shfl_down_sync(0xffffffffu, sum, o);
    if ((threadIdx.x & 31) == 0) warpred[threadIdx.x >> 5] = sum;
    __syncthreads();
    if (threadIdx.x == 0) {
        float t = 0.0f;
        int nw = blockDim.x >> 5;
        for (int k = 0; k < nw; k++) t += warpred[k];
        s_sum = t;
    }
    __syncthreads();
    float inv = 1.0f / s_sum;

    for (int j = threadIdx.x; j < N_NODES; j += blockDim.x) {
        float v = ei + e2[j];
        v = (v > 0.0f) ? v : 0.01f * v;
        if (adj[(size_t)i * N_NODES + j] <= 0) v = -9.0e15f;
        att[(size_t)i * N_NODES + j] = expf(v - smax) * inv;
    }
}

// Z[n] = [hc, hs2[n], hc*hs2[n], hc - hs2[n]],  hc = hs2[0]
__global__ void zassemble_kernel(const float* __restrict__ h2, float* __restrict__ Z)
{
    int idx = blockIdx.x * blockDim.x + threadIdx.x;
    if (idx >= N_NODES * G4) return;
    int n = idx / G4, j = idx % G4;
    float a = h2[j];
    float b = h2[(size_t)n * G4 + j];
    size_t base = (size_t)n * 4800;
    Z[base + j]        = a;
    Z[base + 1200 + j] = b;
    Z[base + 2400 + j] = a * b;
    Z[base + 3600 + j] = a - b;
}

__global__ void final_kernel(const float* __restrict__ ea,
                             const float* __restrict__ Wlin,
                             const float* __restrict__ blin,
                             float* __restrict__ out)
{
    __shared__ float r0[8], r1[8];
    float s0 = 0.0f, s1 = 0.0f;
    for (int j = threadIdx.x; j < 2400; j += blockDim.x) {
        float e = ea[j];
        s0 += e * Wlin[j];
        s1 += e * Wlin[2400 + j];
    }
#pragma unroll
    for (int o = 16; o > 0; o >>= 1) {
        s0 += __shfl_down_sync(0xffffffffu, s0, o);
        s1 += __shfl_down_sync(0xffffffffu, s1, o);
    }
    if ((threadIdx.x & 31) == 0) { r0[threadIdx.x >> 5] = s0; r1[threadIdx.x >> 5] = s1; }
    __syncthreads();
    if (threadIdx.x == 0) {
        float l0 = 0.0f, l1 = 0.0f;
        int nw = blockDim.x >> 5;
        for (int i = 0; i < nw; i++) { l0 += r0[i]; l1 += r1[i]; }
        l0 += blin[0]; l1 += blin[1];
        float m = fmaxf(l0, l1);
        float e0 = expf(l0 - m), e1v = expf(l1 - m);
        float inv = 1.0f / (e0 + e1v);
        out[0] = e0 * inv;
        out[1] = e1v * inv;
    }
}

// ---------------------------------------------------------------------------
// Host orchestration
// ---------------------------------------------------------------------------
static inline dim3 grid64(int M, int N)  { return dim3((N + BN - 1) / BN, (M + BM - 1) / BM); }
static inline dim3 grid128(int M, int N) { return dim3((N + XBN - 1) / XBN, (M + XBM - 1) / XBM); }

static void run_gate_gat(const float* h_in, float* h_out,
                         const float* gate_W, const float* gate_U,
                         const float* W_gat, const float* a_gat,
                         const int* adj, float* pool)
{
    float* U   = pool + OFF_U;
    float* Vb  = pool + OFF_V;
    float* S   = pool + OFF_S;
    float* CAT = pool + OFF_CAT;
    float* WHp = pool + OFF_WH;
    float* E1  = pool + OFF_E1;
    float* E2  = pool + OFF_E2;
    float* ATT = pool + OFF_ATT;

    rows_dot_kernel<0><<<N_NODES, 256>>>(h_in, G4, gate_W, G4, U);
    rows_dot_kernel<0><<<1, 256>>>(h_in, G4, gate_U, G4, Vb);
    colsum_kernel<<<(G4 + 255) / 256, 256>>>(h_in + G4, G4, N_NODES - 1, nullptr, 1.0f, S, G4);
    gate_cat_kernel<<<(N_NODES * G4 + 255) / 256, 256>>>(h_in, U, Vb, S, CAT);

    gemm_kernel<0, 0><<<grid64(N_NODES, G4), 256>>>(
        N_NODES, G4, 2400, CAT, 2400, W_gat, G4, nullptr, 0, WHp, G4);
    rows_dot2_kernel<<<N_NODES, 256>>>(WHp, G4, a_gat, a_gat + G4, G4, E1, E2);
    att_softmax_kernel<<<N_NODES, 128>>>(E1, E2, adj, ATT);
    gemm_kernel<0, 2><<<grid64(N_NODES, G4), 256>>>(
        N_NODES, G4, N_NODES, ATT, N_NODES, WHp, G4, nullptr, 0, h_out, G4);
}

extern "C" void kernel_launch(void* const* d_in, const int* in_sizes, int n_in,
                              void* d_out, int out_size)
{
    (void)in_sizes; (void)n_in; (void)out_size;

    float* pool = nullptr;
    cudaGetSymbolAddress((void**)&pool, g_pool);

    static bool attr_done = false;
    if (!attr_done) {
        cudaFuncSetAttribute(lstm_scan_kernel,
                             cudaFuncAttributeMaxDynamicSharedMemorySize, (int)SMEM_SCAN);
        attr_done = true;
    }

    const int*   tokens  = (const int*)d_in[0];
    const int*   adj     = (const int*)d_in[1];
    const float* emb     = (const float*)d_in[2];
    const float* Wih_l0f = (const float*)d_in[3];
    const float* Whh_l0f = (const float*)d_in[4];
    const float* b_l0f   = (const float*)d_in[5];
    const float* Wih_l0b = (const float*)d_in[6];
    const float* Whh_l0b = (const float*)d_in[7];
    const float* b_l0b   = (const float*)d_in[8];
    const float* Wih_l1f = (const float*)d_in[9];
    const float* Whh_l1f = (const float*)d_in[10];
    const float* b_l1f   = (const float*)d_in[11];
    const float* Wih_l1b = (const float*)d_in[12];
    const float* Whh_l1b = (const float*)d_in[13];
    const float* b_l1b   = (const float*)d_in[14];
    const float* W_gat   = (const float*)d_in[15];
    const float* a_gat   = (const float*)d_in[16];
    const float* gate_W  = (const float*)d_in[17];
    const float* gate_U  = (const float*)d_in[18];
    const float* FC1     = (const float*)d_in[19];
    const float* FC2     = (const float*)d_in[20];
    const float* Wlin    = (const float*)d_in[21];
    const float* blin    = (const float*)d_in[22];
    float* out = (float*)d_out;

    float* X    = pool + OFF_X;
    float* PF   = pool + OFF_P0F;
    float* PB   = pool + OFF_P0B;
    float* O0   = pool + OFF_O0;
    float* HSA  = pool + OFF_HSA;
    float* HSB  = pool + OFF_HSB;
    float* HS1  = pool + OFF_HS1;
    float* HS2  = pool + OFF_HS2;
    float* Z    = pool + OFF_Z;
    float* HC3  = pool + OFF_HC3;
    float* WHHR  = pool + OFF_WHHR;
    float* WIHR0 = pool + OFF_WIHR0;
    float* WIHR1 = pool + OFF_WIHR1;
    float* BR    = pool + OFF_BR;
    float* FCP   = pool + OFF_FCP;
    unsigned* BARC = (unsigned*)(pool + OFF_BAR);
    float* BATT = pool + OFF_BATT;
    float* EA   = pool + OFF_EA;

    const int LN = L_SEQ * N_NODES;   // 17300
    const size_t W3 = PREP_W3, W6 = PREP_W6;

    // launch 0: all weight prep + HSA zero in one kernel
    prep_kernel<<<(int)((PREP_TOTAL + 255) / 256), 256>>>(
        Wih_l0f, Wih_l0b, Whh_l0f, Whh_l0b, Whh_l1f, Whh_l1b,
        Wih_l1f, Wih_l1b, b_l0f, b_l0b, b_l1f, b_l1b, pool);

    // launch 1: embedding
    embed_kernel<<<(int)((SZ_X + 255) / 256), 256>>>(tokens, emb, X);

    // launches 2,3: layer-0 input projections
    gemm128_kernel<1, 0><<<grid128(LN, G4), 256>>>(
        LN, G4, D_EMB, X, D_EMB, WIHR0 + 0 * W3, 300, BR + 0 * G4, 0, PF, G4);
    gemm128_kernel<1, 0><<<grid128(LN, G4), 256>>>(
        LN, G4, D_EMB, X, D_EMB, WIHR0 + 1 * W3, 300, BR + 1 * G4, 0, PB, G4);

    // launch 4: barrier zero; launch 5 (ncu-profiled): persistent scan l0
    memzero_kernel<<<1, 32>>>((float*)BARC, 1);
    {
        dim3 grid(LSTM_GX, LSTM_GY, 2);
        lstm_scan_kernel<<<grid, LTHREADS, SMEM_SCAN>>>(
            HSA, HSB, 0, 300,
            WHHR + 0 * W3, WHHR + 1 * W3,
            PF, PB, O0, BARC);
    }

    // layer-1 input projections
    gemm128_kernel<1, 0><<<grid128(LN, G4), 256>>>(
        LN, G4, 600, O0, 600, WIHR1 + 0 * W6, 600, BR + 2 * G4, 0, PF, G4);
    gemm128_kernel<1, 0><<<grid128(LN, G4), 256>>>(
        LN, G4, 600, O0, 600, WIHR1 + 1 * W6, 600, BR + 3 * G4, 0, PB, G4);

    // layer-1 scan (persistent)
    memzero_kernel<<<1, 32>>>((float*)BARC, 1);
    {
        dim3 grid(LSTM_GX, LSTM_GY, 2);
        lstm_scan_kernel<<<grid, LTHREADS, SMEM_SCAN>>>(
            HSA, HSB, 600, 900,
            WHHR + 2 * W3, WHHR + 3 * W3,
            PF, PB, nullptr, BARC);
    }
    // L_SEQ=50 (even): final h for both layers lands in HSA.

    // two gate+GAT stages
    run_gate_gat(HSA, HS1, gate_W, gate_U, W_gat, a_gat, adj, pool);
    run_gate_gat(HS1, HS2, gate_W, gate_U, W_gat, a_gat, adj, pool);

    // final head: FC1 via split-K partials + reduce(+tanh)
    zassemble_kernel<<<(N_NODES * G4 + 255) / 256, 256>>>(HS2, Z);
    {
        dim3 grid(9600 / XBN, (N_NODES + XBM - 1) / XBM, FC1_KS);  // (75,3,8)
        fc1_partial_kernel<<<grid, 256>>>(Z, FC1, FCP);
        fc1_reduce_kernel<<<(int)((SZ_HC + 255) / 256), 256>>>(FCP, HC3);
    }
    rows_dot_kernel<1><<<N_NODES, 256>>>(HC3, 9600, FC2, 9600, BATT);
    colsum_kernel<<<(G4 + 255) / 256, 256>>>(HS2, G4, N_NODES, nullptr,
                                             1.0f / (float)N_NODES, EA, G4);
    colsum_kernel<<<(G4 + 255) / 256, 256>>>(HS2, G4, N_NODES, BATT, 1.0f, EA + G4, G4);
    final_kernel<<<1, 256>>>(EA, Wlin, blin, out);
}

// round 15
// speedup vs baseline: 1.8412x; 1.0118x over previous
#include <cuda_runtime.h>
#include <math.h>

#define N_NODES 346
#define L_SEQ   50
#define D_EMB   300
#define H_HID   300
#define G4      1200   // 4*H

// ---------------------------------------------------------------------------
// Scratch pool (static device allocation — no cudaMalloc anywhere)
// ---------------------------------------------------------------------------
constexpr size_t A256(size_t x) { return (x + 255) & ~(size_t)255; }

constexpr size_t SZ_X   = (size_t)L_SEQ * N_NODES * D_EMB;
constexpr size_t SZ_P   = (size_t)L_SEQ * N_NODES * G4;
constexpr size_t SZ_O0  = (size_t)L_SEQ * N_NODES * 600;
constexpr size_t SZ_NG4 = (size_t)N_NODES * G4;

constexpr size_t OFF_X    = 0;
constexpr size_t OFF_P0F  = A256(OFF_X   + SZ_X);
constexpr size_t OFF_P0B  = A256(OFF_P0F + SZ_P);
constexpr size_t OFF_O0   = A256(OFF_P0B + SZ_P);
constexpr size_t OFF_HSA  = A256(OFF_O0  + SZ_O0);
constexpr size_t OFF_HSB  = A256(OFF_HSA + SZ_NG4);
constexpr size_t OFF_CAT  = A256(OFF_HSB + SZ_NG4);
constexpr size_t OFF_WH   = A256(OFF_CAT + (size_t)N_NODES * 2400);
constexpr size_t OFF_ATT  = A256(OFF_WH  + SZ_NG4);
constexpr size_t OFF_HS1  = A256(OFF_ATT + (size_t)N_NODES * N_NODES);
constexpr size_t OFF_HS2  = A256(OFF_HS1 + SZ_NG4);
constexpr size_t OFF_Z    = A256(OFF_HS2 + SZ_NG4);
constexpr size_t OFF_HC3  = A256(OFF_Z   + (size_t)N_NODES * 4800);
constexpr size_t OFF_WHHR  = A256(OFF_HC3  + (size_t)N_NODES * 9600);
constexpr size_t OFF_WIHR0 = A256(OFF_WHHR + 4 * (size_t)G4 * H_HID);
constexpr size_t OFF_WIHR1 = A256(OFF_WIHR0 + 2 * (size_t)G4 * 300);
constexpr size_t OFF_BR    = A256(OFF_WIHR1 + 2 * (size_t)G4 * 600);
constexpr size_t OFF_BAR  = A256(OFF_BR  + 4 * (size_t)G4);
constexpr size_t OFF_U    = A256(OFF_BAR + 64);
constexpr size_t OFF_V    = A256(OFF_U   + 512);
constexpr size_t OFF_S    = A256(OFF_V   + 32);
constexpr size_t OFF_E1   = A256(OFF_S   + 1280);
constexpr size_t OFF_E2   = A256(OFF_E1  + 512);
constexpr size_t OFF_BATT = A256(OFF_E2  + 512);
constexpr size_t OFF_EA   = A256(OFF_BATT + 512);
constexpr size_t SZ_HC   = (size_t)N_NODES * 9600;
constexpr size_t OFF_FCP  = A256(OFF_EA + 2560);
constexpr size_t POOL_SZ  = A256(OFF_FCP + 8 * SZ_HC);

__device__ float g_pool[POOL_SZ];

__device__ __forceinline__ float sigm_(float x) { return 1.0f / (1.0f + expf(-x)); }

// ---------------------------------------------------------------------------
// 64x64x16 fp32 GEMM core, double-buffered — GAT GEMMs (unchanged winner)
// ---------------------------------------------------------------------------
#define BM 64
#define BN 64
#define BK 16
#define SPAD 68

template<int TB>
__device__ __forceinline__ void gemm_acc64(
    int M, int N, int K,
    const float* __restrict__ A, int lda,
    const float* __restrict__ B, int ldb,
    float (*As)[BK * SPAD], float (*Bs)[BK * SPAD], float acc[4][4],
    int m0, int n0, int tid, int tx, int ty)
{
#pragma unroll
    for (int i = 0; i < 4; i++)
#pragma unroll
        for (int j = 0; j < 4; j++) acc[i][j] = 0.0f;

    const int nt = (K + BK - 1) / BK;

#pragma unroll
    for (int i = 0; i < 4; i++) {
        int idx = tid + i * 256;
        int m = idx >> 4, k = idx & 15;
        int gm = m0 + m, gk = k;
        As[0][k * SPAD + m] = (gm < M && gk < K) ? __ldg(&A[(size_t)gm * lda + gk]) : 0.0f;
    }
    if (TB) {
#pragma unroll
        for (int i = 0; i < 4; i++) {
            int idx = tid + i * 256;
            int j = idx >> 4, k = idx & 15;
            int gj = n0 + j, gk = k;
            Bs[0][k * SPAD + j] = (gj < N && gk < K) ? __ldg(&B[(size_t)gj * ldb + gk]) : 0.0f;
        }
    } else {
#pragma unroll
        for (int i = 0; i < 4; i++) {
            int idx = tid + i * 256;
            int j = idx & 63, k = idx >> 6;
            int gj = n0 + j, gk = k;
            Bs[0][k * SPAD + j] = (gj < N && gk < K) ? __ldg(&B[(size_t)gk * ldb + gj]) : 0.0f;
        }
    }
    __syncthreads();

    float ra[4], rb[4];
    for (int t = 0; t < nt; t++) {
        const int cur = t & 1;
        const bool more = (t + 1 < nt);
        if (more) {
            int k0 = (t + 1) * BK;
#pragma unroll
            for (int i = 0; i < 4; i++) {
                int idx = tid + i * 256;
                int m = idx >> 4, k = idx & 15;
                int gm = m0 + m, gk = k0 + k;
                ra[i] = (gm < M && gk < K) ? __ldg(&A[(size_t)gm * lda + gk]) : 0.0f;
            }
            if (TB) {
#pragma unroll
                for (int i = 0; i < 4; i++) {
                    int idx = tid + i * 256;
                    int j = idx >> 4, k = idx & 15;
                    int gj = n0 + j, gk = k0 + k;
                    rb[i] = (gj < N && gk < K) ? __ldg(&B[(size_t)gj * ldb + gk]) : 0.0f;
                }
            } else {
#pragma unroll
                for (int i = 0; i < 4; i++) {
                    int idx = tid + i * 256;
                    int j = idx & 63, k = idx >> 6;
                    int gj = n0 + j, gk = k0 + k;
                    rb[i] = (gj < N && gk < K) ? __ldg(&B[(size_t)gk * ldb + gj]) : 0.0f;
                }
            }
        }
#pragma unroll
        for (int kk = 0; kk < BK; kk++) {
            float4 av = *reinterpret_cast<const float4*>(&As[cur][kk * SPAD + ty * 4]);
            float4 bv = *reinterpret_cast<const float4*>(&Bs[cur][kk * SPAD + tx * 4]);
            float a[4] = {av.x, av.y, av.z, av.w};
            float b[4] = {bv.x, bv.y, bv.z, bv.w};
#pragma unroll
            for (int i = 0; i < 4; i++)
#pragma unroll
                for (int j = 0; j < 4; j++)
                    acc[i][j] += a[i] * b[j];
        }
        if (more) {
            const int nxt = cur ^ 1;
#pragma unroll
            for (int i = 0; i < 4; i++) {
                int idx = tid + i * 256;
                int m = idx >> 4, k = idx & 15;
                As[nxt][k * SPAD + m] = ra[i];
            }
            if (TB) {
#pragma unroll
                for (int i = 0; i < 4; i++) {
                    int idx = tid + i * 256;
                    int j = idx >> 4, k = idx & 15;
                    Bs[nxt][k * SPAD + j] = rb[i];
                }
            } else {
#pragma unroll
                for (int i = 0; i < 4; i++) {
                    int idx = tid + i * 256;
                    int j = idx & 63, k = idx >> 6;
                    Bs[nxt][k * SPAD + j] = rb[i];
                }
            }
            __syncthreads();
        }
    }
}

template<int TB, int EPI>
__global__ void __launch_bounds__(256) gemm_kernel(
    int M, int N, int K,
    const float* __restrict__ A, int lda,
    const float* __restrict__ B, int ldb,
    const float* __restrict__ Dm, int ldd,
    float* __restrict__ C, int ldc)
{
    __shared__ float As[2][BK * SPAD], Bs[2][BK * SPAD];
    const int m0 = blockIdx.y * BM, n0 = blockIdx.x * BN;
    const int tid = threadIdx.x, tx = tid & 15, ty = tid >> 4;
    float acc[4][4];
    gemm_acc64<TB>(M, N, K, A, lda, B, ldb, As, Bs, acc, m0, n0, tid, tx, ty);

#pragma unroll
    for (int i = 0; i < 4; i++) {
        int gm = m0 + ty * 4 + i;
        if (gm >= M) continue;
#pragma unroll
        for (int j = 0; j < 4; j++) {
            int gn = n0 + tx * 4 + j;
            if (gn >= N) continue;
            float v = acc[i][j];
            if (Dm) v += (ldd == 0) ? Dm[gn] : Dm[(size_t)gm * ldd + gn];
            if (EPI == 1) v = tanhf(v);
            if (EPI == 2) v = (v > 0.0f) ? v : expm1f(v);
            C[(size_t)gm * ldc + gn] = v;
        }
    }
}

// ---------------------------------------------------------------------------
// Dual projection GEMM (fwd+bwd via blockIdx.z), 128x128x8, float4 LDG.
//   C = A @ B^T + bias,  A [M][K], B [G4][K], k-contiguous, lda==ldb==K.
// ---------------------------------------------------------------------------
#define XBM 128
#define XBN 128
#define XBK 8
#define XPAD 132

__device__ __forceinline__ float4 ldA4(const float* __restrict__ A, int lda,
                                       int M, int K, int gm, int gk)
{
    float4 v = make_float4(0.f, 0.f, 0.f, 0.f);
    if (gm < M) {
        if (gk + 3 < K) v = *reinterpret_cast<const float4*>(&A[(size_t)gm * lda + gk]);
        else {
            if (gk < K)     v.x = A[(size_t)gm * lda + gk];
            if (gk + 1 < K) v.y = A[(size_t)gm * lda + gk + 1];
            if (gk + 2 < K) v.z = A[(size_t)gm * lda + gk + 2];
        }
    }
    return v;
}

__global__ void __launch_bounds__(256) proj_dual_kernel(
    int M, int K,
    const float* __restrict__ A,
    const float* __restrict__ B0, const float* __restrict__ B1,
    const float* __restrict__ bias0, const float* __restrict__ bias1,
    float* __restrict__ C0, float* __restrict__ C1)
{
    __shared__ float As[2][XBK * XPAD], Bs[2][XBK * XPAD];
    const float* B    = blockIdx.z ? B1 : B0;
    const float* bias = blockIdx.z ? bias1 : bias0;
    float* C          = blockIdx.z ? C1 : C0;

    const int m0 = blockIdx.y * XBM, n0 = blockIdx.x * XBN;
    const int tid = threadIdx.x, tx = tid & 15, ty = tid >> 4;
    const int lr = tid >> 1, lk = (tid & 1) * 4;    // loader: row, k-quad

    float acc[8][8];
#pragma unroll
    for (int i = 0; i < 8; i++)
#pragma unroll
        for (int j = 0; j < 8; j++) acc[i][j] = 0.0f;

    const int nt = (K + XBK - 1) / XBK;

    // prologue
    {
        float4 va = ldA4(A, K, M, K, m0 + lr, lk);
        float4 vb = ldA4(B, K, G4, K, n0 + lr, lk);
        As[0][(lk + 0) * XPAD + lr] = va.x;
        As[0][(lk + 1) * XPAD + lr] = va.y;
        As[0][(lk + 2) * XPAD + lr] = va.z;
        As[0][(lk + 3) * XPAD + lr] = va.w;
        Bs[0][(lk + 0) * XPAD + lr] = vb.x;
        Bs[0][(lk + 1) * XPAD + lr] = vb.y;
        Bs[0][(lk + 2) * XPAD + lr] = vb.z;
        Bs[0][(lk + 3) * XPAD + lr] = vb.w;
    }
    __syncthreads();

    float4 ra, rb;
    for (int t = 0; t < nt; t++) {
        const int cur = t & 1;
        const bool more = (t + 1 < nt);
        if (more) {
            int k0 = (t + 1) * XBK;
            ra = ldA4(A, K, M, K, m0 + lr, k0 + lk);
            rb = ldA4(B, K, G4, K, n0 + lr, k0 + lk);
        }
#pragma unroll
        for (int kk = 0; kk < XBK; kk++) {
            float a[8], b[8];
            float4 a0 = *reinterpret_cast<const float4*>(&As[cur][kk * XPAD + ty * 8]);
            float4 a1 = *reinterpret_cast<const float4*>(&As[cur][kk * XPAD + ty * 8 + 4]);
            float4 b0 = *reinterpret_cast<const float4*>(&Bs[cur][kk * XPAD + tx * 8]);
            float4 b1 = *reinterpret_cast<const float4*>(&Bs[cur][kk * XPAD + tx * 8 + 4]);
            a[0]=a0.x; a[1]=a0.y; a[2]=a0.z; a[3]=a0.w;
            a[4]=a1.x; a[5]=a1.y; a[6]=a1.z; a[7]=a1.w;
            b[0]=b0.x; b[1]=b0.y; b[2]=b0.z; b[3]=b0.w;
            b[4]=b1.x; b[5]=b1.y; b[6]=b1.z; b[7]=b1.w;
#pragma unroll
            for (int i = 0; i < 8; i++)
#pragma unroll
                for (int j = 0; j < 8; j++)
                    acc[i][j] += a[i] * b[j];
        }
        if (more) {
            const int nxt = cur ^ 1;
            As[nxt][(lk + 0) * XPAD + lr] = ra.x;
            As[nxt][(lk + 1) * XPAD + lr] = ra.y;
            As[nxt][(lk + 2) * XPAD + lr] = ra.z;
            As[nxt][(lk + 3) * XPAD + lr] = ra.w;
            Bs[nxt][(lk + 0) * XPAD + lr] = rb.x;
            Bs[nxt][(lk + 1) * XPAD + lr] = rb.y;
            Bs[nxt][(lk + 2) * XPAD + lr] = rb.z;
            Bs[nxt][(lk + 3) * XPAD + lr] = rb.w;
            __syncthreads();
        }
    }

#pragma unroll
    for (int i = 0; i < 8; i++) {
        int gm = m0 + ty * 8 + i;
        if (gm >= M) continue;
#pragma unroll
        for (int j = 0; j < 8; j++) {
            int gn = n0 + tx * 8 + j;
            if (gn >= G4) continue;
            C[(size_t)gm * G4 + gn] = acc[i][j] + bias[gn];
        }
    }
}

// ---------------------------------------------------------------------------
// FC1 split-K: partial GEMM (K chunk 600 per z) + reduction with tanh.
// float4 global loads on both operands.
// ---------------------------------------------------------------------------
#define FC1_KS 8
#define FC1_KC 600

__global__ void __launch_bounds__(256) fc1_partial_kernel(
    const float* __restrict__ A,     // Z, lda 4800
    const float* __restrict__ B,     // FC1, ldb 9600
    float* __restrict__ P)
{
    __shared__ float As[2][XBK * XPAD], Bs[2][XBK * XPAD];
    const int M = N_NODES;
    const int lda = 4800, ldb = 9600;
    const int kbase = blockIdx.z * FC1_KC;
    const int m0 = blockIdx.y * XBM, n0 = blockIdx.x * XBN;
    const int tid = threadIdx.x, tx = tid & 15, ty = tid >> 4;
    const int lr = tid >> 1, lk = (tid & 1) * 4;       // A loader
    const int bk = tid >> 5, bj = (tid & 31) * 4;      // B loader
    float* C = P + (size_t)blockIdx.z * SZ_HC;

    float acc[8][8];
#pragma unroll
    for (int i = 0; i < 8; i++)
#pragma unroll
        for (int j = 0; j < 8; j++) acc[i][j] = 0.0f;

    const int nt = FC1_KC / XBK;   // 75

    {
        int gm = m0 + lr;
        float4 va = make_float4(0.f, 0.f, 0.f, 0.f);
        if (gm < M) va = *reinterpret_cast<const float4*>(&A[(size_t)gm * lda + kbase + lk]);
        As[0][(lk + 0) * XPAD + lr] = va.x;
        As[0][(lk + 1) * XPAD + lr] = va.y;
        As[0][(lk + 2) * XPAD + lr] = va.z;
        As[0][(lk + 3) * XPAD + lr] = va.w;
        float4 vb = *reinterpret_cast<const float4*>(&B[(size_t)(kbase + bk) * ldb + n0 + bj]);
        *reinterpret_cast<float4*>(&Bs[0][bk * XPAD + bj]) = vb;
    }
    __syncthreads();

    float4 ra, rb;
    for (int t = 0; t < nt; t++) {
        const int cur = t & 1;
        const bool more = (t + 1 < nt);
        if (more) {
            int k0 = kbase + (t + 1) * XBK;
            int gm = m0 + lr;
            ra = make_float4(0.f, 0.f, 0.f, 0.f);
            if (gm < M) ra = *reinterpret_cast<const float4*>(&A[(size_t)gm * lda + k0 + lk]);
            rb = *reinterpret_cast<const float4*>(&B[(size_t)(k0 + bk) * ldb + n0 + bj]);
        }
#pragma unroll
        for (int kk = 0; kk < XBK; kk++) {
            float a[8], b[8];
            float4 a0 = *reinterpret_cast<const float4*>(&As[cur][kk * XPAD + ty * 8]);
            float4 a1 = *reinterpret_cast<const float4*>(&As[cur][kk * XPAD + ty * 8 + 4]);
            float4 b0 = *reinterpret_cast<const float4*>(&Bs[cur][kk * XPAD + tx * 8]);
            float4 b1 = *reinterpret_cast<const float4*>(&Bs[cur][kk * XPAD + tx * 8 + 4]);
            a[0]=a0.x; a[1]=a0.y; a[2]=a0.z; a[3]=a0.w;
            a[4]=a1.x; a[5]=a1.y; a[6]=a1.z; a[7]=a1.w;
            b[0]=b0.x; b[1]=b0.y; b[2]=b0.z; b[3]=b0.w;
            b[4]=b1.x; b[5]=b1.y; b[6]=b1.z; b[7]=b1.w;
#pragma unroll
            for (int i = 0; i < 8; i++)
#pragma unroll
                for (int j = 0; j < 8; j++)
                    acc[i][j] += a[i] * b[j];
        }
        if (more) {
            const int nxt = cur ^ 1;
            As[nxt][(lk + 0) * XPAD + lr] = ra.x;
            As[nxt][(lk + 1) * XPAD + lr] = ra.y;
            As[nxt][(lk + 2) * XPAD + lr] = ra.z;
            As[nxt][(lk + 3) * XPAD + lr] = ra.w;
            *reinterpret_cast<float4*>(&Bs[nxt][bk * XPAD + bj]) = rb;
            __syncthreads();
        }
    }

#pragma unroll
    for (int i = 0; i < 8; i++) {
        int gm = m0 + ty * 8 + i;
        if (gm >= M) continue;
#pragma unroll
        for (int j = 0; j < 8; j++) {
            int gn = n0 + tx * 8 + j;
            C[(size_t)gm * 9600 + gn] = acc[i][j];
        }
    }
}

__global__ void fc1_reduce_kernel(const float* __restrict__ P, float* __restrict__ out)
{
    size_t idx = (size_t)blockIdx.x * blockDim.x + threadIdx.x;
    if (idx >= SZ_HC) return;
    float s = 0.0f;
#pragma unroll
    for (int z = 0; z < FC1_KS; z++) s += P[(size_t)z * SZ_HC + idx];
    out[idx] = tanhf(s);
}

// ---------------------------------------------------------------------------
// Persistent LSTM scan (R13 winner, unchanged): BN=48, 300 blocks, 192 thr
// ---------------------------------------------------------------------------
#define LBN 48
#define LSPD 52
#define LTHREADS 192
constexpr int LSTM_GX = G4 / LBN;                  // 25
constexpr int LSTM_GY = (N_NODES + BM - 1) / BM;   // 6
constexpr unsigned LSTM_BLOCKS = LSTM_GX * LSTM_GY * 2;  // 300
constexpr int BS_ROWS = 304;
constexpr size_t SMEM_SCAN = (size_t)(BS_ROWS * LSPD + 2 * BK * SPAD) * 4;  // 71936 B

__global__ void __launch_bounds__(LTHREADS) lstm_scan_kernel(
    float* __restrict__ hsA, float* __restrict__ hsB,
    int hcol_f, int hcol_b,
    const float* __restrict__ Whh_rf, const float* __restrict__ Whh_rb,
    const float* __restrict__ Pf, const float* __restrict__ Pb,
    float* __restrict__ outbuf,
    unsigned* __restrict__ bar)
{
    extern __shared__ float smem[];
    float* Bres = smem;
    float* As   = smem + BS_ROWS * LSPD;

    const int z = blockIdx.z;
    const int hcol = z ? hcol_b : hcol_f;
    const float* Bw = z ? Whh_rb : Whh_rf;
    const float* Pbase = z ? Pb : Pf;

    const int m0 = blockIdx.y * BM, n0 = blockIdx.x * LBN;
    const int tid = threadIdx.x;
    const int tx = tid % 12, ty = tid / 12;

    for (int idx = tid; idx < LBN * BS_ROWS; idx += LTHREADS) {
        int j = idx / BS_ROWS, k = idx % BS_ROWS;
        int gj = n0 + j;
        Bres[k * LSPD + j] = (gj < G4 && k < H_HID) ? __ldg(&Bw[(size_t)gj * H_HID + k]) : 0.0f;
    }

    const int r0 = n0 + tx * 4;
    const int ju = r0 >> 2;
    float c_reg[4] = {0.0f, 0.0f, 0.0f, 0.0f};

    __syncthreads();

    const int nt = (H_HID + BK - 1) / BK;

    for (int t = 0; t < L_SEQ; t++) {
        const float* hin  = (t & 1) ? hsB : hsA;
        float*       hout = (t & 1) ? hsA : hsB;
        const float* A = hin + hcol;

        for (int idx = tid; idx < BM * BK; idx += LTHREADS) {
            int m = idx >> 4, k = idx & 15;
            int gm = m0 + m;
            As[k * SPAD + m] = (gm < N_NODES) ? __ldg(&A[(size_t)gm * G4 + k]) : 0.0f;
        }
        __syncthreads();

        float acc[4][4];
#pragma unroll
        for (int i = 0; i < 4; i++)
#pragma unroll
            for (int j = 0; j < 4; j++) acc[i][j] = 0.0f;

        float ra[6];
        for (int kt = 0; kt < nt; kt++) {
            const int cur = kt & 1;
            const bool more = (kt + 1 < nt);
            if (more) {
                int k0 = (kt + 1) * BK;
#pragma unroll
                for (int i = 0; i < 6; i++) {
                    int idx = tid + i * LTHREADS;
                    if (idx < BM * BK) {
                        int m = idx >> 4, k = idx & 15;
                        int gm = m0 + m, gk = k0 + k;
                        ra[i] = (gm < N_NODES && gk < H_HID) ? __ldg(&A[(size_t)gm * G4 + gk]) : 0.0f;
                    }
                }
            }
#pragma unroll
            for (int kk = 0; kk < BK; kk++) {
                float4 av = *reinterpret_cast<const float4*>(&As[cur * (BK * SPAD) + kk * SPAD + ty * 4]);
                float4 bv = *reinterpret_cast<const float4*>(&Bres[(kt * BK + kk) * LSPD + tx * 4]);
                float a[4] = {av.x, av.y, av.z, av.w};
                float b[4] = {bv.x, bv.y, bv.z, bv.w};
#pragma unroll
                for (int i = 0; i < 4; i++)
#pragma unroll
                    for (int j = 0; j < 4; j++)
                        acc[i][j] += a[i] * b[j];
            }
            if (more) {
                const int nxt = cur ^ 1;
#pragma unroll
                for (int i = 0; i < 6; i++) {
                    int idx = tid + i * LTHREADS;
                    if (idx < BM * BK) {
                        int m = idx >> 4, k = idx & 15;
                        As[nxt * (BK * SPAD) + k * SPAD + m] = ra[i];
                    }
                }
                __syncthreads();
            }
        }

        {
            const size_t toff = (size_t)(z ? (L_SEQ - 1 - t) : t) * N_NODES * G4;
            const float* P = Pbase + toff;
#pragma unroll
            for (int i = 0; i < 4; i++) {
                int gm = m0 + ty * 4 + i;
                if (gm >= N_NODES) continue;
                float4 p = *reinterpret_cast<const float4*>(P + (size_t)gm * G4 + r0);
                float gi = acc[i][0] + p.x;
                float gf = acc[i][1] + p.y;
                float gg = acc[i][2] + p.z;
                float go = acc[i][3] + p.w;
                float cn = sigm_(gf) * c_reg[i] + sigm_(gi) * tanhf(gg);
                float h  = sigm_(go) * tanhf(cn);
                c_reg[i] = cn;
                hout[(size_t)gm * G4 + hcol + ju] = h;
                if (outbuf) {
                    int tt = z ? (L_SEQ - 1 - t) : t;
                    outbuf[(size_t)tt * N_NODES * 600 + (size_t)gm * 600 + z * H_HID + ju] = h;
                }
            }
        }

        if (t + 1 < L_SEQ) {
            __threadfence();
            __syncthreads();
            if (tid == 0) {
                atomicAdd(bar, 1u);
                const unsigned target = LSTM_BLOCKS * (unsigned)(t + 1);
                const volatile unsigned* vb = bar;
                while (*vb < target) __nanosleep(64);
                __threadfence();
            }
            __syncthreads();
        }
    }
}

// ---------------------------------------------------------------------------
// prep: weight reorders + bias reorders + HSA zero + barrier counters
// ---------------------------------------------------------------------------
constexpr size_t PREP_W3 = (size_t)G4 * 300;
constexpr size_t PREP_W6 = (size_t)G4 * 600;
constexpr size_t PREP_B0 = 6 * PREP_W3;
constexpr size_t PREP_B1 = PREP_B0 + 2 * PREP_W6;
constexpr size_t PREP_B2 = PREP_B1 + 4 * (size_t)G4;
constexpr size_t PREP_TOTAL = PREP_B2 + SZ_NG4;

__device__ __forceinline__ void reo_(const float* in, float* out, size_t idx, int K) {
    int r = (int)(idx / K), k = (int)(idx % K);
    int j = r >> 2, g = r & 3;
    out[(size_t)r * K + k] = in[(size_t)(g * H_HID + j) * K + k];
}

__global__ void prep_kernel(
    const float* __restrict__ Wih_l0f, const float* __restrict__ Wih_l0b,
    const float* __restrict__ Whh_l0f, const float* __restrict__ Whh_l0b,
    const float* __restrict__ Whh_l1f, const float* __restrict__ Whh_l1b,
    const float* __restrict__ Wih_l1f, const float* __restrict__ Wih_l1b,
    const float* __restrict__ b_l0f, const float* __restrict__ b_l0b,
    const float* __restrict__ b_l1f, const float* __restrict__ b_l1b,
    float* __restrict__ pool)
{
    size_t i = (size_t)blockIdx.x * blockDim.x + threadIdx.x;
    if (i == 0) {
        ((unsigned*)(pool + OFF_BAR))[0] = 0u;
        ((unsigned*)(pool + OFF_BAR))[1] = 0u;
    }
    if (i >= PREP_TOTAL) return;

    float* WIHR0 = pool + OFF_WIHR0;
    float* WIHR1 = pool + OFF_WIHR1;
    float* WHHR  = pool + OFF_WHHR;
    float* BR    = pool + OFF_BR;

    if (i < PREP_B0) {
        int seg = (int)(i / PREP_W3);
        size_t l = i % PREP_W3;
        switch (seg) {
            case 0: reo_(Wih_l0f, WIHR0 + 0 * PREP_W3, l, 300); break;
            case 1: reo_(Wih_l0b, WIHR0 + 1 * PREP_W3, l, 300); break;
            case 2: reo_(Whh_l0f, WHHR + 0 * PREP_W3, l, 300); break;
            case 3: reo_(Whh_l0b, WHHR + 1 * PREP_W3, l, 300); break;
            case 4: reo_(Whh_l1f, WHHR + 2 * PREP_W3, l, 300); break;
            default: reo_(Whh_l1b, WHHR + 3 * PREP_W3, l, 300); break;
        }
    } else if (i < PREP_B1) {
        size_t l = i - PREP_B0;
        if (l < PREP_W6) reo_(Wih_l1f, WIHR1 + 0 * PREP_W6, l, 600);
        else             reo_(Wih_l1b, WIHR1 + 1 * PREP_W6, l - PREP_W6, 600);
    } else if (i < PREP_B2) {
        size_t l = i - PREP_B1;
        int which = (int)(l / G4);
        int r = (int)(l % G4);
        int j = r >> 2, g = r & 3;
        const float* src = (which == 0) ? b_l0f : (which == 1) ? b_l0b : (which == 2) ? b_l1f : b_l1b;
        BR[(size_t)which * G4 + r] = src[g * H_HID + j];
    } else {
        pool[OFF_HSA + (i - PREP_B2)] = 0.0f;
    }
}

__global__ void embed_kernel(const int* __restrict__ tok,
                             const float* __restrict__ emb,
                             float* __restrict__ x)
{
    size_t idx = (size_t)blockIdx.x * blockDim.x + threadIdx.x;
    const size_t total = (size_t)L_SEQ * N_NODES * D_EMB;
    if (idx >= total) return;
    int d = (int)(idx % D_EMB);
    size_t r = idx / D_EMB;
    int n = (int)(r % N_NODES);
    int t = (int)(r / N_NODES);
    int tv = tok[n * L_SEQ + t];
    x[idx] = emb[(size_t)tv * D_EMB + d];
}

// out[row] = epi( dot(A[row,:K], w) )
template<int EPI>
__global__ void rows_dot_kernel(const float* __restrict__ A, int lda,
                                const float* __restrict__ w, int K,
                                float* __restrict__ out)
{
    __shared__ float red[8];
    const float* a = A + (size_t)blockIdx.x * lda;
    float s = 0.0f;
    for (int k = threadIdx.x; k < K; k += blockDim.x) s += a[k] * w[k];
#pragma unroll
    for (int o = 16; o > 0; o >>= 1) s += __shfl_down_sync(0xffffffffu, s, o);
    if ((threadIdx.x & 31) == 0) red[threadIdx.x >> 5] = s;
    __syncthreads();
    if (threadIdx.x == 0) {
        float t = 0.0f;
        int nw = blockDim.x >> 5;
        for (int i = 0; i < nw; i++) t += red[i];
        if (EPI == 1) t = tanhf(t);
        out[blockIdx.x] = t;
    }
}

__global__ void rows_dot2_kernel(const float* __restrict__ A, int lda,
                                 const float* __restrict__ w1,
                                 const float* __restrict__ w2, int K,
                                 float* __restrict__ out1, float* __restrict__ out2)
{
    __shared__ float red1[8], red2[8];
    const float* a = A + (size_t)blockIdx.x * lda;
    float s1 = 0.0f, s2 = 0.0f;
    for (int k = threadIdx.x; k < K; k += blockDim.x) {
        float v = a[k];
        s1 += v * w1[k];
        s2 += v * w2[k];
    }
#pragma unroll
    for (int o = 16; o > 0; o >>= 1) {
        s1 += __shfl_down_sync(0xffffffffu, s1, o);
        s2 += __shfl_down_sync(0xffffffffu, s2, o);
    }
    if ((threadIdx.x & 31) == 0) { red1[threadIdx.x >> 5] = s1; red2[threadIdx.x >> 5] = s2; }
    __syncthreads();
    if (threadIdx.x == 0) {
        float t1 = 0.0f, t2 = 0.0f;
        int nw = blockDim.x >> 5;
        for (int i = 0; i < nw; i++) { t1 += red1[i]; t2 += red2[i]; }
        out1[blockIdx.x] = t1;
        out2[blockIdx.x] = t2;
    }
}

__global__ void colsum_kernel(const float* __restrict__ A, int lda, int rows,
                              const float* __restrict__ w, float scale,
                              float* __restrict__ out, int ncols)
{
    int j = blockIdx.x * blockDim.x + threadIdx.x;
    if (j >= ncols) return;
    float s = 0.0f;
#pragma unroll 4
    for (int n = 0; n < rows; n++) {
        float v = A[(size_t)n * lda + j];
        s += w ? w[n] * v : v;
    }
    out[j] = s * scale;
}

__global__ void gate_cat_kernel(const float* __restrict__ h,
                                const float* __restrict__ u,
                                const float* __restrict__ vsc,
                                const float* __restrict__ s,
                                float* __restrict__ cat)
{
    int idx = blockIdx.x * blockDim.x + threadIdx.x;
    if (idx >= N_NODES * G4) return;
    int n = idx / G4, j = idx % G4;
    float hv = h[(size_t)n * G4 + j];
    float h0 = h[j];
    float val;
    if (n == 0) {
        val = h0;
    } else {
        float g = sigm_(u[n] + vsc[0]);
        val = g * s[j] + (1.0f - g) * ((float)(N_NODES - 1) * h0);
    }
    cat[(size_t)n * 2400 + j] = hv;
    cat[(size_t)n * 2400 + 1200 + j] = val;
}

__global__ void att_softmax_kernel(const float* __restrict__ e1,
                                   const float* __restrict__ e2,
                                   const int* __restrict__ adj,
                                   float* __restrict__ att)
{
    __shared__ float warpred[4];
    __shared__ float s_max, s_sum;
    int i = blockIdx.x;
    float ei = e1[i];

    float mx = -3.4e38f;
    for (int j = threadIdx.x; j < N_NODES; j += blockDim.x) {
        float v = ei + e2[j];
        v = (v > 0.0f) ? v : 0.01f * v;
        if (adj[(size_t)i * N_NODES + j] <= 0) v = -9.0e15f;
        mx = fmaxf(mx, v);
    }
#pragma unroll
    for (int o = 16; o > 0; o >>= 1) mx = fmaxf(mx, __shfl_down_sync(0xffffffffu, mx, o));
    if ((threadIdx.x & 31) == 0) warpred[threadIdx.x >> 5] = mx;
    __syncthreads();
    if (threadIdx.x == 0) {
        float m2 = warpred[0];
        int nw = blockDim.x >> 5;
        for (int k = 1; k < nw; k++) m2 = fmaxf(m2, warpred[k]);
        s_max = m2;
    }
    __syncthreads();
    float smax = s_max;

    float sum = 0.0f;
    for (int j = threadIdx.x; j < N_NODES; j += blockDim.x) {
        float v = ei + e2[j];
        v = (v > 0.0f) ? v : 0.01f * v;
        if (adj[(size_t)i * N_NODES + j] <= 0) v = -9.0e15f;
        sum += expf(v - smax);
    }
#pragma unroll
    for (int o = 16; o > 0; o >>= 1) sum += __shfl_down_sync(0xffffffffu, sum, o);
    if ((threadIdx.x & 31) == 0) warpred[threadIdx.x >> 5] = sum;
    __syncthreads();
    if (threadIdx.x == 0) {
        float t = 0.0f;
        int nw = blockDim.x >> 5;
        for (int k = 0; k < nw; k++) t += warpred[k];
        s_sum = t;
    }
    __syncthreads();
    float inv = 1.0f / s_sum;

    for (int j = threadIdx.x; j < N_NODES; j += blockDim.x) {
        float v = ei + e2[j];
        v = (v > 0.0f) ? v : 0.01f * v;
        if (adj[(size_t)i * N_NODES + j] <= 0) v = -9.0e15f;
        att[(size_t)i * N_NODES + j] = expf(v - smax) * inv;
    }
}

__global__ void zassemble_kernel(const float* __restrict__ h2, float* __restrict__ Z)
{
    int idx = blockIdx.x * blockDim.x + threadIdx.x;
    if (idx >= N_NODES * G4) return;
    int n = idx / G4, j = idx % G4;
    float a = h2[j];
    float b = h2[(size_t)n * G4 + j];
    size_t base = (size_t)n * 4800;
    Z[base + j]        = a;
    Z[base + 1200 + j] = b;
    Z[base + 2400 + j] = a * b;
    Z[base + 3600 + j] = a - b;
}

__global__ void final_kernel(const float* __restrict__ ea,
                             const float* __restrict__ Wlin,
                             const float* __restrict__ blin,
                             float* __restrict__ out)
{
    __shared__ float r0[8], r1[8];
    float s0 = 0.0f, s1 = 0.0f;
    for (int j = threadIdx.x; j < 2400; j += blockDim.x) {
        float e = ea[j];
        s0 += e * Wlin[j];
        s1 += e * Wlin[2400 + j];
    }
#pragma unroll
    for (int o = 16; o > 0; o >>= 1) {
        s0 += __shfl_down_sync(0xffffffffu, s0, o);
        s1 += __shfl_down_sync(0xffffffffu, s1, o);
    }
    if ((threadIdx.x & 31) == 0) { r0[threadIdx.x >> 5] = s0; r1[threadIdx.x >> 5] = s1; }
    __syncthreads();
    if (threadIdx.x == 0) {
        float l0 = 0.0f, l1 = 0.0f;
        int nw = blockDim.x >> 5;
        for (int i = 0; i < nw; i++) { l0 += r0[i]; l1 += r1[i]; }
        l0 += blin[0]; l1 += blin[1];
        float m = fmaxf(l0, l1);
        float e0 = expf(l0 - m), e1v = expf(l1 - m);
        float inv = 1.0f / (e0 + e1v);
        out[0] = e0 * inv;
        out[1] = e1v * inv;
    }
}

// ---------------------------------------------------------------------------
// Host orchestration
// ---------------------------------------------------------------------------
static inline dim3 grid64(int M, int N)  { return dim3((N + BN - 1) / BN, (M + BM - 1) / BM); }

static void run_gate_gat(const float* h_in, float* h_out,
                         const float* gate_W, const float* gate_U,
                         const float* W_gat, const float* a_gat,
                         const int* adj, float* pool)
{
    float* U   = pool + OFF_U;
    float* Vb  = pool + OFF_V;
    float* S   = pool + OFF_S;
    float* CAT = pool + OFF_CAT;
    float* WHp = pool + OFF_WH;
    float* E1  = pool + OFF_E1;
    float* E2  = pool + OFF_E2;
    float* ATT = pool + OFF_ATT;

    rows_dot_kernel<0><<<N_NODES, 256>>>(h_in, G4, gate_W, G4, U);
    rows_dot_kernel<0><<<1, 256>>>(h_in, G4, gate_U, G4, Vb);
    colsum_kernel<<<(G4 + 255) / 256, 256>>>(h_in + G4, G4, N_NODES - 1, nullptr, 1.0f, S, G4);
    gate_cat_kernel<<<(N_NODES * G4 + 255) / 256, 256>>>(h_in, U, Vb, S, CAT);

    gemm_kernel<0, 0><<<grid64(N_NODES, G4), 256>>>(
        N_NODES, G4, 2400, CAT, 2400, W_gat, G4, nullptr, 0, WHp, G4);
    rows_dot2_kernel<<<N_NODES, 256>>>(WHp, G4, a_gat, a_gat + G4, G4, E1, E2);
    att_softmax_kernel<<<N_NODES, 128>>>(E1, E2, adj, ATT);
    gemm_kernel<0, 2><<<grid64(N_NODES, G4), 256>>>(
        N_NODES, G4, N_NODES, ATT, N_NODES, WHp, G4, nullptr, 0, h_out, G4);
}

extern "C" void kernel_launch(void* const* d_in, const int* in_sizes, int n_in,
                              void* d_out, int out_size)
{
    (void)in_sizes; (void)n_in; (void)out_size;

    float* pool = nullptr;
    cudaGetSymbolAddress((void**)&pool, g_pool);

    static bool attr_done = false;
    if (!attr_done) {
        cudaFuncSetAttribute(lstm_scan_kernel,
                             cudaFuncAttributeMaxDynamicSharedMemorySize, (int)SMEM_SCAN);
        attr_done = true;
    }

    const int*   tokens  = (const int*)d_in[0];
    const int*   adj     = (const int*)d_in[1];
    const float* emb     = (const float*)d_in[2];
    const float* Wih_l0f = (const float*)d_in[3];
    const float* Whh_l0f = (const float*)d_in[4];
    const float* b_l0f   = (const float*)d_in[5];
    const float* Wih_l0b = (const float*)d_in[6];
    const float* Whh_l0b = (const float*)d_in[7];
    const float* b_l0b   = (const float*)d_in[8];
    const float* Wih_l1f = (const float*)d_in[9];
    const float* Whh_l1f = (const float*)d_in[10];
    const float* b_l1f   = (const float*)d_in[11];
    const float* Wih_l1b = (const float*)d_in[12];
    const float* Whh_l1b = (const float*)d_in[13];
    const float* b_l1b   = (const float*)d_in[14];
    const float* W_gat   = (const float*)d_in[15];
    const float* a_gat   = (const float*)d_in[16];
    const float* gate_W  = (const float*)d_in[17];
    const float* gate_U  = (const float*)d_in[18];
    const float* FC1     = (const float*)d_in[19];
    const float* FC2     = (const float*)d_in[20];
    const float* Wlin    = (const float*)d_in[21];
    const float* blin    = (const float*)d_in[22];
    float* out = (float*)d_out;

    float* X    = pool + OFF_X;
    float* PF   = pool + OFF_P0F;
    float* PB   = pool + OFF_P0B;
    float* O0   = pool + OFF_O0;
    float* HSA  = pool + OFF_HSA;
    float* HSB  = pool + OFF_HSB;
    float* HS1  = pool + OFF_HS1;
    float* HS2  = pool + OFF_HS2;
    float* Z    = pool + OFF_Z;
    float* HC3  = pool + OFF_HC3;
    float* WHHR  = pool + OFF_WHHR;
    float* WIHR0 = pool + OFF_WIHR0;
    float* WIHR1 = pool + OFF_WIHR1;
    float* BR    = pool + OFF_BR;
    float* FCP   = pool + OFF_FCP;
    unsigned* BARC = (unsigned*)(pool + OFF_BAR);
    float* BATT = pool + OFF_BATT;
    float* EA   = pool + OFF_EA;

    const int LN = L_SEQ * N_NODES;   // 17300
    const size_t W3 = PREP_W3, W6 = PREP_W6;

    // launch 0: prep (weights + HSA zero + barrier counters)
    prep_kernel<<<(int)((PREP_TOTAL + 255) / 256), 256>>>(
        Wih_l0f, Wih_l0b, Whh_l0f, Whh_l0b, Whh_l1f, Whh_l1b,
        Wih_l1f, Wih_l1b, b_l0f, b_l0b, b_l1f, b_l1b, pool);

    // launch 1: embedding
    embed_kernel<<<(int)((SZ_X + 255) / 256), 256>>>(tokens, emb, X);

    // launch 2: layer-0 projections (fwd+bwd fused)
    {
        dim3 grid((G4 + XBN - 1) / XBN, (LN + XBM - 1) / XBM, 2);  // (10,136,2)
        proj_dual_kernel<<<grid, 256>>>(
            LN, D_EMB, X,
            WIHR0 + 0 * W3, WIHR0 + 1 * W3,
            BR + 0 * G4, BR + 1 * G4, PF, PB);
    }

    // launch 3: layer-0 persistent scan
    {
        dim3 grid(LSTM_GX, LSTM_GY, 2);
        lstm_scan_kernel<<<grid, LTHREADS, SMEM_SCAN>>>(
            HSA, HSB, 0, 300,
            WHHR + 0 * W3, WHHR + 1 * W3,
            PF, PB, O0, BARC + 0);
    }

    // launch 4: layer-1 projections (fwd+bwd fused)
    {
        dim3 grid((G4 + XBN - 1) / XBN, (LN + XBM - 1) / XBM, 2);
        proj_dual_kernel<<<grid, 256>>>(
            LN, 600, O0,
            WIHR1 + 0 * W6, WIHR1 + 1 * W6,
            BR + 2 * G4, BR + 3 * G4, PF, PB);
    }

    // launch 5 (ncu-profiled): layer-1 persistent scan
    {
        dim3 grid(LSTM_GX, LSTM_GY, 2);
        lstm_scan_kernel<<<grid, LTHREADS, SMEM_SCAN>>>(
            HSA, HSB, 600, 900,
            WHHR + 2 * W3, WHHR + 3 * W3,
            PF, PB, nullptr, BARC + 1);
    }
    // L_SEQ=50 (even): final h for both layers lands in HSA.

    // two gate+GAT stages
    run_gate_gat(HSA, HS1, gate_W, gate_U, W_gat, a_gat, adj, pool);
    run_gate_gat(HS1, HS2, gate_W, gate_U, W_gat, a_gat, adj, pool);

    // final head: FC1 via split-K partials + reduce(+tanh)
    zassemble_kernel<<<(N_NODES * G4 + 255) / 256, 256>>>(HS2, Z);
    {
        dim3 grid(9600 / XBN, (N_NODES + XBM - 1) / XBM, FC1_KS);  // (75,3,8)
        fc1_partial_kernel<<<grid, 256>>>(Z, FC1, FCP);
        fc1_reduce_kernel<<<(int)((SZ_HC + 255) / 256), 256>>>(FCP, HC3);
    }
    rows_dot_kernel<1><<<N_NODES, 256>>>(HC3, 9600, FC2, 9600, BATT);
    colsum_kernel<<<(G4 + 255) / 256, 256>>>(HS2, G4, N_NODES, nullptr,
                                             1.0f / (float)N_NODES, EA, G4);
    colsum_kernel<<<(G4 + 255) / 256, 256>>>(HS2, G4, N_NODES, BATT, 1.0f, EA + G4, G4);
    final_kernel<<<1, 256>>>(EA, Wlin, blin, out);
}